// round 6
// baseline (speedup 1.0000x reference)
#include <cuda_runtime.h>
#include <cuda_bf16.h>
#include <math.h>
#include <stdint.h>

#define SQ   4096
#define EMB  300
#define NH   3
#define HDIM 100
#define NHID 200
#define QB   128
#define TJ   32
#define JCH  1024
#define NCH  4
#define SKCH 2
#define KSPL 2048
#define KCF  64    // k floats per gemm tile
#define KPR  32    // packed pair-rows per tile
#define ASTR 136   // As smem stride (words)
#define BSTR 72    // Bs smem stride (words)

// ---------------- scratch (static device globals; no allocation) ----------------
__device__ float g_x[2 * SQ * EMB];
__device__ float g_qkv[2 * SQ * 3 * EMB];
__device__ float g_o[2 * SQ * EMB];
__device__ float g_t1[2 * SQ * EMB];
__device__ float g_ff[2 * SQ * NHID];
__device__ float g_A[SQ * SQ];                 // fp32 scores
__device__ __nv_bfloat16 g_Ab[SQ * SQ];        // bf16 softmaxed A
__device__ float g_P[SQ * EMB];
__device__ float g_Q[SQ * EMB];
__device__ float g_Pp[SKCH * SQ * EMB];
__device__ float g_Qp[SKCH * SQ * EMB];
__device__ float g_part_o[6 * NCH * SQ * HDIM];
__device__ float g_part_ml[6 * NCH * SQ * 2];
__device__ float g_suv[2 * EMB];
__device__ float g_fc1o[EMB];

// ---------------- positional encoding + add ----------------
__global__ void add_pe_kernel(const float* __restrict__ solv, const float* __restrict__ solu,
                              float* __restrict__ x) {
    int idx = blockIdx.x * blockDim.x + threadIdx.x;
    if (idx >= SQ * EMB) return;
    int z = blockIdx.z;
    const float* src = z ? solu : solv;
    int s = idx / EMB, c = idx % EMB;
    int k = c >> 1;
    float dv = expf(-(float)(2 * k) * (logf(10000.0f) / (float)EMB));
    float arg = (float)s * dv;
    float pe = (c & 1) ? cosf(arg) : sinf(arg);
    x[(size_t)z * SQ * EMB + idx] = src[idx] + pe;
}

// ---------------- bf16 helpers ----------------
__device__ __forceinline__ uint32_t packbf(float lo, float hi) {
    uint32_t r;
    asm("cvt.rn.bf16x2.f32 %0, %1, %2;" : "=r"(r) : "f"(hi), "f"(lo));
    return r;
}

#define MMA_BF16(C, A, B0, B1)                                                  \
    asm volatile(                                                               \
        "mma.sync.aligned.m16n8k16.row.col.f32.bf16.bf16.f32 "                  \
        "{%0,%1,%2,%3},{%4,%5,%6,%7},{%8,%9},{%0,%1,%2,%3};"                    \
        : "+f"((C)[0]), "+f"((C)[1]), "+f"((C)[2]), "+f"((C)[3])                \
        : "r"((A)[0]), "r"((A)[1]), "r"((A)[2]), "r"((A)[3]), "r"(B0), "r"(B1))

// ---------------- bf16 tensor-core GEMM (128x64 tile, KCF=64, prefetch) ----------------
// C[m,n] = act( sum_k Ae(m,k)*Be(k,n) + bias[n] ),  ldc = N.  M mult of 128.
// BF16A: A is __nv_bfloat16 (pre-quantized); else fp32 packed on the fly.
template<int TA, int TB, int RELU, int SPLITK, int BF16A>
__global__ __launch_bounds__(256, 2)
void mma_gemm(const float* __restrict__ A, const float* __restrict__ B,
              const float* __restrict__ bias, float* __restrict__ C,
              int M, int N, int K, int lda, int ldb,
              size_t sA, size_t sB, size_t sBias, size_t sC, int kc) {
    int z = blockIdx.z;
    int k_begin = 0, k_end = K;
    if (SPLITK) {
        k_begin = z * kc;
        k_end = min(K, k_begin + kc);
        C += (size_t)z * sC;
    } else {
        A += (size_t)z * sA; B += (size_t)z * sB; C += (size_t)z * sC;
        if (bias) bias += (size_t)z * sBias;
    }
    const __nv_bfloat16* A16 = (const __nv_bfloat16*)A;

    __shared__ uint32_t As[KPR][ASTR];
    __shared__ uint32_t Bs[KPR][BSTR];

    int t = threadIdx.x;
    int warp = t >> 5, lane = t & 31;
    int g = lane >> 2, tig = lane & 3;
    int wm = warp & 3, wn = warp >> 2;
    int row0 = blockIdx.y * 128, col0 = blockIdx.x * 64;
    int wr0 = wm * 32, wc0 = wn * 32;

    float acc[2][4][4];
#pragma unroll
    for (int i = 0; i < 2; i++)
#pragma unroll
        for (int j = 0; j < 4; j++)
#pragma unroll
            for (int h = 0; h < 4; h++) acc[i][j][h] = 0.f;

    uint32_t ra[16], rb[8];
    int nk = (k_end - k_begin + KCF - 1) / KCF;

    auto loadA = [&](int kt) {
        if (!TA) {
            int m = t >> 1, kq = (t & 1) * 32;
            if (BF16A) {
                const uint32_t* Ap = (const uint32_t*)(A16 + (size_t)(row0 + m) * lda + kt + kq);
                if (kt + kq + 31 < k_end) {
#pragma unroll
                    for (int u = 0; u < 16; u++) ra[u] = Ap[u];
                } else {
                    const unsigned short* As16 = (const unsigned short*)(A16 + (size_t)(row0 + m) * lda);
#pragma unroll
                    for (int u = 0; u < 16; u++) {
                        int gk = kt + kq + 2 * u;
                        uint32_t lo = (gk < k_end) ? As16[gk] : 0;
                        uint32_t hi = (gk + 1 < k_end) ? As16[gk + 1] : 0;
                        ra[u] = lo | (hi << 16);
                    }
                }
            } else {
                const float* Ap = A + (size_t)(row0 + m) * lda + kt + kq;
                if (kt + kq + 31 < k_end) {
#pragma unroll
                    for (int u = 0; u < 8; u++) {
                        float4 v = *(const float4*)(Ap + 4 * u);
                        ra[2 * u]     = packbf(v.x, v.y);
                        ra[2 * u + 1] = packbf(v.z, v.w);
                    }
                } else {
#pragma unroll
                    for (int u = 0; u < 16; u++) {
                        int gk = kt + kq + 2 * u;
                        float x0 = (gk < k_end) ? Ap[2 * u] : 0.f;
                        float x1 = (gk + 1 < k_end) ? Ap[2 * u + 1] : 0.f;
                        ra[u] = packbf(x0, x1);
                    }
                }
            }
        } else {
            int kp = t >> 3, mq = (t & 7) * 16;
            int gk0 = kt + 2 * kp;
            bool ok0 = gk0 < k_end, ok1 = gk0 + 1 < k_end;
            if (BF16A) {
                const uint32_t* r0p = (const uint32_t*)(A16 + (size_t)gk0 * lda + row0 + mq);
                const uint32_t* r1p = (const uint32_t*)(A16 + (size_t)(gk0 + 1) * lda + row0 + mq);
                if (ok1) {
#pragma unroll
                    for (int u = 0; u < 8; u++) {
                        uint32_t w0 = r0p[u], w1 = r1p[u];
                        ra[2 * u]     = __byte_perm(w0, w1, 0x5410);
                        ra[2 * u + 1] = __byte_perm(w0, w1, 0x7632);
                    }
                } else {
#pragma unroll
                    for (int u = 0; u < 8; u++) {
                        uint32_t w0 = ok0 ? r0p[u] : 0;
                        ra[2 * u]     = __byte_perm(w0, 0u, 0x5410);
                        ra[2 * u + 1] = __byte_perm(w0, 0u, 0x7632);
                    }
                }
            } else {
                const float* Ap0 = A + (size_t)gk0 * lda + row0 + mq;
                if (ok0 && ok1) {
#pragma unroll
                    for (int u = 0; u < 4; u++) {
                        float4 v0 = *(const float4*)(Ap0 + 4 * u);
                        float4 v1 = *(const float4*)(Ap0 + lda + 4 * u);
                        ra[4 * u]     = packbf(v0.x, v1.x);
                        ra[4 * u + 1] = packbf(v0.y, v1.y);
                        ra[4 * u + 2] = packbf(v0.z, v1.z);
                        ra[4 * u + 3] = packbf(v0.w, v1.w);
                    }
                } else {
#pragma unroll
                    for (int u = 0; u < 16; u++) {
                        float x0 = ok0 ? Ap0[u] : 0.f;
                        float x1 = ok1 ? Ap0[lda + u] : 0.f;
                        ra[u] = packbf(x0, x1);
                    }
                }
            }
        }
    };
    auto loadB = [&](int kt) {
        if (!TB) {
            int kp = t >> 3, nq = (t & 7) * 8;
            int gk0 = kt + 2 * kp;
            const float* Bp0 = B + (size_t)gk0 * ldb + col0 + nq;
            bool ok0 = gk0 < k_end, ok1 = gk0 + 1 < k_end;
            if (ok0 && ok1 && col0 + nq + 7 < N) {
#pragma unroll
                for (int u = 0; u < 2; u++) {
                    float4 v0 = *(const float4*)(Bp0 + 4 * u);
                    float4 v1 = *(const float4*)(Bp0 + ldb + 4 * u);
                    rb[4 * u]     = packbf(v0.x, v1.x);
                    rb[4 * u + 1] = packbf(v0.y, v1.y);
                    rb[4 * u + 2] = packbf(v0.z, v1.z);
                    rb[4 * u + 3] = packbf(v0.w, v1.w);
                }
            } else {
#pragma unroll
                for (int u = 0; u < 8; u++) {
                    bool okn = (col0 + nq + u) < N;
                    float x0 = (ok0 && okn) ? Bp0[u] : 0.f;
                    float x1 = (ok1 && okn) ? Bp0[ldb + u] : 0.f;
                    rb[u] = packbf(x0, x1);
                }
            }
        } else {
            int n = t >> 2, kq = (t & 3) * 16;
            int gn = col0 + n;
            const float* Bp = B + (size_t)gn * ldb + kt + kq;
            bool okn = gn < N;
            if (okn && kt + kq + 15 < k_end) {
#pragma unroll
                for (int u = 0; u < 4; u++) {
                    float4 v = *(const float4*)(Bp + 4 * u);
                    rb[2 * u]     = packbf(v.x, v.y);
                    rb[2 * u + 1] = packbf(v.z, v.w);
                }
            } else {
#pragma unroll
                for (int u = 0; u < 8; u++) {
                    int gk = kt + kq + 2 * u;
                    float x0 = (okn && gk < k_end) ? Bp[2 * u] : 0.f;
                    float x1 = (okn && gk + 1 < k_end) ? Bp[2 * u + 1] : 0.f;
                    rb[u] = packbf(x0, x1);
                }
            }
        }
    };

    loadA(k_begin); loadB(k_begin);
    for (int it = 0; it < nk; it++) {
        if (!TA) {
            int m = t >> 1, kp0 = (t & 1) * 16;
#pragma unroll
            for (int u = 0; u < 16; u++) As[kp0 + u][m] = ra[u];
        } else {
            int kp = t >> 3, mq = (t & 7) * 16;
#pragma unroll
            for (int u = 0; u < 16; u++) As[kp][mq + u] = ra[u];
        }
        if (!TB) {
            int kp = t >> 3, nq = (t & 7) * 8;
#pragma unroll
            for (int u = 0; u < 8; u++) Bs[kp][nq + u] = rb[u];
        } else {
            int n = t >> 2, kp0 = (t & 3) * 8;
#pragma unroll
            for (int u = 0; u < 8; u++) Bs[kp0 + u][n] = rb[u];
        }
        __syncthreads();
        if (it + 1 < nk) { loadA(k_begin + (it + 1) * KCF); loadB(k_begin + (it + 1) * KCF); }
#pragma unroll
        for (int ks = 0; ks < KPR; ks += 8) {
            uint32_t a[2][4], b[4][2];
#pragma unroll
            for (int i = 0; i < 2; i++) {
                int mb = wr0 + i * 16;
                a[i][0] = As[ks + tig][mb + g];
                a[i][1] = As[ks + tig][mb + 8 + g];
                a[i][2] = As[ks + tig + 4][mb + g];
                a[i][3] = As[ks + tig + 4][mb + 8 + g];
            }
#pragma unroll
            for (int j = 0; j < 4; j++) {
                int nb = wc0 + j * 8;
                b[j][0] = Bs[ks + tig][nb + g];
                b[j][1] = Bs[ks + tig + 4][nb + g];
            }
#pragma unroll
            for (int i = 0; i < 2; i++)
#pragma unroll
                for (int j = 0; j < 4; j++)
                    MMA_BF16(acc[i][j], a[i], b[j][0], b[j][1]);
        }
        __syncthreads();
    }

#pragma unroll
    for (int i = 0; i < 2; i++) {
        int r0 = row0 + wr0 + i * 16 + g;
#pragma unroll
        for (int j = 0; j < 4; j++) {
            int cc = col0 + wc0 + j * 8 + tig * 2;
#pragma unroll
            for (int h = 0; h < 2; h++) {
                int gr = r0 + h * 8;
                float v0 = acc[i][j][h * 2], v1 = acc[i][j][h * 2 + 1];
                if (!SPLITK && bias) {
                    if (cc < N) v0 += bias[cc];
                    if (cc + 1 < N) v1 += bias[cc + 1];
                }
                if (RELU) { v0 = fmaxf(v0, 0.f); v1 = fmaxf(v1, 0.f); }
                if (cc + 1 < N) {
                    *(float2*)&C[(size_t)gr * N + cc] = make_float2(v0, v1);
                } else if (cc < N) {
                    C[(size_t)gr * N + cc] = v0;
                }
            }
        }
    }
}

// ---------------- split-K reduce for P and Q (float4) ----------------
__global__ void reduce_pq(const float* __restrict__ Pp, const float* __restrict__ Qp,
                          float* __restrict__ P, float* __restrict__ Q) {
    int idx = blockIdx.x * 256 + threadIdx.x;
    if (idx >= SQ * EMB / 4) return;
    const float* src = blockIdx.y ? Qp : Pp;
    float* dst = blockIdx.y ? Q : P;
    float4 a = ((const float4*)src)[idx];
    float4 b = ((const float4*)(src + (size_t)SQ * EMB))[idx];
    float4 r = make_float4(a.x + b.x, a.y + b.y, a.z + b.z, a.w + b.w);
    ((float4*)dst)[idx] = r;
}

// ---------------- bf16 tensor-core flash attention (partials) ----------------
// grid (32, NCH, 6), block 256 = 8 warps x 16 queries
__global__ void attn_mma_kernel(const float* __restrict__ qkv_all,
                                float* __restrict__ part_o, float* __restrict__ part_ml) {
    __shared__ uint32_t k_s[TJ][60];      // K packed along d: [j][d-pair], 56 used
    __shared__ uint32_t v_s[16][108];     // V packed along j: [j-pair][d], 104 used
    __shared__ uint32_t p_s[8][16][20];   // per-warp P: [q-row][j-pair], 16 used

    int z = blockIdx.z, e = z / 3, h = z % 3;
    int qt = (int)gridDim.x - 1 - (int)blockIdx.x;  // heaviest first
    int q0 = qt * QB;
    int c = blockIdx.y, c0 = c * JCH;
    if (c0 > q0 + QB - 1) return;

    const float* qkv = qkv_all + (size_t)e * SQ * 900;
    int t = threadIdx.x, w = t >> 5, lane = t & 31;
    int g = lane >> 2, tig = lane & 3;

    int r0 = q0 + w * 16 + g;
    int r1 = r0 + 8;

    // Q fragments (bf16x2 packed along d), pre-scaled by 1/sqrt(HD)
    uint32_t qf[7][4];
    {
        const float* q0p = qkv + (size_t)r0 * 900 + h * HDIM;
        const float* q1p = qkv + (size_t)r1 * 900 + h * HDIM;
#pragma unroll
        for (int s = 0; s < 7; s++) {
            int d0 = 2 * (s * 8 + tig);
            int d1 = 2 * (s * 8 + tig + 4);
            float a0 = d0 < HDIM ? q0p[d0] * 0.1f : 0.f;
            float a1 = d0 + 1 < HDIM ? q0p[d0 + 1] * 0.1f : 0.f;
            float b0 = d0 < HDIM ? q1p[d0] * 0.1f : 0.f;
            float b1 = d0 + 1 < HDIM ? q1p[d0 + 1] * 0.1f : 0.f;
            float c0f = d1 < HDIM ? q0p[d1] * 0.1f : 0.f;
            float c1f = d1 + 1 < HDIM ? q0p[d1 + 1] * 0.1f : 0.f;
            float e0 = d1 < HDIM ? q1p[d1] * 0.1f : 0.f;
            float e1 = d1 + 1 < HDIM ? q1p[d1 + 1] * 0.1f : 0.f;
            qf[s][0] = packbf(a0, a1);
            qf[s][1] = packbf(b0, b1);
            qf[s][2] = packbf(c0f, c1f);
            qf[s][3] = packbf(e0, e1);
        }
    }

    float of[13][4];
#pragma unroll
    for (int nt = 0; nt < 13; nt++) { of[nt][0] = of[nt][1] = of[nt][2] = of[nt][3] = 0.f; }
    float m0 = -INFINITY, m1 = -INFINITY, l0 = 0.f, l1 = 0.f;

    int jend = min(c0 + JCH, q0 + QB);
    for (int jt = c0; jt < jend; jt += TJ) {
        // stage K (packed along d)
        for (int idx = t; idx < TJ * 56; idx += 256) {
            int row = idx / 56, dp = idx - row * 56;
            int d0 = 2 * dp;
            const float* kp = qkv + (size_t)(jt + row) * 900 + h * HDIM + 300;
            float x0 = d0 < HDIM ? kp[d0] : 0.f;
            float x1 = d0 < HDIM ? kp[d0 + 1] : 0.f;
            k_s[row][dp] = packbf(x0, x1);
        }
        // stage V (packed along j)
        for (int idx = t; idx < 16 * 104; idx += 256) {
            int jp = idx / 104, d = idx - jp * 104;
            const float* vp = qkv + (size_t)(jt + 2 * jp) * 900 + h * HDIM + 600 + d;
            float x0 = d < HDIM ? vp[0] : 0.f;
            float x1 = d < HDIM ? vp[900] : 0.f;
            v_s[jp][d] = packbf(x0, x1);
        }
        __syncthreads();

        // S = Q K^T
        float sc[4][4];
#pragma unroll
        for (int nt = 0; nt < 4; nt++) { sc[nt][0] = sc[nt][1] = sc[nt][2] = sc[nt][3] = 0.f; }
#pragma unroll
        for (int s = 0; s < 7; s++) {
#pragma unroll
            for (int nt = 0; nt < 4; nt++) {
                uint32_t b0 = k_s[nt * 8 + g][s * 8 + tig];
                uint32_t b1 = k_s[nt * 8 + g][s * 8 + tig + 4];
                MMA_BF16(sc[nt], qf[s], b0, b1);
            }
        }

        // causal mask (diagonal steps only)
        if (jt + TJ > q0) {
#pragma unroll
            for (int nt = 0; nt < 4; nt++) {
                int jb = jt + nt * 8 + 2 * tig;
                if (jb > r0)     sc[nt][0] = -INFINITY;
                if (jb + 1 > r0) sc[nt][1] = -INFINITY;
                if (jb > r1)     sc[nt][2] = -INFINITY;
                if (jb + 1 > r1) sc[nt][3] = -INFINITY;
            }
        }

        // online softmax
        float rm0 = -INFINITY, rm1 = -INFINITY;
#pragma unroll
        for (int nt = 0; nt < 4; nt++) {
            rm0 = fmaxf(rm0, fmaxf(sc[nt][0], sc[nt][1]));
            rm1 = fmaxf(rm1, fmaxf(sc[nt][2], sc[nt][3]));
        }
        rm0 = fmaxf(rm0, __shfl_xor_sync(0xffffffffu, rm0, 1));
        rm0 = fmaxf(rm0, __shfl_xor_sync(0xffffffffu, rm0, 2));
        rm1 = fmaxf(rm1, __shfl_xor_sync(0xffffffffu, rm1, 1));
        rm1 = fmaxf(rm1, __shfl_xor_sync(0xffffffffu, rm1, 2));
        float mn0 = fmaxf(m0, rm0), mn1 = fmaxf(m1, rm1);
        float s0 = __expf(m0 - mn0), s1 = __expf(m1 - mn1);

        float rs0 = 0.f, rs1 = 0.f;
#pragma unroll
        for (int nt = 0; nt < 4; nt++) {
            float p0 = __expf(sc[nt][0] - mn0);
            float p1 = __expf(sc[nt][1] - mn0);
            float p2 = __expf(sc[nt][2] - mn1);
            float p3 = __expf(sc[nt][3] - mn1);
            rs0 += p0 + p1;
            rs1 += p2 + p3;
            p_s[w][g][nt * 4 + tig]     = packbf(p0, p1);
            p_s[w][g + 8][nt * 4 + tig] = packbf(p2, p3);
        }
        rs0 += __shfl_xor_sync(0xffffffffu, rs0, 1);
        rs0 += __shfl_xor_sync(0xffffffffu, rs0, 2);
        rs1 += __shfl_xor_sync(0xffffffffu, rs1, 1);
        rs1 += __shfl_xor_sync(0xffffffffu, rs1, 2);
        l0 = l0 * s0 + rs0;
        l1 = l1 * s1 + rs1;
        m0 = mn0; m1 = mn1;

#pragma unroll
        for (int nt = 0; nt < 13; nt++) {
            of[nt][0] *= s0; of[nt][1] *= s0;
            of[nt][2] *= s1; of[nt][3] *= s1;
        }
        __syncwarp();

        // O += P V
#pragma unroll
        for (int ks = 0; ks < 16; ks += 8) {
            uint32_t pa[4];
            pa[0] = p_s[w][g][ks + tig];
            pa[1] = p_s[w][g + 8][ks + tig];
            pa[2] = p_s[w][g][ks + tig + 4];
            pa[3] = p_s[w][g + 8][ks + tig + 4];
#pragma unroll
            for (int nt = 0; nt < 13; nt++) {
                uint32_t b0 = v_s[ks + tig][nt * 8 + g];
                uint32_t b1 = v_s[ks + tig + 4][nt * 8 + g];
                MMA_BF16(of[nt], pa, b0, b1);
            }
        }
        __syncthreads();
    }

    // write partials
    size_t pb0 = (size_t)(z * NCH + c) * SQ + r0;
    size_t pb1 = (size_t)(z * NCH + c) * SQ + r1;
#pragma unroll
    for (int nt = 0; nt < 13; nt++) {
        int d = nt * 8 + 2 * tig;
        if (d < HDIM) {
            *(float2*)&part_o[pb0 * HDIM + d] = make_float2(of[nt][0], of[nt][1]);
            *(float2*)&part_o[pb1 * HDIM + d] = make_float2(of[nt][2], of[nt][3]);
        }
    }
    if (tig == 0) {
        part_ml[pb0 * 2] = m0; part_ml[pb0 * 2 + 1] = l0;
        part_ml[pb1 * 2] = m1; part_ml[pb1 * 2 + 1] = l1;
    }
}

__global__ void attn_combine(const float* __restrict__ part_o,
                             const float* __restrict__ part_ml,
                             float* __restrict__ o_all) {
    int qi = blockIdx.x, h = blockIdx.y, e = blockIdx.z;
    int z = e * 3 + h;
    int t = threadIdx.x;
    int nch = qi / JCH + 1;
    float M = -INFINITY;
    for (int cc = 0; cc < nch; cc++)
        M = fmaxf(M, part_ml[((size_t)(z * NCH + cc) * SQ + qi) * 2]);
    float L = 0.f, acc = 0.f;
    for (int cc = 0; cc < nch; cc++) {
        size_t pb = (size_t)(z * NCH + cc) * SQ + qi;
        float w = __expf(part_ml[pb * 2] - M);
        L += part_ml[pb * 2 + 1] * w;
        if (t < HDIM) acc += w * part_o[pb * HDIM + t];
    }
    if (t < HDIM)
        o_all[((size_t)e * SQ + qi) * EMB + h * HDIM + t] = acc / L;
}

// ---------------- fused residual + LayerNorm ----------------
__global__ void ln_kernel(float* __restrict__ x, const float* __restrict__ delta,
                          const float* __restrict__ g, const float* __restrict__ b) {
    __shared__ float r1[128], r2[128];
    int z = blockIdx.z;
    x += (size_t)z * SQ * EMB; delta += (size_t)z * SQ * EMB;
    g += z * EMB; b += z * EMB;
    int r = blockIdx.x, t = threadIdx.x;
    float y[3];
    float s1 = 0.f, s2 = 0.f;
#pragma unroll
    for (int i = 0; i < 3; i++) {
        int c = t + i * 128;
        float v = 0.f;
        if (c < EMB) v = x[(size_t)r * EMB + c] + delta[(size_t)r * EMB + c];
        y[i] = v; s1 += v; s2 += v * v;
    }
    r1[t] = s1; r2[t] = s2;
    __syncthreads();
    for (int off = 64; off > 0; off >>= 1) {
        if (t < off) { r1[t] += r1[t + off]; r2[t] += r2[t + off]; }
        __syncthreads();
    }
    float mu = r1[0] / (float)EMB;
    float var = r2[0] / (float)EMB - mu * mu;
    float rstd = rsqrtf(var + 1e-5f);
#pragma unroll
    for (int i = 0; i < 3; i++) {
        int c = t + i * 128;
        if (c < EMB) x[(size_t)r * EMB + c] = (y[i] - mu) * rstd * g[c] + b[c];
    }
}

// ---------------- row softmax over A: fp32 in, bf16 out ----------------
__global__ void softmax_rows(const float* __restrict__ A, __nv_bfloat16* __restrict__ Ab) {
    __shared__ float row[SQ];
    __shared__ float red[256];
    int r = blockIdx.x, t = threadIdx.x;
    float mx = -INFINITY;
    for (int j = t; j < SQ; j += 256) { float v = A[(size_t)r * SQ + j]; row[j] = v; mx = fmaxf(mx, v); }
    red[t] = mx; __syncthreads();
    for (int off = 128; off > 0; off >>= 1) { if (t < off) red[t] = fmaxf(red[t], red[t + off]); __syncthreads(); }
    mx = red[0];
    __syncthreads();
    float s = 0.f;
    for (int j = t; j < SQ; j += 256) { float e = __expf(row[j] - mx); row[j] = e; s += e; }
    red[t] = s; __syncthreads();
    for (int off = 128; off > 0; off >>= 1) { if (t < off) red[t] += red[t + off]; __syncthreads(); }
    float inv = 1.f / red[0];
    uint32_t* out = (uint32_t*)(Ab + (size_t)r * SQ);
    for (int j = 2 * t; j < SQ; j += 512)
        out[j >> 1] = packbf(row[j] * inv, row[j + 1] * inv);
}

// ---------------- column sum of elementwise max ----------------
__global__ void colsum_max_kernel(const float* __restrict__ X, const float* __restrict__ Y,
                                  float* __restrict__ out) {
    __shared__ float red[256];
    int c = blockIdx.x, t = threadIdx.x;
    float s = 0.f;
    for (int r = t; r < SQ; r += 256)
        s += fmaxf(X[(size_t)r * EMB + c], Y[(size_t)r * EMB + c]);
    red[t] = s; __syncthreads();
    for (int off = 128; off > 0; off >>= 1) { if (t < off) red[t] += red[t + off]; __syncthreads(); }
    if (t == 0) out[c] = red[0];
}

// ---------------- tiny FC layers ----------------
__global__ void fc1_kernel(const float* __restrict__ inp, const float* __restrict__ w,
                           const float* __restrict__ b, float* __restrict__ out) {
    __shared__ float red[128];
    int i = blockIdx.x, t = threadIdx.x;
    float s = 0.f;
    for (int j = t; j < 2 * EMB; j += 128) s += inp[j] * w[(size_t)i * 2 * EMB + j];
    red[t] = s; __syncthreads();
    for (int off = 64; off > 0; off >>= 1) { if (t < off) red[t] += red[t + off]; __syncthreads(); }
    if (t == 0) out[i] = fmaxf(red[0] + b[i], 0.f);
}

__global__ void fc2_kernel(const float* __restrict__ inp, const float* __restrict__ w,
                           const float* __restrict__ b, float* __restrict__ out) {
    __shared__ float red[256];
    int t = threadIdx.x;
    float s = 0.f;
    for (int j = t; j < EMB; j += 256) s += inp[j] * w[j];
    red[t] = s; __syncthreads();
    for (int off = 128; off > 0; off >>= 1) { if (t < off) red[t] += red[t + off]; __syncthreads(); }
    if (t == 0) out[0] = red[0] + b[0];
}

// ---------------- host orchestration ----------------
extern "C" void kernel_launch(void* const* d_in, const int* in_sizes, int n_in,
                              void* d_out, int out_size) {
    const float* solv = (const float*)d_in[0];
    const float* solu = (const float*)d_in[1];
    const float* ipw  = (const float*)d_in[2];
    const float* ipb  = (const float*)d_in[3];
    const float* ow   = (const float*)d_in[4];
    const float* ob   = (const float*)d_in[5];
    const float* g1   = (const float*)d_in[6];
    const float* b1   = (const float*)d_in[7];
    const float* w1   = (const float*)d_in[8];
    const float* bb1  = (const float*)d_in[9];
    const float* w2   = (const float*)d_in[10];
    const float* bb2  = (const float*)d_in[11];
    const float* g2   = (const float*)d_in[12];
    const float* b2   = (const float*)d_in[13];
    const float* fc1w = (const float*)d_in[14];
    const float* fc1b = (const float*)d_in[15];
    const float* fc2w = (const float*)d_in[16];
    const float* fc2b = (const float*)d_in[17];

    float *x, *qkv, *o, *t1, *ff, *A, *P, *Q, *Pp, *Qp, *po, *pml, *suv, *fc1o;
    __nv_bfloat16* Ab;
    cudaGetSymbolAddress((void**)&x,    g_x);
    cudaGetSymbolAddress((void**)&qkv,  g_qkv);
    cudaGetSymbolAddress((void**)&o,    g_o);
    cudaGetSymbolAddress((void**)&t1,   g_t1);
    cudaGetSymbolAddress((void**)&ff,   g_ff);
    cudaGetSymbolAddress((void**)&A,    g_A);
    cudaGetSymbolAddress((void**)&Ab,   g_Ab);
    cudaGetSymbolAddress((void**)&P,    g_P);
    cudaGetSymbolAddress((void**)&Q,    g_Q);
    cudaGetSymbolAddress((void**)&Pp,   g_Pp);
    cudaGetSymbolAddress((void**)&Qp,   g_Qp);
    cudaGetSymbolAddress((void**)&po,   g_part_o);
    cudaGetSymbolAddress((void**)&pml,  g_part_ml);
    cudaGetSymbolAddress((void**)&suv,  g_suv);
    cudaGetSymbolAddress((void**)&fc1o, g_fc1o);

    const size_t SE = (size_t)SQ * EMB;

    add_pe_kernel<<<dim3((SQ * EMB + 255) / 256, 1, 2), 256>>>(solv, solu, x);

    // qkv = x @ ipw^T + ipb
    mma_gemm<0, 1, 0, 0, 0><<<dim3(15, 32, 2), 256>>>(
        x, ipw, ipb, qkv, SQ, 3 * EMB, EMB, EMB, EMB,
        SE, (size_t)3 * EMB * EMB, 3 * EMB, (size_t)SQ * 3 * EMB, 0);

    attn_mma_kernel<<<dim3(SQ / QB, NCH, 6), 256>>>(qkv, po, pml);
    attn_combine<<<dim3(SQ, NH, 2), 128>>>(po, pml, o);

    // proj = o @ ow^T + ob
    mma_gemm<0, 1, 0, 0, 0><<<dim3(5, 32, 2), 256>>>(
        o, ow, ob, t1, SQ, EMB, EMB, EMB, EMB,
        SE, (size_t)EMB * EMB, EMB, SE, 0);
    ln_kernel<<<dim3(SQ, 1, 2), 128>>>(x, t1, g1, b1);

    // ff1 = relu(x @ w1^T + bb1)
    mma_gemm<0, 1, 1, 0, 0><<<dim3(4, 32, 2), 256>>>(
        x, w1, bb1, ff, SQ, NHID, EMB, EMB, EMB,
        SE, (size_t)NHID * EMB, NHID, (size_t)SQ * NHID, 0);
    // ff2 = ff1 @ w2^T + bb2
    mma_gemm<0, 1, 0, 0, 0><<<dim3(5, 32, 2), 256>>>(
        ff, w2, bb2, t1, SQ, EMB, NHID, NHID, NHID,
        (size_t)SQ * NHID, (size_t)EMB * NHID, EMB, SE, 0);
    ln_kernel<<<dim3(SQ, 1, 2), 128>>>(x, t1, g2, b2);

    float* H = x;
    float* G = x + SE;

    // A = H @ G^T (fp32 out)
    mma_gemm<0, 1, 0, 0, 0><<<dim3(64, 32, 1), 256>>>(
        H, G, (const float*)nullptr, A, SQ, SQ, EMB, EMB, EMB, 0, 0, 0, 0, 0);
    // softmax: fp32 A -> bf16 Ab
    softmax_rows<<<SQ, 256>>>(A, Ab);

    // P = Ab @ G (NN, bf16-A, split-K x2), Q = Ab^T @ H (TN, bf16-A, split-K x2)
    mma_gemm<0, 0, 0, 1, 1><<<dim3(5, 32, SKCH), 256>>>(
        (const float*)Ab, G, (const float*)nullptr, Pp, SQ, EMB, SQ, SQ, EMB, 0, 0, 0, SE, KSPL);
    mma_gemm<1, 0, 0, 1, 1><<<dim3(5, 32, SKCH), 256>>>(
        (const float*)Ab, H, (const float*)nullptr, Qp, SQ, EMB, SQ, SQ, EMB, 0, 0, 0, SE, KSPL);
    reduce_pq<<<dim3((SQ * EMB / 4 + 255) / 256, 2), 256>>>(Pp, Qp, P, Q);

    colsum_max_kernel<<<EMB, 256>>>(H, P, suv);
    colsum_max_kernel<<<EMB, 256>>>(G, Q, suv + EMB);

    fc1_kernel<<<EMB, 128>>>(suv, fc1w, fc1b, fc1o);
    fc2_kernel<<<1, 256>>>(fc1o, fc2w, fc2b, (float*)d_out);
}

// round 7
// speedup vs baseline: 1.1050x; 1.1050x over previous
#include <cuda_runtime.h>
#include <cuda_bf16.h>
#include <math.h>
#include <stdint.h>

#define SQ   4096
#define EMB  300
#define NH   3
#define HDIM 100
#define NHID 200
#define QB   64
#define TJ   32
#define JCH  1024
#define NCH  4
#define KSPL 1024
#define KCF  64    // k floats per gemm tile
#define KPR  32    // packed pair-rows per tile
#define ASTR 136   // As smem stride (words)
#define BSTR 72    // Bs smem stride (words)

// ---------------- scratch (static device globals; no allocation) ----------------
__device__ float g_x[2 * SQ * EMB];
__device__ float g_qkv[2 * SQ * 3 * EMB];
__device__ float g_o[2 * SQ * EMB];
__device__ float g_t1[2 * SQ * EMB];
__device__ float g_ff[2 * SQ * NHID];
__device__ float g_A[SQ * SQ];                 // fp32 scores
__device__ __nv_bfloat16 g_Ab[SQ * SQ];        // bf16 softmaxed A
__device__ float g_P[SQ * EMB];
__device__ float g_Q[SQ * EMB];
__device__ float g_Pp[NCH * SQ * EMB];
__device__ float g_Qp[NCH * SQ * EMB];
__device__ float g_part_o[6 * NCH * SQ * HDIM];
__device__ float g_part_ml[6 * NCH * SQ * 2];
__device__ float g_suv[2 * EMB];
__device__ float g_fc1o[EMB];

// ---------------- positional encoding + add ----------------
__global__ void add_pe_kernel(const float* __restrict__ solv, const float* __restrict__ solu,
                              float* __restrict__ x) {
    int idx = blockIdx.x * blockDim.x + threadIdx.x;
    if (idx >= SQ * EMB) return;
    int z = blockIdx.z;
    const float* src = z ? solu : solv;
    int s = idx / EMB, c = idx % EMB;
    int k = c >> 1;
    float dv = expf(-(float)(2 * k) * (logf(10000.0f) / (float)EMB));
    float arg = (float)s * dv;
    float pe = (c & 1) ? cosf(arg) : sinf(arg);
    x[(size_t)z * SQ * EMB + idx] = src[idx] + pe;
}

// ---------------- bf16 helpers ----------------
__device__ __forceinline__ uint32_t packbf(float lo, float hi) {
    uint32_t r;
    asm("cvt.rn.bf16x2.f32 %0, %1, %2;" : "=r"(r) : "f"(hi), "f"(lo));
    return r;
}

#define MMA_BF16(C, A, B0, B1)                                                  \
    asm volatile(                                                               \
        "mma.sync.aligned.m16n8k16.row.col.f32.bf16.bf16.f32 "                  \
        "{%0,%1,%2,%3},{%4,%5,%6,%7},{%8,%9},{%0,%1,%2,%3};"                    \
        : "+f"((C)[0]), "+f"((C)[1]), "+f"((C)[2]), "+f"((C)[3])                \
        : "r"((A)[0]), "r"((A)[1]), "r"((A)[2]), "r"((A)[3]), "r"(B0), "r"(B1))

// ---------------- bf16 tensor-core GEMM (128x64 tile, KCF=64, prefetch) ----------------
// C[m,n] = act( sum_k Ae(m,k)*Be(k,n) + bias[n] ),  ldc = N.  M mult of 128.
// BF16A: A is __nv_bfloat16 (pre-quantized); else fp32 packed on the fly.
template<int TA, int TB, int RELU, int SPLITK, int BF16A>
__global__ __launch_bounds__(256, 2)
void mma_gemm(const float* __restrict__ A, const float* __restrict__ B,
              const float* __restrict__ bias, float* __restrict__ C,
              int M, int N, int K, int lda, int ldb,
              size_t sA, size_t sB, size_t sBias, size_t sC, int kc) {
    int z = blockIdx.z;
    int k_begin = 0, k_end = K;
    if (SPLITK) {
        k_begin = z * kc;
        k_end = min(K, k_begin + kc);
        C += (size_t)z * sC;
    } else {
        A += (size_t)z * sA; B += (size_t)z * sB; C += (size_t)z * sC;
        if (bias) bias += (size_t)z * sBias;
    }
    const __nv_bfloat16* A16 = (const __nv_bfloat16*)A;

    __shared__ uint32_t As[KPR][ASTR];
    __shared__ uint32_t Bs[KPR][BSTR];

    int t = threadIdx.x;
    int warp = t >> 5, lane = t & 31;
    int g = lane >> 2, tig = lane & 3;
    int wm = warp & 3, wn = warp >> 2;
    int row0 = blockIdx.y * 128, col0 = blockIdx.x * 64;
    int wr0 = wm * 32, wc0 = wn * 32;

    float acc[2][4][4];
#pragma unroll
    for (int i = 0; i < 2; i++)
#pragma unroll
        for (int j = 0; j < 4; j++)
#pragma unroll
            for (int h = 0; h < 4; h++) acc[i][j][h] = 0.f;

    uint32_t ra[16], rb[8];
    int nk = (k_end - k_begin + KCF - 1) / KCF;

    auto loadA = [&](int kt) {
        if (!TA) {
            int m = t >> 1, kq = (t & 1) * 32;
            if (BF16A) {
                const uint32_t* Ap = (const uint32_t*)(A16 + (size_t)(row0 + m) * lda + kt + kq);
                if (kt + kq + 31 < k_end) {
#pragma unroll
                    for (int u = 0; u < 16; u++) ra[u] = Ap[u];
                } else {
                    const unsigned short* As16 = (const unsigned short*)(A16 + (size_t)(row0 + m) * lda);
#pragma unroll
                    for (int u = 0; u < 16; u++) {
                        int gk = kt + kq + 2 * u;
                        uint32_t lo = (gk < k_end) ? As16[gk] : 0;
                        uint32_t hi = (gk + 1 < k_end) ? As16[gk + 1] : 0;
                        ra[u] = lo | (hi << 16);
                    }
                }
            } else {
                const float* Ap = A + (size_t)(row0 + m) * lda + kt + kq;
                if (kt + kq + 31 < k_end) {
#pragma unroll
                    for (int u = 0; u < 8; u++) {
                        float4 v = *(const float4*)(Ap + 4 * u);
                        ra[2 * u]     = packbf(v.x, v.y);
                        ra[2 * u + 1] = packbf(v.z, v.w);
                    }
                } else {
#pragma unroll
                    for (int u = 0; u < 16; u++) {
                        int gk = kt + kq + 2 * u;
                        float x0 = (gk < k_end) ? Ap[2 * u] : 0.f;
                        float x1 = (gk + 1 < k_end) ? Ap[2 * u + 1] : 0.f;
                        ra[u] = packbf(x0, x1);
                    }
                }
            }
        } else {
            int kp = t >> 3, mq = (t & 7) * 16;
            int gk0 = kt + 2 * kp;
            bool ok0 = gk0 < k_end, ok1 = gk0 + 1 < k_end;
            if (BF16A) {
                const uint32_t* r0p = (const uint32_t*)(A16 + (size_t)gk0 * lda + row0 + mq);
                const uint32_t* r1p = (const uint32_t*)(A16 + (size_t)(gk0 + 1) * lda + row0 + mq);
                if (ok1) {
#pragma unroll
                    for (int u = 0; u < 8; u++) {
                        uint32_t w0 = r0p[u], w1 = r1p[u];
                        ra[2 * u]     = __byte_perm(w0, w1, 0x5410);
                        ra[2 * u + 1] = __byte_perm(w0, w1, 0x7632);
                    }
                } else {
#pragma unroll
                    for (int u = 0; u < 8; u++) {
                        uint32_t w0 = ok0 ? r0p[u] : 0;
                        ra[2 * u]     = __byte_perm(w0, 0u, 0x5410);
                        ra[2 * u + 1] = __byte_perm(w0, 0u, 0x7632);
                    }
                }
            } else {
                const float* Ap0 = A + (size_t)gk0 * lda + row0 + mq;
                if (ok0 && ok1) {
#pragma unroll
                    for (int u = 0; u < 4; u++) {
                        float4 v0 = *(const float4*)(Ap0 + 4 * u);
                        float4 v1 = *(const float4*)(Ap0 + lda + 4 * u);
                        ra[4 * u]     = packbf(v0.x, v1.x);
                        ra[4 * u + 1] = packbf(v0.y, v1.y);
                        ra[4 * u + 2] = packbf(v0.z, v1.z);
                        ra[4 * u + 3] = packbf(v0.w, v1.w);
                    }
                } else {
#pragma unroll
                    for (int u = 0; u < 16; u++) {
                        float x0 = ok0 ? Ap0[u] : 0.f;
                        float x1 = ok1 ? Ap0[lda + u] : 0.f;
                        ra[u] = packbf(x0, x1);
                    }
                }
            }
        }
    };
    auto loadB = [&](int kt) {
        if (!TB) {
            int kp = t >> 3, nq = (t & 7) * 8;
            int gk0 = kt + 2 * kp;
            const float* Bp0 = B + (size_t)gk0 * ldb + col0 + nq;
            bool ok0 = gk0 < k_end, ok1 = gk0 + 1 < k_end;
            if (ok0 && ok1 && col0 + nq + 7 < N) {
#pragma unroll
                for (int u = 0; u < 2; u++) {
                    float4 v0 = *(const float4*)(Bp0 + 4 * u);
                    float4 v1 = *(const float4*)(Bp0 + ldb + 4 * u);
                    rb[4 * u]     = packbf(v0.x, v1.x);
                    rb[4 * u + 1] = packbf(v0.y, v1.y);
                    rb[4 * u + 2] = packbf(v0.z, v1.z);
                    rb[4 * u + 3] = packbf(v0.w, v1.w);
                }
            } else {
#pragma unroll
                for (int u = 0; u < 8; u++) {
                    bool okn = (col0 + nq + u) < N;
                    float x0 = (ok0 && okn) ? Bp0[u] : 0.f;
                    float x1 = (ok1 && okn) ? Bp0[ldb + u] : 0.f;
                    rb[u] = packbf(x0, x1);
                }
            }
        } else {
            int n = t >> 2, kq = (t & 3) * 16;
            int gn = col0 + n;
            const float* Bp = B + (size_t)gn * ldb + kt + kq;
            bool okn = gn < N;
            if (okn && kt + kq + 15 < k_end) {
#pragma unroll
                for (int u = 0; u < 4; u++) {
                    float4 v = *(const float4*)(Bp + 4 * u);
                    rb[2 * u]     = packbf(v.x, v.y);
                    rb[2 * u + 1] = packbf(v.z, v.w);
                }
            } else {
#pragma unroll
                for (int u = 0; u < 8; u++) {
                    int gk = kt + kq + 2 * u;
                    float x0 = (okn && gk < k_end) ? Bp[2 * u] : 0.f;
                    float x1 = (okn && gk + 1 < k_end) ? Bp[2 * u + 1] : 0.f;
                    rb[u] = packbf(x0, x1);
                }
            }
        }
    };

    loadA(k_begin); loadB(k_begin);
    for (int it = 0; it < nk; it++) {
        if (!TA) {
            int m = t >> 1, kp0 = (t & 1) * 16;
#pragma unroll
            for (int u = 0; u < 16; u++) As[kp0 + u][m] = ra[u];
        } else {
            int kp = t >> 3, mq = (t & 7) * 16;
#pragma unroll
            for (int u = 0; u < 16; u++) As[kp][mq + u] = ra[u];
        }
        if (!TB) {
            int kp = t >> 3, nq = (t & 7) * 8;
#pragma unroll
            for (int u = 0; u < 8; u++) Bs[kp][nq + u] = rb[u];
        } else {
            int n = t >> 2, kp0 = (t & 3) * 8;
#pragma unroll
            for (int u = 0; u < 8; u++) Bs[kp0 + u][n] = rb[u];
        }
        __syncthreads();
        if (it + 1 < nk) { loadA(k_begin + (it + 1) * KCF); loadB(k_begin + (it + 1) * KCF); }
#pragma unroll
        for (int ks = 0; ks < KPR; ks += 8) {
            uint32_t a[2][4], b[4][2];
#pragma unroll
            for (int i = 0; i < 2; i++) {
                int mb = wr0 + i * 16;
                a[i][0] = As[ks + tig][mb + g];
                a[i][1] = As[ks + tig][mb + 8 + g];
                a[i][2] = As[ks + tig + 4][mb + g];
                a[i][3] = As[ks + tig + 4][mb + 8 + g];
            }
#pragma unroll
            for (int j = 0; j < 4; j++) {
                int nb = wc0 + j * 8;
                b[j][0] = Bs[ks + tig][nb + g];
                b[j][1] = Bs[ks + tig + 4][nb + g];
            }
#pragma unroll
            for (int i = 0; i < 2; i++)
#pragma unroll
                for (int j = 0; j < 4; j++)
                    MMA_BF16(acc[i][j], a[i], b[j][0], b[j][1]);
        }
        __syncthreads();
    }

#pragma unroll
    for (int i = 0; i < 2; i++) {
        int r0 = row0 + wr0 + i * 16 + g;
#pragma unroll
        for (int j = 0; j < 4; j++) {
            int cc = col0 + wc0 + j * 8 + tig * 2;
#pragma unroll
            for (int h = 0; h < 2; h++) {
                int gr = r0 + h * 8;
                float v0 = acc[i][j][h * 2], v1 = acc[i][j][h * 2 + 1];
                if (!SPLITK && bias) {
                    if (cc < N) v0 += bias[cc];
                    if (cc + 1 < N) v1 += bias[cc + 1];
                }
                if (RELU) { v0 = fmaxf(v0, 0.f); v1 = fmaxf(v1, 0.f); }
                if (cc + 1 < N) {
                    *(float2*)&C[(size_t)gr * N + cc] = make_float2(v0, v1);
                } else if (cc < N) {
                    C[(size_t)gr * N + cc] = v0;
                }
            }
        }
    }
}

// ---------------- split-K reduce for P and Q (float4, 4 chunks) ----------------
__global__ void reduce_pq(const float* __restrict__ Pp, const float* __restrict__ Qp,
                          float* __restrict__ P, float* __restrict__ Q) {
    int idx = blockIdx.x * 256 + threadIdx.x;
    if (idx >= SQ * EMB / 4) return;
    const float* src = blockIdx.y ? Qp : Pp;
    float* dst = blockIdx.y ? Q : P;
    float4 r = make_float4(0.f, 0.f, 0.f, 0.f);
#pragma unroll
    for (int c = 0; c < NCH; c++) {
        float4 a = ((const float4*)(src + (size_t)c * SQ * EMB))[idx];
        r.x += a.x; r.y += a.y; r.z += a.z; r.w += a.w;
    }
    ((float4*)dst)[idx] = r;
}

// ---------------- bf16 tensor-core flash attention (partials) ----------------
// grid (64, NCH, 6), block 128 = 4 warps x 16 queries
__global__ void attn_mma_kernel(const float* __restrict__ qkv_all,
                                float* __restrict__ part_o, float* __restrict__ part_ml) {
    __shared__ uint32_t k_s[TJ][60];      // K packed along d: [j][d-pair], 56 used
    __shared__ uint32_t v_s[16][108];     // V packed along j: [j-pair][d], 104 used
    __shared__ uint32_t p_s[4][16][20];   // per-warp P: [q-row][j-pair], 16 used

    int z = blockIdx.z, e = z / 3, h = z % 3;
    int qt = (int)gridDim.x - 1 - (int)blockIdx.x;  // heaviest first
    int q0 = qt * QB;
    int c = blockIdx.y, c0 = c * JCH;
    if (c0 > q0 + QB - 1) return;

    const float* qkv = qkv_all + (size_t)e * SQ * 900;
    int t = threadIdx.x, w = t >> 5, lane = t & 31;
    int g = lane >> 2, tig = lane & 3;

    int r0 = q0 + w * 16 + g;
    int r1 = r0 + 8;

    // Q fragments (bf16x2 packed along d), pre-scaled by 1/sqrt(HD)
    uint32_t qf[7][4];
    {
        const float* q0p = qkv + (size_t)r0 * 900 + h * HDIM;
        const float* q1p = qkv + (size_t)r1 * 900 + h * HDIM;
#pragma unroll
        for (int s = 0; s < 7; s++) {
            int d0 = 2 * (s * 8 + tig);
            int d1 = 2 * (s * 8 + tig + 4);
            float a0 = d0 < HDIM ? q0p[d0] * 0.1f : 0.f;
            float a1 = d0 + 1 < HDIM ? q0p[d0 + 1] * 0.1f : 0.f;
            float b0 = d0 < HDIM ? q1p[d0] * 0.1f : 0.f;
            float b1 = d0 + 1 < HDIM ? q1p[d0 + 1] * 0.1f : 0.f;
            float c0f = d1 < HDIM ? q0p[d1] * 0.1f : 0.f;
            float c1f = d1 + 1 < HDIM ? q0p[d1 + 1] * 0.1f : 0.f;
            float e0 = d1 < HDIM ? q1p[d1] * 0.1f : 0.f;
            float e1 = d1 + 1 < HDIM ? q1p[d1 + 1] * 0.1f : 0.f;
            qf[s][0] = packbf(a0, a1);
            qf[s][1] = packbf(b0, b1);
            qf[s][2] = packbf(c0f, c1f);
            qf[s][3] = packbf(e0, e1);
        }
    }

    float of[13][4];
#pragma unroll
    for (int nt = 0; nt < 13; nt++) { of[nt][0] = of[nt][1] = of[nt][2] = of[nt][3] = 0.f; }
    float m0 = -INFINITY, m1 = -INFINITY, l0 = 0.f, l1 = 0.f;

    int jend = min(c0 + JCH, q0 + QB);
    for (int jt = c0; jt < jend; jt += TJ) {
        // stage K (packed along d)
        for (int idx = t; idx < TJ * 56; idx += 128) {
            int row = idx / 56, dp = idx - row * 56;
            int d0 = 2 * dp;
            const float* kp = qkv + (size_t)(jt + row) * 900 + h * HDIM + 300;
            float x0 = d0 < HDIM ? kp[d0] : 0.f;
            float x1 = d0 < HDIM ? kp[d0 + 1] : 0.f;
            k_s[row][dp] = packbf(x0, x1);
        }
        // stage V (packed along j)
        for (int idx = t; idx < 16 * 104; idx += 128) {
            int jp = idx / 104, d = idx - jp * 104;
            const float* vp = qkv + (size_t)(jt + 2 * jp) * 900 + h * HDIM + 600 + d;
            float x0 = d < HDIM ? vp[0] : 0.f;
            float x1 = d < HDIM ? vp[900] : 0.f;
            v_s[jp][d] = packbf(x0, x1);
        }
        __syncthreads();

        // S = Q K^T
        float sc[4][4];
#pragma unroll
        for (int nt = 0; nt < 4; nt++) { sc[nt][0] = sc[nt][1] = sc[nt][2] = sc[nt][3] = 0.f; }
#pragma unroll
        for (int s = 0; s < 7; s++) {
#pragma unroll
            for (int nt = 0; nt < 4; nt++) {
                uint32_t b0 = k_s[nt * 8 + g][s * 8 + tig];
                uint32_t b1 = k_s[nt * 8 + g][s * 8 + tig + 4];
                MMA_BF16(sc[nt], qf[s], b0, b1);
            }
        }

        // causal mask (diagonal steps only)
        if (jt + TJ > q0) {
#pragma unroll
            for (int nt = 0; nt < 4; nt++) {
                int jb = jt + nt * 8 + 2 * tig;
                if (jb > r0)     sc[nt][0] = -INFINITY;
                if (jb + 1 > r0) sc[nt][1] = -INFINITY;
                if (jb > r1)     sc[nt][2] = -INFINITY;
                if (jb + 1 > r1) sc[nt][3] = -INFINITY;
            }
        }

        // online softmax
        float rm0 = -INFINITY, rm1 = -INFINITY;
#pragma unroll
        for (int nt = 0; nt < 4; nt++) {
            rm0 = fmaxf(rm0, fmaxf(sc[nt][0], sc[nt][1]));
            rm1 = fmaxf(rm1, fmaxf(sc[nt][2], sc[nt][3]));
        }
        rm0 = fmaxf(rm0, __shfl_xor_sync(0xffffffffu, rm0, 1));
        rm0 = fmaxf(rm0, __shfl_xor_sync(0xffffffffu, rm0, 2));
        rm1 = fmaxf(rm1, __shfl_xor_sync(0xffffffffu, rm1, 1));
        rm1 = fmaxf(rm1, __shfl_xor_sync(0xffffffffu, rm1, 2));
        float mn0 = fmaxf(m0, rm0), mn1 = fmaxf(m1, rm1);
        float s0 = __expf(m0 - mn0), s1 = __expf(m1 - mn1);

        float rs0 = 0.f, rs1 = 0.f;
#pragma unroll
        for (int nt = 0; nt < 4; nt++) {
            float p0 = __expf(sc[nt][0] - mn0);
            float p1 = __expf(sc[nt][1] - mn0);
            float p2 = __expf(sc[nt][2] - mn1);
            float p3 = __expf(sc[nt][3] - mn1);
            rs0 += p0 + p1;
            rs1 += p2 + p3;
            p_s[w][g][nt * 4 + tig]     = packbf(p0, p1);
            p_s[w][g + 8][nt * 4 + tig] = packbf(p2, p3);
        }
        rs0 += __shfl_xor_sync(0xffffffffu, rs0, 1);
        rs0 += __shfl_xor_sync(0xffffffffu, rs0, 2);
        rs1 += __shfl_xor_sync(0xffffffffu, rs1, 1);
        rs1 += __shfl_xor_sync(0xffffffffu, rs1, 2);
        l0 = l0 * s0 + rs0;
        l1 = l1 * s1 + rs1;
        m0 = mn0; m1 = mn1;

#pragma unroll
        for (int nt = 0; nt < 13; nt++) {
            of[nt][0] *= s0; of[nt][1] *= s0;
            of[nt][2] *= s1; of[nt][3] *= s1;
        }
        __syncwarp();

        // O += P V
#pragma unroll
        for (int ks = 0; ks < 16; ks += 8) {
            uint32_t pa[4];
            pa[0] = p_s[w][g][ks + tig];
            pa[1] = p_s[w][g + 8][ks + tig];
            pa[2] = p_s[w][g][ks + tig + 4];
            pa[3] = p_s[w][g + 8][ks + tig + 4];
#pragma unroll
            for (int nt = 0; nt < 13; nt++) {
                uint32_t b0 = v_s[ks + tig][nt * 8 + g];
                uint32_t b1 = v_s[ks + tig + 4][nt * 8 + g];
                MMA_BF16(of[nt], pa, b0, b1);
            }
        }
        __syncthreads();
    }

    // write partials
    size_t pb0 = (size_t)(z * NCH + c) * SQ + r0;
    size_t pb1 = (size_t)(z * NCH + c) * SQ + r1;
#pragma unroll
    for (int nt = 0; nt < 13; nt++) {
        int d = nt * 8 + 2 * tig;
        if (d < HDIM) {
            *(float2*)&part_o[pb0 * HDIM + d] = make_float2(of[nt][0], of[nt][1]);
            *(float2*)&part_o[pb1 * HDIM + d] = make_float2(of[nt][2], of[nt][3]);
        }
    }
    if (tig == 0) {
        part_ml[pb0 * 2] = m0; part_ml[pb0 * 2 + 1] = l0;
        part_ml[pb1 * 2] = m1; part_ml[pb1 * 2 + 1] = l1;
    }
}

__global__ void attn_combine(const float* __restrict__ part_o,
                             const float* __restrict__ part_ml,
                             float* __restrict__ o_all) {
    int qi = blockIdx.x, h = blockIdx.y, e = blockIdx.z;
    int z = e * 3 + h;
    int t = threadIdx.x;
    int nch = qi / JCH + 1;
    float M = -INFINITY;
    for (int cc = 0; cc < nch; cc++)
        M = fmaxf(M, part_ml[((size_t)(z * NCH + cc) * SQ + qi) * 2]);
    float L = 0.f, acc = 0.f;
    for (int cc = 0; cc < nch; cc++) {
        size_t pb = (size_t)(z * NCH + cc) * SQ + qi;
        float w = __expf(part_ml[pb * 2] - M);
        L += part_ml[pb * 2 + 1] * w;
        if (t < HDIM) acc += w * part_o[pb * HDIM + t];
    }
    if (t < HDIM)
        o_all[((size_t)e * SQ + qi) * EMB + h * HDIM + t] = acc / L;
}

// ---------------- fused residual + LayerNorm ----------------
__global__ void ln_kernel(float* __restrict__ x, const float* __restrict__ delta,
                          const float* __restrict__ g, const float* __restrict__ b) {
    __shared__ float r1[128], r2[128];
    int z = blockIdx.z;
    x += (size_t)z * SQ * EMB; delta += (size_t)z * SQ * EMB;
    g += z * EMB; b += z * EMB;
    int r = blockIdx.x, t = threadIdx.x;
    float y[3];
    float s1 = 0.f, s2 = 0.f;
#pragma unroll
    for (int i = 0; i < 3; i++) {
        int c = t + i * 128;
        float v = 0.f;
        if (c < EMB) v = x[(size_t)r * EMB + c] + delta[(size_t)r * EMB + c];
        y[i] = v; s1 += v; s2 += v * v;
    }
    r1[t] = s1; r2[t] = s2;
    __syncthreads();
    for (int off = 64; off > 0; off >>= 1) {
        if (t < off) { r1[t] += r1[t + off]; r2[t] += r2[t + off]; }
        __syncthreads();
    }
    float mu = r1[0] / (float)EMB;
    float var = r2[0] / (float)EMB - mu * mu;
    float rstd = rsqrtf(var + 1e-5f);
#pragma unroll
    for (int i = 0; i < 3; i++) {
        int c = t + i * 128;
        if (c < EMB) x[(size_t)r * EMB + c] = (y[i] - mu) * rstd * g[c] + b[c];
    }
}

// ---------------- row softmax over A: fp32 in, bf16 out ----------------
__global__ void softmax_rows(const float* __restrict__ A, __nv_bfloat16* __restrict__ Ab) {
    __shared__ float row[SQ];
    __shared__ float red[256];
    int r = blockIdx.x, t = threadIdx.x;
    float mx = -INFINITY;
    for (int j = t; j < SQ; j += 256) { float v = A[(size_t)r * SQ + j]; row[j] = v; mx = fmaxf(mx, v); }
    red[t] = mx; __syncthreads();
    for (int off = 128; off > 0; off >>= 1) { if (t < off) red[t] = fmaxf(red[t], red[t + off]); __syncthreads(); }
    mx = red[0];
    __syncthreads();
    float s = 0.f;
    for (int j = t; j < SQ; j += 256) { float e = __expf(row[j] - mx); row[j] = e; s += e; }
    red[t] = s; __syncthreads();
    for (int off = 128; off > 0; off >>= 1) { if (t < off) red[t] += red[t + off]; __syncthreads(); }
    float inv = 1.f / red[0];
    uint32_t* out = (uint32_t*)(Ab + (size_t)r * SQ);
    for (int j = 2 * t; j < SQ; j += 512)
        out[j >> 1] = packbf(row[j] * inv, row[j + 1] * inv);
}

// ---------------- column sum of elementwise max ----------------
__global__ void colsum_max_kernel(const float* __restrict__ X, const float* __restrict__ Y,
                                  float* __restrict__ out) {
    __shared__ float red[256];
    int c = blockIdx.x, t = threadIdx.x;
    float s = 0.f;
    for (int r = t; r < SQ; r += 256)
        s += fmaxf(X[(size_t)r * EMB + c], Y[(size_t)r * EMB + c]);
    red[t] = s; __syncthreads();
    for (int off = 128; off > 0; off >>= 1) { if (t < off) red[t] += red[t + off]; __syncthreads(); }
    if (t == 0) out[c] = red[0];
}

// ---------------- tiny FC layers ----------------
__global__ void fc1_kernel(const float* __restrict__ inp, const float* __restrict__ w,
                           const float* __restrict__ b, float* __restrict__ out) {
    __shared__ float red[128];
    int i = blockIdx.x, t = threadIdx.x;
    float s = 0.f;
    for (int j = t; j < 2 * EMB; j += 128) s += inp[j] * w[(size_t)i * 2 * EMB + j];
    red[t] = s; __syncthreads();
    for (int off = 64; off > 0; off >>= 1) { if (t < off) red[t] += red[t + off]; __syncthreads(); }
    if (t == 0) out[i] = fmaxf(red[0] + b[i], 0.f);
}

__global__ void fc2_kernel(const float* __restrict__ inp, const float* __restrict__ w,
                           const float* __restrict__ b, float* __restrict__ out) {
    __shared__ float red[256];
    int t = threadIdx.x;
    float s = 0.f;
    for (int j = t; j < EMB; j += 256) s += inp[j] * w[j];
    red[t] = s; __syncthreads();
    for (int off = 128; off > 0; off >>= 1) { if (t < off) red[t] += red[t + off]; __syncthreads(); }
    if (t == 0) out[0] = red[0] + b[0];
}

// ---------------- host orchestration ----------------
extern "C" void kernel_launch(void* const* d_in, const int* in_sizes, int n_in,
                              void* d_out, int out_size) {
    const float* solv = (const float*)d_in[0];
    const float* solu = (const float*)d_in[1];
    const float* ipw  = (const float*)d_in[2];
    const float* ipb  = (const float*)d_in[3];
    const float* ow   = (const float*)d_in[4];
    const float* ob   = (const float*)d_in[5];
    const float* g1   = (const float*)d_in[6];
    const float* b1   = (const float*)d_in[7];
    const float* w1   = (const float*)d_in[8];
    const float* bb1  = (const float*)d_in[9];
    const float* w2   = (const float*)d_in[10];
    const float* bb2  = (const float*)d_in[11];
    const float* g2   = (const float*)d_in[12];
    const float* b2   = (const float*)d_in[13];
    const float* fc1w = (const float*)d_in[14];
    const float* fc1b = (const float*)d_in[15];
    const float* fc2w = (const float*)d_in[16];
    const float* fc2b = (const float*)d_in[17];

    float *x, *qkv, *o, *t1, *ff, *A, *P, *Q, *Pp, *Qp, *po, *pml, *suv, *fc1o;
    __nv_bfloat16* Ab;
    cudaGetSymbolAddress((void**)&x,    g_x);
    cudaGetSymbolAddress((void**)&qkv,  g_qkv);
    cudaGetSymbolAddress((void**)&o,    g_o);
    cudaGetSymbolAddress((void**)&t1,   g_t1);
    cudaGetSymbolAddress((void**)&ff,   g_ff);
    cudaGetSymbolAddress((void**)&A,    g_A);
    cudaGetSymbolAddress((void**)&Ab,   g_Ab);
    cudaGetSymbolAddress((void**)&P,    g_P);
    cudaGetSymbolAddress((void**)&Q,    g_Q);
    cudaGetSymbolAddress((void**)&Pp,   g_Pp);
    cudaGetSymbolAddress((void**)&Qp,   g_Qp);
    cudaGetSymbolAddress((void**)&po,   g_part_o);
    cudaGetSymbolAddress((void**)&pml,  g_part_ml);
    cudaGetSymbolAddress((void**)&suv,  g_suv);
    cudaGetSymbolAddress((void**)&fc1o, g_fc1o);

    const size_t SE = (size_t)SQ * EMB;

    add_pe_kernel<<<dim3((SQ * EMB + 255) / 256, 1, 2), 256>>>(solv, solu, x);

    // qkv = x @ ipw^T + ipb
    mma_gemm<0, 1, 0, 0, 0><<<dim3(15, 32, 2), 256>>>(
        x, ipw, ipb, qkv, SQ, 3 * EMB, EMB, EMB, EMB,
        SE, (size_t)3 * EMB * EMB, 3 * EMB, (size_t)SQ * 3 * EMB, 0);

    attn_mma_kernel<<<dim3(SQ / QB, NCH, 6), 128>>>(qkv, po, pml);
    attn_combine<<<dim3(SQ, NH, 2), 128>>>(po, pml, o);

    // proj = o @ ow^T + ob
    mma_gemm<0, 1, 0, 0, 0><<<dim3(5, 32, 2), 256>>>(
        o, ow, ob, t1, SQ, EMB, EMB, EMB, EMB,
        SE, (size_t)EMB * EMB, EMB, SE, 0);
    ln_kernel<<<dim3(SQ, 1, 2), 128>>>(x, t1, g1, b1);

    // ff1 = relu(x @ w1^T + bb1)
    mma_gemm<0, 1, 1, 0, 0><<<dim3(4, 32, 2), 256>>>(
        x, w1, bb1, ff, SQ, NHID, EMB, EMB, EMB,
        SE, (size_t)NHID * EMB, NHID, (size_t)SQ * NHID, 0);
    // ff2 = ff1 @ w2^T + bb2
    mma_gemm<0, 1, 0, 0, 0><<<dim3(5, 32, 2), 256>>>(
        ff, w2, bb2, t1, SQ, EMB, NHID, NHID, NHID,
        (size_t)SQ * NHID, (size_t)EMB * NHID, EMB, SE, 0);
    ln_kernel<<<dim3(SQ, 1, 2), 128>>>(x, t1, g2, b2);

    float* H = x;
    float* G = x + SE;

    // A = H @ G^T (fp32 out)
    mma_gemm<0, 1, 0, 0, 0><<<dim3(64, 32, 1), 256>>>(
        H, G, (const float*)nullptr, A, SQ, SQ, EMB, EMB, EMB, 0, 0, 0, 0, 0);
    // softmax: fp32 A -> bf16 Ab
    softmax_rows<<<SQ, 256>>>(A, Ab);

    // P = Ab @ G (NN, bf16-A, split-K x4), Q = Ab^T @ H (TN, bf16-A, split-K x4)
    mma_gemm<0, 0, 0, 1, 1><<<dim3(5, 32, NCH), 256>>>(
        (const float*)Ab, G, (const float*)nullptr, Pp, SQ, EMB, SQ, SQ, EMB, 0, 0, 0, SE, KSPL);
    mma_gemm<1, 0, 0, 1, 1><<<dim3(5, 32, NCH), 256>>>(
        (const float*)Ab, H, (const float*)nullptr, Qp, SQ, EMB, SQ, SQ, EMB, 0, 0, 0, SE, KSPL);
    reduce_pq<<<dim3((SQ * EMB / 4 + 255) / 256, 2), 256>>>(Pp, Qp, P, Q);

    colsum_max_kernel<<<EMB, 256>>>(H, P, suv);
    colsum_max_kernel<<<EMB, 256>>>(G, Q, suv + EMB);

    fc1_kernel<<<EMB, 128>>>(suv, fc1w, fc1b, fc1o);
    fc2_kernel<<<1, 256>>>(fc1o, fc2w, fc2b, (float*)d_out);
}

// round 8
// speedup vs baseline: 1.1733x; 1.0619x over previous
#include <cuda_runtime.h>
#include <cuda_bf16.h>
#include <math.h>
#include <stdint.h>

#define SQ   4096
#define EMB  300
#define NH   3
#define HDIM 100
#define NHID 200
#define QB   64
#define TJ   32
#define JCH  1024
#define NCH  4
#define KSPL 1024
#define KCF  64    // k floats per gemm tile
#define KPR  32    // packed pair-rows per tile
#define ASTR 136   // As smem stride (words)
#define BSTR 72    // Bs smem stride (words)

// ---------------- scratch (static device globals; no allocation) ----------------
__device__ float g_x[2 * SQ * EMB];            // fp32 encoder state (residual/LN/colsum)
__device__ uint32_t g_xb[2 * SQ * 150];        // bf16x2 packed x (GEMM A/B operands)
__device__ uint32_t g_qkvb[2 * SQ * 450];      // bf16x2 packed qkv
__device__ uint32_t g_ob[2 * SQ * 150];        // bf16x2 packed attention output
__device__ float g_t1[2 * SQ * EMB];           // proj / ff2 temp (fp32, feeds LN)
__device__ uint32_t g_ffb[2 * SQ * 100];       // bf16x2 packed ff1 output
__device__ float g_A[SQ * SQ];                 // fp32 scores
__device__ __nv_bfloat16 g_Ab[SQ * SQ];        // bf16 softmaxed A
__device__ float g_P[SQ * EMB];
__device__ float g_Q[SQ * EMB];
__device__ float g_Pp[NCH * SQ * EMB];
__device__ float g_Qp[NCH * SQ * EMB];
__device__ float g_part_o[6 * NCH * SQ * HDIM];
__device__ float g_part_ml[6 * NCH * SQ * 2];
__device__ float g_suv[2 * EMB];
__device__ float g_fc1o[EMB];

// ---------------- bf16 helpers ----------------
__device__ __forceinline__ uint32_t packbf(float lo, float hi) {
    uint32_t r;
    asm("cvt.rn.bf16x2.f32 %0, %1, %2;" : "=r"(r) : "f"(hi), "f"(lo));
    return r;
}

#define MMA_BF16(C, A, B0, B1)                                                  \
    asm volatile(                                                               \
        "mma.sync.aligned.m16n8k16.row.col.f32.bf16.bf16.f32 "                  \
        "{%0,%1,%2,%3},{%4,%5,%6,%7},{%8,%9},{%0,%1,%2,%3};"                    \
        : "+f"((C)[0]), "+f"((C)[1]), "+f"((C)[2]), "+f"((C)[3])                \
        : "r"((A)[0]), "r"((A)[1]), "r"((A)[2]), "r"((A)[3]), "r"(B0), "r"(B1))

// ---------------- positional encoding + add (pair-packed dual write) ----------------
__global__ void add_pe_kernel(const float* __restrict__ solv, const float* __restrict__ solu,
                              float* __restrict__ x, uint32_t* __restrict__ xb) {
    int p = blockIdx.x * blockDim.x + threadIdx.x;
    if (p >= SQ * 150) return;
    int z = blockIdx.z;
    const float* src = z ? solu : solv;
    int s = p / 150, pc = p - s * 150, c = 2 * pc;
    float dv = __expf(-(float)c * (logf(10000.0f) / (float)EMB));
    float arg = (float)s * dv;
    float pe0 = sinf(arg), pe1 = cosf(arg);
    float2 a = *(const float2*)&src[(size_t)s * EMB + c];
    float v0 = a.x + pe0, v1 = a.y + pe1;
    *(float2*)&x[(size_t)z * SQ * EMB + (size_t)s * EMB + c] = make_float2(v0, v1);
    xb[(size_t)z * SQ * 150 + p] = packbf(v0, v1);
}

// ---------------- bf16 tensor-core GEMM (128x64 tile, KCF=64, prefetch) ----------------
// C[m,n] = act( sum_k Ae(m,k)*Be(k,n) + bias[n] ),  ldc = N.  M mult of 128.
// BF16A / BF16B(TB=1 only): operand pre-packed bf16.  BF16OUT: C is bf16x2 words.
// Strides sA/sB/sC are in 4-byte units.
template<int TA, int TB, int RELU, int SPLITK, int BF16A, int BF16B, int BF16OUT>
__global__ __launch_bounds__(256, 2)
void mma_gemm(const float* __restrict__ A, const float* __restrict__ B,
              const float* __restrict__ bias, float* __restrict__ C,
              int M, int N, int K, int lda, int ldb,
              size_t sA, size_t sB, size_t sBias, size_t sC, int kc) {
    int z = blockIdx.z;
    int k_begin = 0, k_end = K;
    if (SPLITK) {
        k_begin = z * kc;
        k_end = min(K, k_begin + kc);
        C += (size_t)z * sC;
    } else {
        A += (size_t)z * sA; B += (size_t)z * sB; C += (size_t)z * sC;
        if (bias) bias += (size_t)z * sBias;
    }
    const __nv_bfloat16* A16 = (const __nv_bfloat16*)A;
    const __nv_bfloat16* B16 = (const __nv_bfloat16*)B;
    uint32_t* C32 = (uint32_t*)C;

    __shared__ uint32_t As[KPR][ASTR];
    __shared__ uint32_t Bs[KPR][BSTR];

    int t = threadIdx.x;
    int warp = t >> 5, lane = t & 31;
    int g = lane >> 2, tig = lane & 3;
    int wm = warp & 3, wn = warp >> 2;
    int row0 = blockIdx.y * 128, col0 = blockIdx.x * 64;
    int wr0 = wm * 32, wc0 = wn * 32;

    float acc[2][4][4];
#pragma unroll
    for (int i = 0; i < 2; i++)
#pragma unroll
        for (int j = 0; j < 4; j++)
#pragma unroll
            for (int h = 0; h < 4; h++) acc[i][j][h] = 0.f;

    uint32_t ra[16], rb[8];
    int nk = (k_end - k_begin + KCF - 1) / KCF;

    auto loadA = [&](int kt) {
        if (!TA) {
            int m = t >> 1, kq = (t & 1) * 32;
            if (BF16A) {
                const uint32_t* Ap = (const uint32_t*)(A16 + (size_t)(row0 + m) * lda + kt + kq);
                if (kt + kq + 31 < k_end) {
#pragma unroll
                    for (int u = 0; u < 16; u++) ra[u] = Ap[u];
                } else {
                    const unsigned short* As16 = (const unsigned short*)(A16 + (size_t)(row0 + m) * lda);
#pragma unroll
                    for (int u = 0; u < 16; u++) {
                        int gk = kt + kq + 2 * u;
                        uint32_t lo = (gk < k_end) ? As16[gk] : 0;
                        uint32_t hi = (gk + 1 < k_end) ? As16[gk + 1] : 0;
                        ra[u] = lo | (hi << 16);
                    }
                }
            } else {
                const float* Ap = A + (size_t)(row0 + m) * lda + kt + kq;
                if (kt + kq + 31 < k_end) {
#pragma unroll
                    for (int u = 0; u < 8; u++) {
                        float4 v = *(const float4*)(Ap + 4 * u);
                        ra[2 * u]     = packbf(v.x, v.y);
                        ra[2 * u + 1] = packbf(v.z, v.w);
                    }
                } else {
#pragma unroll
                    for (int u = 0; u < 16; u++) {
                        int gk = kt + kq + 2 * u;
                        float x0 = (gk < k_end) ? Ap[2 * u] : 0.f;
                        float x1 = (gk + 1 < k_end) ? Ap[2 * u + 1] : 0.f;
                        ra[u] = packbf(x0, x1);
                    }
                }
            }
        } else {
            int kp = t >> 3, mq = (t & 7) * 16;
            int gk0 = kt + 2 * kp;
            bool ok0 = gk0 < k_end, ok1 = gk0 + 1 < k_end;
            if (BF16A) {
                const uint32_t* r0p = (const uint32_t*)(A16 + (size_t)gk0 * lda + row0 + mq);
                const uint32_t* r1p = (const uint32_t*)(A16 + (size_t)(gk0 + 1) * lda + row0 + mq);
                if (ok1) {
#pragma unroll
                    for (int u = 0; u < 8; u++) {
                        uint32_t w0 = r0p[u], w1 = r1p[u];
                        ra[2 * u]     = __byte_perm(w0, w1, 0x5410);
                        ra[2 * u + 1] = __byte_perm(w0, w1, 0x7632);
                    }
                } else {
#pragma unroll
                    for (int u = 0; u < 8; u++) {
                        uint32_t w0 = ok0 ? r0p[u] : 0;
                        ra[2 * u]     = __byte_perm(w0, 0u, 0x5410);
                        ra[2 * u + 1] = __byte_perm(w0, 0u, 0x7632);
                    }
                }
            } else {
                const float* Ap0 = A + (size_t)gk0 * lda + row0 + mq;
                if (ok0 && ok1) {
#pragma unroll
                    for (int u = 0; u < 4; u++) {
                        float4 v0 = *(const float4*)(Ap0 + 4 * u);
                        float4 v1 = *(const float4*)(Ap0 + lda + 4 * u);
                        ra[4 * u]     = packbf(v0.x, v1.x);
                        ra[4 * u + 1] = packbf(v0.y, v1.y);
                        ra[4 * u + 2] = packbf(v0.z, v1.z);
                        ra[4 * u + 3] = packbf(v0.w, v1.w);
                    }
                } else {
#pragma unroll
                    for (int u = 0; u < 16; u++) {
                        float x0 = ok0 ? Ap0[u] : 0.f;
                        float x1 = ok1 ? Ap0[lda + u] : 0.f;
                        ra[u] = packbf(x0, x1);
                    }
                }
            }
        }
    };
    auto loadB = [&](int kt) {
        if (!TB) {
            int kp = t >> 3, nq = (t & 7) * 8;
            int gk0 = kt + 2 * kp;
            const float* Bp0 = B + (size_t)gk0 * ldb + col0 + nq;
            bool ok0 = gk0 < k_end, ok1 = gk0 + 1 < k_end;
            if (ok0 && ok1 && col0 + nq + 7 < N) {
#pragma unroll
                for (int u = 0; u < 2; u++) {
                    float4 v0 = *(const float4*)(Bp0 + 4 * u);
                    float4 v1 = *(const float4*)(Bp0 + ldb + 4 * u);
                    rb[4 * u]     = packbf(v0.x, v1.x);
                    rb[4 * u + 1] = packbf(v0.y, v1.y);
                    rb[4 * u + 2] = packbf(v0.z, v1.z);
                    rb[4 * u + 3] = packbf(v0.w, v1.w);
                }
            } else {
#pragma unroll
                for (int u = 0; u < 8; u++) {
                    bool okn = (col0 + nq + u) < N;
                    float x0 = (ok0 && okn) ? Bp0[u] : 0.f;
                    float x1 = (ok1 && okn) ? Bp0[ldb + u] : 0.f;
                    rb[u] = packbf(x0, x1);
                }
            }
        } else {
            int n = t >> 2, kq = (t & 3) * 16;
            int gn = col0 + n;
            bool okn = gn < N;
            if (BF16B) {
                const uint32_t* Bp = (const uint32_t*)(B16 + (size_t)gn * ldb + kt + kq);
                if (okn && kt + kq + 15 < k_end) {
#pragma unroll
                    for (int u = 0; u < 8; u++) rb[u] = Bp[u];
                } else {
                    const unsigned short* Bs16 = (const unsigned short*)(B16 + (size_t)gn * ldb);
#pragma unroll
                    for (int u = 0; u < 8; u++) {
                        int gk = kt + kq + 2 * u;
                        uint32_t lo = (okn && gk < k_end) ? Bs16[gk] : 0;
                        uint32_t hi = (okn && gk + 1 < k_end) ? Bs16[gk + 1] : 0;
                        rb[u] = lo | (hi << 16);
                    }
                }
            } else {
                const float* Bp = B + (size_t)gn * ldb + kt + kq;
                if (okn && kt + kq + 15 < k_end) {
#pragma unroll
                    for (int u = 0; u < 4; u++) {
                        float4 v = *(const float4*)(Bp + 4 * u);
                        rb[2 * u]     = packbf(v.x, v.y);
                        rb[2 * u + 1] = packbf(v.z, v.w);
                    }
                } else {
#pragma unroll
                    for (int u = 0; u < 8; u++) {
                        int gk = kt + kq + 2 * u;
                        float x0 = (okn && gk < k_end) ? Bp[2 * u] : 0.f;
                        float x1 = (okn && gk + 1 < k_end) ? Bp[2 * u + 1] : 0.f;
                        rb[u] = packbf(x0, x1);
                    }
                }
            }
        }
    };

    loadA(k_begin); loadB(k_begin);
    for (int it = 0; it < nk; it++) {
        if (!TA) {
            int m = t >> 1, kp0 = (t & 1) * 16;
#pragma unroll
            for (int u = 0; u < 16; u++) As[kp0 + u][m] = ra[u];
        } else {
            int kp = t >> 3, mq = (t & 7) * 16;
#pragma unroll
            for (int u = 0; u < 16; u++) As[kp][mq + u] = ra[u];
        }
        if (!TB) {
            int kp = t >> 3, nq = (t & 7) * 8;
#pragma unroll
            for (int u = 0; u < 8; u++) Bs[kp][nq + u] = rb[u];
        } else {
            int n = t >> 2, kp0 = (t & 3) * 8;
#pragma unroll
            for (int u = 0; u < 8; u++) Bs[kp0 + u][n] = rb[u];
        }
        __syncthreads();
        if (it + 1 < nk) { loadA(k_begin + (it + 1) * KCF); loadB(k_begin + (it + 1) * KCF); }
#pragma unroll
        for (int ks = 0; ks < KPR; ks += 8) {
            uint32_t a[2][4], b[4][2];
#pragma unroll
            for (int i = 0; i < 2; i++) {
                int mb = wr0 + i * 16;
                a[i][0] = As[ks + tig][mb + g];
                a[i][1] = As[ks + tig][mb + 8 + g];
                a[i][2] = As[ks + tig + 4][mb + g];
                a[i][3] = As[ks + tig + 4][mb + 8 + g];
            }
#pragma unroll
            for (int j = 0; j < 4; j++) {
                int nb = wc0 + j * 8;
                b[j][0] = Bs[ks + tig][nb + g];
                b[j][1] = Bs[ks + tig + 4][nb + g];
            }
#pragma unroll
            for (int i = 0; i < 2; i++)
#pragma unroll
                for (int j = 0; j < 4; j++)
                    MMA_BF16(acc[i][j], a[i], b[j][0], b[j][1]);
        }
        __syncthreads();
    }

#pragma unroll
    for (int i = 0; i < 2; i++) {
        int r0 = row0 + wr0 + i * 16 + g;
#pragma unroll
        for (int j = 0; j < 4; j++) {
            int cc = col0 + wc0 + j * 8 + tig * 2;
#pragma unroll
            for (int h = 0; h < 2; h++) {
                int gr = r0 + h * 8;
                float v0 = acc[i][j][h * 2], v1 = acc[i][j][h * 2 + 1];
                if (!SPLITK && bias) {
                    if (cc < N) v0 += bias[cc];
                    if (cc + 1 < N) v1 += bias[cc + 1];
                }
                if (RELU) { v0 = fmaxf(v0, 0.f); v1 = fmaxf(v1, 0.f); }
                if (BF16OUT) {
                    if (cc < N)  // N even, cc even -> cc+1 < N too
                        C32[(size_t)gr * (N >> 1) + (cc >> 1)] = packbf(v0, v1);
                } else if (cc + 1 < N) {
                    *(float2*)&C[(size_t)gr * N + cc] = make_float2(v0, v1);
                } else if (cc < N) {
                    C[(size_t)gr * N + cc] = v0;
                }
            }
        }
    }
}

// ---------------- split-K reduce for P and Q (float4, 4 chunks) ----------------
__global__ void reduce_pq(const float* __restrict__ Pp, const float* __restrict__ Qp,
                          float* __restrict__ P, float* __restrict__ Q) {
    int idx = blockIdx.x * 256 + threadIdx.x;
    if (idx >= SQ * EMB / 4) return;
    const float* src = blockIdx.y ? Qp : Pp;
    float* dst = blockIdx.y ? Q : P;
    float4 r = make_float4(0.f, 0.f, 0.f, 0.f);
#pragma unroll
    for (int c = 0; c < NCH; c++) {
        float4 a = ((const float4*)(src + (size_t)c * SQ * EMB))[idx];
        r.x += a.x; r.y += a.y; r.z += a.z; r.w += a.w;
    }
    ((float4*)dst)[idx] = r;
}

// ---------------- bf16 tensor-core flash attention (packed qkv input) ----------------
// grid (64, NCH, 6), block 128 = 4 warps x 16 queries
__global__ void attn_mma_kernel(const uint32_t* __restrict__ qb_all,
                                float* __restrict__ part_o, float* __restrict__ part_ml) {
    __shared__ uint32_t k_s[TJ][60];      // K packed along d: [j][d-pair], 50 used
    __shared__ uint32_t v_s[16][108];     // V packed along j: [j-pair][d], 104 used
    __shared__ uint32_t p_s[4][16][20];   // per-warp P: [q-row][j-pair], 16 used

    int z = blockIdx.z, e = z / 3, h = z % 3;
    int qt = (int)gridDim.x - 1 - (int)blockIdx.x;  // heaviest first
    int q0 = qt * QB;
    int c = blockIdx.y, c0 = c * JCH;
    if (c0 > q0 + QB - 1) return;

    const uint32_t* qb = qb_all + (size_t)e * SQ * 450;
    int t = threadIdx.x, w = t >> 5, lane = t & 31;
    int g = lane >> 2, tig = lane & 3;

    int r0 = q0 + w * 16 + g;
    int r1 = r0 + 8;

    // Q fragments: raw packed words (d-pairs); scale 0.1 applied to S in fp32
    uint32_t qf[7][4];
    {
        const uint32_t* q0p = qb + (size_t)r0 * 450 + h * 50;
        const uint32_t* q1p = qb + (size_t)r1 * 450 + h * 50;
#pragma unroll
        for (int s = 0; s < 7; s++) {
            int dp0 = s * 8 + tig, dp1 = dp0 + 4;
            qf[s][0] = dp0 < 50 ? q0p[dp0] : 0u;
            qf[s][1] = dp0 < 50 ? q1p[dp0] : 0u;
            qf[s][2] = dp1 < 50 ? q0p[dp1] : 0u;
            qf[s][3] = dp1 < 50 ? q1p[dp1] : 0u;
        }
    }

    float of[13][4];
#pragma unroll
    for (int nt = 0; nt < 13; nt++) { of[nt][0] = of[nt][1] = of[nt][2] = of[nt][3] = 0.f; }
    float m0 = -INFINITY, m1 = -INFINITY, l0 = 0.f, l1 = 0.f;

    int jend = min(c0 + JCH, q0 + QB);
    for (int jt = c0; jt < jend; jt += TJ) {
        // stage K: raw copy of packed d-pairs
        for (int idx = t; idx < TJ * 56; idx += 128) {
            int row = idx / 56, dp = idx - row * 56;
            k_s[row][dp] = dp < 50 ? qb[(size_t)(jt + row) * 450 + 150 + h * 50 + dp] : 0u;
        }
        // stage V: interleave two j rows via byte_perm -> j-pair packing
        for (int idx = t; idx < 16 * 52; idx += 128) {
            int jp = idx / 52, dp = idx - jp * 52;
            uint32_t w0 = 0u, w1 = 0u;
            if (dp < 50) {
                const uint32_t* vb = qb + (size_t)(jt + 2 * jp) * 450 + 300 + h * 50 + dp;
                w0 = vb[0];
                w1 = vb[450];
            }
            v_s[jp][2 * dp]     = __byte_perm(w0, w1, 0x5410);
            v_s[jp][2 * dp + 1] = __byte_perm(w0, w1, 0x7632);
        }
        __syncthreads();

        // S = Q K^T
        float sc[4][4];
#pragma unroll
        for (int nt = 0; nt < 4; nt++) { sc[nt][0] = sc[nt][1] = sc[nt][2] = sc[nt][3] = 0.f; }
#pragma unroll
        for (int s = 0; s < 7; s++) {
#pragma unroll
            for (int nt = 0; nt < 4; nt++) {
                uint32_t b0 = k_s[nt * 8 + g][s * 8 + tig];
                uint32_t b1 = k_s[nt * 8 + g][s * 8 + tig + 4];
                MMA_BF16(sc[nt], qf[s], b0, b1);
            }
        }
        // scale by 1/sqrt(HD)
#pragma unroll
        for (int nt = 0; nt < 4; nt++) {
            sc[nt][0] *= 0.1f; sc[nt][1] *= 0.1f; sc[nt][2] *= 0.1f; sc[nt][3] *= 0.1f;
        }

        // causal mask (diagonal steps only)
        if (jt + TJ > q0) {
#pragma unroll
            for (int nt = 0; nt < 4; nt++) {
                int jb = jt + nt * 8 + 2 * tig;
                if (jb > r0)     sc[nt][0] = -INFINITY;
                if (jb + 1 > r0) sc[nt][1] = -INFINITY;
                if (jb > r1)     sc[nt][2] = -INFINITY;
                if (jb + 1 > r1) sc[nt][3] = -INFINITY;
            }
        }

        // online softmax
        float rm0 = -INFINITY, rm1 = -INFINITY;
#pragma unroll
        for (int nt = 0; nt < 4; nt++) {
            rm0 = fmaxf(rm0, fmaxf(sc[nt][0], sc[nt][1]));
            rm1 = fmaxf(rm1, fmaxf(sc[nt][2], sc[nt][3]));
        }
        rm0 = fmaxf(rm0, __shfl_xor_sync(0xffffffffu, rm0, 1));
        rm0 = fmaxf(rm0, __shfl_xor_sync(0xffffffffu, rm0, 2));
        rm1 = fmaxf(rm1, __shfl_xor_sync(0xffffffffu, rm1, 1));
        rm1 = fmaxf(rm1, __shfl_xor_sync(0xffffffffu, rm1, 2));
        float mn0 = fmaxf(m0, rm0), mn1 = fmaxf(m1, rm1);
        float s0 = __expf(m0 - mn0), s1 = __expf(m1 - mn1);

        float rs0 = 0.f, rs1 = 0.f;
#pragma unroll
        for (int nt = 0; nt < 4; nt++) {
            float p0 = __expf(sc[nt][0] - mn0);
            float p1 = __expf(sc[nt][1] - mn0);
            float p2 = __expf(sc[nt][2] - mn1);
            float p3 = __expf(sc[nt][3] - mn1);
            rs0 += p0 + p1;
            rs1 += p2 + p3;
            p_s[w][g][nt * 4 + tig]     = packbf(p0, p1);
            p_s[w][g + 8][nt * 4 + tig] = packbf(p2, p3);
        }
        rs0 += __shfl_xor_sync(0xffffffffu, rs0, 1);
        rs0 += __shfl_xor_sync(0xffffffffu, rs0, 2);
        rs1 += __shfl_xor_sync(0xffffffffu, rs1, 1);
        rs1 += __shfl_xor_sync(0xffffffffu, rs1, 2);
        l0 = l0 * s0 + rs0;
        l1 = l1 * s1 + rs1;
        m0 = mn0; m1 = mn1;

#pragma unroll
        for (int nt = 0; nt < 13; nt++) {
            of[nt][0] *= s0; of[nt][1] *= s0;
            of[nt][2] *= s1; of[nt][3] *= s1;
        }
        __syncwarp();

        // O += P V
#pragma unroll
        for (int ks = 0; ks < 16; ks += 8) {
            uint32_t pa[4];
            pa[0] = p_s[w][g][ks + tig];
            pa[1] = p_s[w][g + 8][ks + tig];
            pa[2] = p_s[w][g][ks + tig + 4];
            pa[3] = p_s[w][g + 8][ks + tig + 4];
#pragma unroll
            for (int nt = 0; nt < 13; nt++) {
                uint32_t b0 = v_s[ks + tig][nt * 8 + g];
                uint32_t b1 = v_s[ks + tig + 4][nt * 8 + g];
                MMA_BF16(of[nt], pa, b0, b1);
            }
        }
        __syncthreads();
    }

    // write partials
    size_t pb0 = (size_t)(z * NCH + c) * SQ + r0;
    size_t pb1 = (size_t)(z * NCH + c) * SQ + r1;
#pragma unroll
    for (int nt = 0; nt < 13; nt++) {
        int d = nt * 8 + 2 * tig;
        if (d < HDIM) {
            *(float2*)&part_o[pb0 * HDIM + d] = make_float2(of[nt][0], of[nt][1]);
            *(float2*)&part_o[pb1 * HDIM + d] = make_float2(of[nt][2], of[nt][3]);
        }
    }
    if (tig == 0) {
        part_ml[pb0 * 2] = m0; part_ml[pb0 * 2 + 1] = l0;
        part_ml[pb1 * 2] = m1; part_ml[pb1 * 2 + 1] = l1;
    }
}

// combine partials -> bf16-packed o.  grid (SQ, 2), block (64, 3)
__global__ void attn_combine(const float* __restrict__ part_o,
                             const float* __restrict__ part_ml,
                             uint32_t* __restrict__ ob) {
    int qi = blockIdx.x, e = blockIdx.y;
    int t = threadIdx.x, h = threadIdx.y;
    int z = e * 3 + h;
    int nch = qi / JCH + 1;
    float M = -INFINITY;
    for (int cc = 0; cc < nch; cc++)
        M = fmaxf(M, part_ml[((size_t)(z * NCH + cc) * SQ + qi) * 2]);
    float L = 0.f, a0 = 0.f, a1 = 0.f;
    for (int cc = 0; cc < nch; cc++) {
        size_t pb = (size_t)(z * NCH + cc) * SQ + qi;
        float w = __expf(part_ml[pb * 2] - M);
        L += part_ml[pb * 2 + 1] * w;
        if (t < 50) {
            float2 v = *(const float2*)&part_o[pb * HDIM + 2 * t];
            a0 += w * v.x; a1 += w * v.y;
        }
    }
    if (t < 50) {
        float inv = 1.f / L;
        ob[((size_t)e * SQ + qi) * 150 + h * 50 + t] = packbf(a0 * inv, a1 * inv);
    }
}

// ---------------- fused residual + LayerNorm (fp32 + packed bf16 dual write) ----------------
__global__ void ln_kernel(float* __restrict__ x, const float* __restrict__ delta,
                          const float* __restrict__ g, const float* __restrict__ b,
                          uint32_t* __restrict__ xb) {
    __shared__ float rs[8];
    int z = blockIdx.z;
    x += (size_t)z * SQ * EMB; delta += (size_t)z * SQ * EMB;
    g += z * EMB; b += z * EMB; xb += (size_t)z * SQ * 150;
    int r = blockIdx.x, t = threadIdx.x;
    int lane = t & 31, wid = t >> 5;
    float v[2][2];
    float s1 = 0.f, s2 = 0.f;
    {
        float2 a = *(const float2*)&x[(size_t)r * EMB + 2 * t];
        float2 d = *(const float2*)&delta[(size_t)r * EMB + 2 * t];
        v[0][0] = a.x + d.x; v[0][1] = a.y + d.y;
        s1 += v[0][0] + v[0][1];
        s2 += v[0][0] * v[0][0] + v[0][1] * v[0][1];
    }
    if (t < 22) {
        int p = t + 128;
        float2 a = *(const float2*)&x[(size_t)r * EMB + 2 * p];
        float2 d = *(const float2*)&delta[(size_t)r * EMB + 2 * p];
        v[1][0] = a.x + d.x; v[1][1] = a.y + d.y;
        s1 += v[1][0] + v[1][1];
        s2 += v[1][0] * v[1][0] + v[1][1] * v[1][1];
    }
#pragma unroll
    for (int off = 16; off > 0; off >>= 1) {
        s1 += __shfl_xor_sync(0xffffffffu, s1, off);
        s2 += __shfl_xor_sync(0xffffffffu, s2, off);
    }
    if (lane == 0) { rs[wid * 2] = s1; rs[wid * 2 + 1] = s2; }
    __syncthreads();
    float S1 = rs[0] + rs[2] + rs[4] + rs[6];
    float S2 = rs[1] + rs[3] + rs[5] + rs[7];
    float mu = S1 / (float)EMB;
    float var = S2 / (float)EMB - mu * mu;
    float rstd = rsqrtf(var + 1e-5f);
    {
        int c = 2 * t;
        float n0 = (v[0][0] - mu) * rstd * g[c] + b[c];
        float n1 = (v[0][1] - mu) * rstd * g[c + 1] + b[c + 1];
        *(float2*)&x[(size_t)r * EMB + c] = make_float2(n0, n1);
        xb[(size_t)r * 150 + t] = packbf(n0, n1);
    }
    if (t < 22) {
        int c = 2 * (t + 128);
        float n0 = (v[1][0] - mu) * rstd * g[c] + b[c];
        float n1 = (v[1][1] - mu) * rstd * g[c + 1] + b[c + 1];
        *(float2*)&x[(size_t)r * EMB + c] = make_float2(n0, n1);
        xb[(size_t)r * 150 + t + 128] = packbf(n0, n1);
    }
}

// ---------------- row softmax over A: fp32 in, bf16 out ----------------
__global__ void softmax_rows(const float* __restrict__ A, __nv_bfloat16* __restrict__ Ab) {
    __shared__ float row[SQ];
    __shared__ float red[256];
    int r = blockIdx.x, t = threadIdx.x;
    float mx = -INFINITY;
    for (int j = t; j < SQ; j += 256) { float v = A[(size_t)r * SQ + j]; row[j] = v; mx = fmaxf(mx, v); }
    red[t] = mx; __syncthreads();
    for (int off = 128; off > 0; off >>= 1) { if (t < off) red[t] = fmaxf(red[t], red[t + off]); __syncthreads(); }
    mx = red[0];
    __syncthreads();
    float s = 0.f;
    for (int j = t; j < SQ; j += 256) { float e = __expf(row[j] - mx); row[j] = e; s += e; }
    red[t] = s; __syncthreads();
    for (int off = 128; off > 0; off >>= 1) { if (t < off) red[t] += red[t + off]; __syncthreads(); }
    float inv = 1.f / red[0];
    uint32_t* out = (uint32_t*)(Ab + (size_t)r * SQ);
    for (int j = 2 * t; j < SQ; j += 512)
        out[j >> 1] = packbf(row[j] * inv, row[j + 1] * inv);
}

// ---------------- column sum of elementwise max ----------------
__global__ void colsum_max_kernel(const float* __restrict__ X, const float* __restrict__ Y,
                                  float* __restrict__ out) {
    __shared__ float red[256];
    int c = blockIdx.x, t = threadIdx.x;
    float s = 0.f;
    for (int r = t; r < SQ; r += 256)
        s += fmaxf(X[(size_t)r * EMB + c], Y[(size_t)r * EMB + c]);
    red[t] = s; __syncthreads();
    for (int off = 128; off > 0; off >>= 1) { if (t < off) red[t] += red[t + off]; __syncthreads(); }
    if (t == 0) out[c] = red[0];
}

// ---------------- tiny FC layers ----------------
__global__ void fc1_kernel(const float* __restrict__ inp, const float* __restrict__ w,
                           const float* __restrict__ b, float* __restrict__ out) {
    __shared__ float red[128];
    int i = blockIdx.x, t = threadIdx.x;
    float s = 0.f;
    for (int j = t; j < 2 * EMB; j += 128) s += inp[j] * w[(size_t)i * 2 * EMB + j];
    red[t] = s; __syncthreads();
    for (int off = 64; off > 0; off >>= 1) { if (t < off) red[t] += red[t + off]; __syncthreads(); }
    if (t == 0) out[i] = fmaxf(red[0] + b[i], 0.f);
}

__global__ void fc2_kernel(const float* __restrict__ inp, const float* __restrict__ w,
                           const float* __restrict__ b, float* __restrict__ out) {
    __shared__ float red[256];
    int t = threadIdx.x;
    float s = 0.f;
    for (int j = t; j < EMB; j += 256) s += inp[j] * w[j];
    red[t] = s; __syncthreads();
    for (int off = 128; off > 0; off >>= 1) { if (t < off) red[t] += red[t + off]; __syncthreads(); }
    if (t == 0) out[0] = red[0] + b[0];
}

// ---------------- host orchestration ----------------
extern "C" void kernel_launch(void* const* d_in, const int* in_sizes, int n_in,
                              void* d_out, int out_size) {
    const float* solv = (const float*)d_in[0];
    const float* solu = (const float*)d_in[1];
    const float* ipw  = (const float*)d_in[2];
    const float* ipb  = (const float*)d_in[3];
    const float* ow   = (const float*)d_in[4];
    const float* ob_b = (const float*)d_in[5];
    const float* g1   = (const float*)d_in[6];
    const float* b1   = (const float*)d_in[7];
    const float* w1   = (const float*)d_in[8];
    const float* bb1  = (const float*)d_in[9];
    const float* w2   = (const float*)d_in[10];
    const float* bb2  = (const float*)d_in[11];
    const float* g2   = (const float*)d_in[12];
    const float* b2   = (const float*)d_in[13];
    const float* fc1w = (const float*)d_in[14];
    const float* fc1b = (const float*)d_in[15];
    const float* fc2w = (const float*)d_in[16];
    const float* fc2b = (const float*)d_in[17];

    float *x, *t1, *A, *P, *Q, *Pp, *Qp, *po, *pml, *suv, *fc1o;
    uint32_t *xb, *qkvb, *ob, *ffb;
    __nv_bfloat16* Ab;
    cudaGetSymbolAddress((void**)&x,    g_x);
    cudaGetSymbolAddress((void**)&xb,   g_xb);
    cudaGetSymbolAddress((void**)&qkvb, g_qkvb);
    cudaGetSymbolAddress((void**)&ob,   g_ob);
    cudaGetSymbolAddress((void**)&t1,   g_t1);
    cudaGetSymbolAddress((void**)&ffb,  g_ffb);
    cudaGetSymbolAddress((void**)&A,    g_A);
    cudaGetSymbolAddress((void**)&Ab,   g_Ab);
    cudaGetSymbolAddress((void**)&P,    g_P);
    cudaGetSymbolAddress((void**)&Q,    g_Q);
    cudaGetSymbolAddress((void**)&Pp,   g_Pp);
    cudaGetSymbolAddress((void**)&Qp,   g_Qp);
    cudaGetSymbolAddress((void**)&po,   g_part_o);
    cudaGetSymbolAddress((void**)&pml,  g_part_ml);
    cudaGetSymbolAddress((void**)&suv,  g_suv);
    cudaGetSymbolAddress((void**)&fc1o, g_fc1o);

    const size_t SE = (size_t)SQ * EMB;

    // x = src + PE (fp32 + bf16 packed)
    add_pe_kernel<<<dim3((SQ * 150 + 255) / 256, 1, 2), 256>>>(solv, solu, x, xb);

    // qkv = x @ ipw^T + ipb  (bf16 A, bf16 packed OUT)
    mma_gemm<0, 1, 0, 0, 1, 0, 1><<<dim3(15, 32, 2), 256>>>(
        (const float*)xb, ipw, ipb, (float*)qkvb, SQ, 3 * EMB, EMB, EMB, EMB,
        (size_t)SQ * 150, (size_t)3 * EMB * EMB, 3 * EMB, (size_t)SQ * 450, 0);

    attn_mma_kernel<<<dim3(SQ / QB, NCH, 6), 128>>>(qkvb, po, pml);
    attn_combine<<<dim3(SQ, 2), dim3(64, 3)>>>(po, pml, ob);

    // proj = o @ ow^T + ob  (bf16 A, fp32 out -> LN)
    mma_gemm<0, 1, 0, 0, 1, 0, 0><<<dim3(5, 32, 2), 256>>>(
        (const float*)ob, ow, ob_b, t1, SQ, EMB, EMB, EMB, EMB,
        (size_t)SQ * 150, (size_t)EMB * EMB, EMB, SE, 0);
    ln_kernel<<<dim3(SQ, 1, 2), 128>>>(x, t1, g1, b1, xb);

    // ff1 = relu(x @ w1^T + bb1)  (bf16 A, bf16 OUT)
    mma_gemm<0, 1, 1, 0, 1, 0, 1><<<dim3(4, 32, 2), 256>>>(
        (const float*)xb, w1, bb1, (float*)ffb, SQ, NHID, EMB, EMB, EMB,
        (size_t)SQ * 150, (size_t)NHID * EMB, NHID, (size_t)SQ * 100, 0);
    // ff2 = ff1 @ w2^T + bb2  (bf16 A, fp32 out -> LN)
    mma_gemm<0, 1, 0, 0, 1, 0, 0><<<dim3(5, 32, 2), 256>>>(
        (const float*)ffb, w2, bb2, t1, SQ, EMB, NHID, NHID, NHID,
        (size_t)SQ * 100, (size_t)EMB * NHID, EMB, SE, 0);
    ln_kernel<<<dim3(SQ, 1, 2), 128>>>(x, t1, g2, b2, xb);

    float* H = x;
    float* G = x + SE;
    uint32_t* Hb = xb;
    uint32_t* Gb = xb + (size_t)SQ * 150;

    // A = H @ G^T  (bf16 A + bf16 B, fp32 out)
    mma_gemm<0, 1, 0, 0, 1, 1, 0><<<dim3(64, 32, 1), 256>>>(
        (const float*)Hb, (const float*)Gb, (const float*)nullptr, A,
        SQ, SQ, EMB, EMB, EMB, 0, 0, 0, 0, 0);
    // softmax: fp32 A -> bf16 Ab
    softmax_rows<<<SQ, 256>>>(A, Ab);

    // P = Ab @ G (NN, bf16-A, split-K x4), Q = Ab^T @ H (TN, bf16-A, split-K x4)
    mma_gemm<0, 0, 0, 1, 1, 0, 0><<<dim3(5, 32, NCH), 256>>>(
        (const float*)Ab, G, (const float*)nullptr, Pp, SQ, EMB, SQ, SQ, EMB, 0, 0, 0, SE, KSPL);
    mma_gemm<1, 0, 0, 1, 1, 0, 0><<<dim3(5, 32, NCH), 256>>>(
        (const float*)Ab, H, (const float*)nullptr, Qp, SQ, EMB, SQ, SQ, EMB, 0, 0, 0, SE, KSPL);
    reduce_pq<<<dim3((SQ * EMB / 4 + 255) / 256, 2), 256>>>(Pp, Qp, P, Q);

    colsum_max_kernel<<<EMB, 256>>>(H, P, suv);
    colsum_max_kernel<<<EMB, 256>>>(G, Q, suv + EMB);

    fc1_kernel<<<EMB, 128>>>(suv, fc1w, fc1b, fc1o);
    fc2_kernel<<<1, 256>>>(fc1o, fc2w, fc2b, (float*)d_out);
}

// round 9
// speedup vs baseline: 1.1915x; 1.0155x over previous
#include <cuda_runtime.h>
#include <cuda_bf16.h>
#include <math.h>
#include <stdint.h>

#define SQ   4096
#define EMB  300
#define NH   3
#define HDIM 100
#define NHID 200
#define QB   64
#define TJ   32
#define JCH  1024
#define NCH  4
#define KSPL 1024
#define ASTR 136   // As smem stride (words)
#define BSTR 72    // Bs smem stride (words)

// ---------------- scratch (static device globals; no allocation) ----------------
__device__ float g_x[2 * SQ * EMB];            // fp32 encoder state
__device__ uint32_t g_xb[2 * SQ * 150];        // bf16x2 packed x
__device__ uint32_t g_xbT[2 * EMB * (SQ / 2)]; // bf16x2 transposed x (k-major)
__device__ uint32_t g_wpack[480000];           // packed weights: ipw|ow|w1|w2
__device__ uint32_t g_qkvb[2 * SQ * 450];
__device__ uint32_t g_ob[2 * SQ * 150];
__device__ float g_t1[2 * SQ * EMB];
__device__ uint32_t g_ffb[2 * SQ * 100];
__device__ float g_A[SQ * SQ];
__device__ __nv_bfloat16 g_Ab[SQ * SQ];
__device__ float g_P[SQ * EMB];
__device__ float g_Q[SQ * EMB];
__device__ float g_Pp[NCH * SQ * EMB];
__device__ float g_Qp[NCH * SQ * EMB];
__device__ float g_part_o[6 * NCH * SQ * HDIM];
__device__ float g_part_ml[6 * NCH * SQ * 2];
__device__ float g_suv[2 * EMB];
__device__ float g_fc1o[EMB];

// ---------------- bf16 helpers ----------------
__device__ __forceinline__ uint32_t packbf(float lo, float hi) {
    uint32_t r;
    asm("cvt.rn.bf16x2.f32 %0, %1, %2;" : "=r"(r) : "f"(hi), "f"(lo));
    return r;
}

#define MMA_BF16(C, A, B0, B1)                                                  \
    asm volatile(                                                               \
        "mma.sync.aligned.m16n8k16.row.col.f32.bf16.bf16.f32 "                  \
        "{%0,%1,%2,%3},{%4,%5,%6,%7},{%8,%9},{%0,%1,%2,%3};"                    \
        : "+f"((C)[0]), "+f"((C)[1]), "+f"((C)[2]), "+f"((C)[3])                \
        : "r"((A)[0]), "r"((A)[1]), "r"((A)[2]), "r"((A)[3]), "r"(B0), "r"(B1))

// ---------------- small packing kernels ----------------
__global__ void pack_flat(const float* __restrict__ src, uint32_t* __restrict__ dst, int nw) {
    int i = blockIdx.x * 256 + threadIdx.x;
    if (i < nw) {
        float2 v = ((const float2*)src)[i];
        dst[i] = packbf(v.x, v.y);
    }
}

// x[z][SQ][300] fp32 -> xT[z][300][SQ/2] bf16x2 words (k-major pairs)
__global__ void transpose_pack(const float* __restrict__ x, uint32_t* __restrict__ xT) {
    __shared__ float tile[64][65];
    int z = blockIdx.z;
    int s0 = blockIdx.x * 64, c0 = blockIdx.y * 64;
    int t = threadIdx.x;
#pragma unroll
    for (int i = 0; i < 16; i++) {
        int idx = t + i * 256;
        int ls = idx >> 6, lc = idx & 63;
        int c = c0 + lc;
        tile[ls][lc] = (c < EMB) ? x[(size_t)z * SQ * EMB + (size_t)(s0 + ls) * EMB + c] : 0.f;
    }
    __syncthreads();
#pragma unroll
    for (int i = 0; i < 8; i++) {
        int idx = t + i * 256;
        int lc = idx >> 5, lsp = idx & 31;
        int c = c0 + lc;
        if (c < EMB)
            xT[(size_t)z * EMB * (SQ / 2) + (size_t)c * (SQ / 2) + (s0 >> 1) + lsp] =
                packbf(tile[2 * lsp][lc], tile[2 * lsp + 1][lc]);
    }
}

// ---------------- positional encoding + add ----------------
__global__ void add_pe_kernel(const float* __restrict__ solv, const float* __restrict__ solu,
                              float* __restrict__ x, uint32_t* __restrict__ xb) {
    int p = blockIdx.x * blockDim.x + threadIdx.x;
    if (p >= SQ * 150) return;
    int z = blockIdx.z;
    const float* src = z ? solu : solv;
    int s = p / 150, pc = p - s * 150, c = 2 * pc;
    float dv = __expf(-(float)c * (logf(10000.0f) / (float)EMB));
    float arg = (float)s * dv;
    float pe0 = sinf(arg), pe1 = cosf(arg);
    float2 a = *(const float2*)&src[(size_t)s * EMB + c];
    float v0 = a.x + pe0, v1 = a.y + pe1;
    *(float2*)&x[(size_t)z * SQ * EMB + (size_t)s * EMB + c] = make_float2(v0, v1);
    xb[(size_t)z * SQ * 150 + p] = packbf(v0, v1);
}

// ---------------- all-bf16 tensor-core GEMM (128x64 tile, KCF=32, double-buffered) ----
// C[m,n] = act( sum_k Ae(m,k)*Be(k,n) + bias[n] ),  ldc = N.  M mult of 128.
// A: bf16. TA=0: row-major [M][lda]. TA=1: [K][lda] (interleaved on stage).
// B: bf16, always k-major rows: Be(k,n) = B[n*ldb + k].
template<int TA, int RELU, int SPLITK, int BF16OUT>
__global__ __launch_bounds__(256, 2)
void mma2(const __nv_bfloat16* __restrict__ A, const __nv_bfloat16* __restrict__ B,
          const float* __restrict__ bias, float* __restrict__ C,
          int M, int N, int K, int lda, int ldb,
          size_t sA, size_t sB, size_t sBias, size_t sC, int kc) {
    int z = blockIdx.z;
    int k_begin = 0, k_end = K;
    if (SPLITK) {
        k_begin = z * kc;
        k_end = min(K, k_begin + kc);
        C += (size_t)z * sC;
    } else {
        A += (size_t)z * sA; B += (size_t)z * sB; C += (size_t)z * sC;
        if (bias) bias += (size_t)z * sBias;
    }
    uint32_t* C32 = (uint32_t*)C;

    __shared__ uint32_t As[2][16][ASTR];
    __shared__ uint32_t Bs[2][16][BSTR];

    int t = threadIdx.x;
    int warp = t >> 5, lane = t & 31;
    int g = lane >> 2, tig = lane & 3;
    int wm = warp & 3, wn = warp >> 2;
    int row0 = blockIdx.y * 128, col0 = blockIdx.x * 64;
    int wr0 = wm * 32, wc0 = wn * 32;

    float acc[2][4][4];
#pragma unroll
    for (int i = 0; i < 2; i++)
#pragma unroll
        for (int j = 0; j < 4; j++)
#pragma unroll
            for (int h = 0; h < 4; h++) acc[i][j][h] = 0.f;

    uint32_t ra[8], rb[4];

    auto loadA = [&](int kt) {
        if (!TA) {
            int m = t >> 1, kq = (t & 1) * 16;
            const uint32_t* Ap = (const uint32_t*)(A + (size_t)(row0 + m) * lda + kt + kq);
            if (kt + kq + 15 < k_end) {
#pragma unroll
                for (int u = 0; u < 8; u++) ra[u] = Ap[u];
            } else {
                const unsigned short* A16 = (const unsigned short*)(A + (size_t)(row0 + m) * lda);
#pragma unroll
                for (int u = 0; u < 8; u++) {
                    int gk = kt + kq + 2 * u;
                    uint32_t lo = (gk < k_end) ? A16[gk] : 0;
                    uint32_t hi = (gk + 1 < k_end) ? A16[gk + 1] : 0;
                    ra[u] = lo | (hi << 16);
                }
            }
        } else {
            int kp = t >> 4, mq = (t & 15) * 8;
            int gk0 = kt + 2 * kp;
            bool ok0 = gk0 < k_end, ok1 = gk0 + 1 < k_end;
            const uint32_t* r0p = (const uint32_t*)(A + (size_t)gk0 * lda + row0 + mq);
            const uint32_t* r1p = (const uint32_t*)(A + (size_t)(gk0 + 1) * lda + row0 + mq);
            if (ok1) {
#pragma unroll
                for (int u = 0; u < 4; u++) {
                    uint32_t w0 = r0p[u], w1 = r1p[u];
                    ra[2 * u]     = __byte_perm(w0, w1, 0x5410);
                    ra[2 * u + 1] = __byte_perm(w0, w1, 0x7632);
                }
            } else {
#pragma unroll
                for (int u = 0; u < 4; u++) {
                    uint32_t w0 = ok0 ? r0p[u] : 0;
                    ra[2 * u]     = __byte_perm(w0, 0u, 0x5410);
                    ra[2 * u + 1] = __byte_perm(w0, 0u, 0x7632);
                }
            }
        }
    };
    auto loadB = [&](int kt) {
        int n = t >> 2, kq = (t & 3) * 8;
        int gn = col0 + n;
        bool okn = gn < N;
        const uint32_t* Bp = (const uint32_t*)(B + (size_t)gn * ldb + kt + kq);
        if (okn && kt + kq + 7 < k_end) {
#pragma unroll
            for (int u = 0; u < 4; u++) rb[u] = Bp[u];
        } else {
            const unsigned short* B16 = (const unsigned short*)(B + (size_t)gn * ldb);
#pragma unroll
            for (int u = 0; u < 4; u++) {
                int gk = kt + kq + 2 * u;
                uint32_t lo = (okn && gk < k_end) ? B16[gk] : 0;
                uint32_t hi = (okn && gk + 1 < k_end) ? B16[gk + 1] : 0;
                rb[u] = lo | (hi << 16);
            }
        }
    };
    auto storeA = [&](int bf) {
        if (!TA) {
            int m = t >> 1, kp0 = (t & 1) * 8;
#pragma unroll
            for (int u = 0; u < 8; u++) As[bf][kp0 + u][m] = ra[u];
        } else {
            int kp = t >> 4, mq = (t & 15) * 8;
#pragma unroll
            for (int u = 0; u < 8; u++) As[bf][kp][mq + u] = ra[u];
        }
    };
    auto storeB = [&](int bf) {
        int n = t >> 2, kp0 = (t & 3) * 4;
#pragma unroll
        for (int u = 0; u < 4; u++) Bs[bf][kp0 + u][n] = rb[u];
    };

    int nk = (k_end - k_begin + 31) >> 5;
    loadA(k_begin); loadB(k_begin);
    storeA(0); storeB(0);
    __syncthreads();

    int buf = 0;
    for (int it = 0; it < nk; it++) {
        if (it + 1 < nk) { loadA(k_begin + (it + 1) * 32); loadB(k_begin + (it + 1) * 32); }
#pragma unroll
        for (int ks = 0; ks < 16; ks += 8) {
            uint32_t a[2][4], b[4][2];
#pragma unroll
            for (int i = 0; i < 2; i++) {
                int mb = wr0 + i * 16;
                a[i][0] = As[buf][ks + tig][mb + g];
                a[i][1] = As[buf][ks + tig][mb + 8 + g];
                a[i][2] = As[buf][ks + tig + 4][mb + g];
                a[i][3] = As[buf][ks + tig + 4][mb + 8 + g];
            }
#pragma unroll
            for (int j = 0; j < 4; j++) {
                int nb = wc0 + j * 8;
                b[j][0] = Bs[buf][ks + tig][nb + g];
                b[j][1] = Bs[buf][ks + tig + 4][nb + g];
            }
#pragma unroll
            for (int i = 0; i < 2; i++)
#pragma unroll
                for (int j = 0; j < 4; j++)
                    MMA_BF16(acc[i][j], a[i], b[j][0], b[j][1]);
        }
        if (it + 1 < nk) {
            storeA(1 - buf); storeB(1 - buf);
            __syncthreads();
            buf ^= 1;
        }
    }

#pragma unroll
    for (int i = 0; i < 2; i++) {
        int r0 = row0 + wr0 + i * 16 + g;
#pragma unroll
        for (int j = 0; j < 4; j++) {
            int cc = col0 + wc0 + j * 8 + tig * 2;
#pragma unroll
            for (int h = 0; h < 2; h++) {
                int gr = r0 + h * 8;
                float v0 = acc[i][j][h * 2], v1 = acc[i][j][h * 2 + 1];
                if (!SPLITK && bias) {
                    if (cc < N) v0 += bias[cc];
                    if (cc + 1 < N) v1 += bias[cc + 1];
                }
                if (RELU) { v0 = fmaxf(v0, 0.f); v1 = fmaxf(v1, 0.f); }
                if (BF16OUT) {
                    if (cc < N)
                        C32[(size_t)gr * (N >> 1) + (cc >> 1)] = packbf(v0, v1);
                } else if (cc + 1 < N) {
                    *(float2*)&C[(size_t)gr * N + cc] = make_float2(v0, v1);
                } else if (cc < N) {
                    C[(size_t)gr * N + cc] = v0;
                }
            }
        }
    }
}

// ---------------- split-K reduce for P and Q ----------------
__global__ void reduce_pq(const float* __restrict__ Pp, const float* __restrict__ Qp,
                          float* __restrict__ P, float* __restrict__ Q) {
    int idx = blockIdx.x * 256 + threadIdx.x;
    if (idx >= SQ * EMB / 4) return;
    const float* src = blockIdx.y ? Qp : Pp;
    float* dst = blockIdx.y ? Q : P;
    float4 r = make_float4(0.f, 0.f, 0.f, 0.f);
#pragma unroll
    for (int c = 0; c < NCH; c++) {
        float4 a = ((const float4*)(src + (size_t)c * SQ * EMB))[idx];
        r.x += a.x; r.y += a.y; r.z += a.z; r.w += a.w;
    }
    ((float4*)dst)[idx] = r;
}

// ---------------- bf16 tensor-core flash attention (packed qkv input) ----------------
__global__ void attn_mma_kernel(const uint32_t* __restrict__ qb_all,
                                float* __restrict__ part_o, float* __restrict__ part_ml) {
    __shared__ uint32_t k_s[TJ][60];
    __shared__ uint32_t v_s[16][108];
    __shared__ uint32_t p_s[4][16][20];

    int z = blockIdx.z, e = z / 3, h = z % 3;
    int qt = (int)gridDim.x - 1 - (int)blockIdx.x;
    int q0 = qt * QB;
    int c = blockIdx.y, c0 = c * JCH;
    if (c0 > q0 + QB - 1) return;

    const uint32_t* qb = qb_all + (size_t)e * SQ * 450;
    int t = threadIdx.x, w = t >> 5, lane = t & 31;
    int g = lane >> 2, tig = lane & 3;

    int r0 = q0 + w * 16 + g;
    int r1 = r0 + 8;

    uint32_t qf[7][4];
    {
        const uint32_t* q0p = qb + (size_t)r0 * 450 + h * 50;
        const uint32_t* q1p = qb + (size_t)r1 * 450 + h * 50;
#pragma unroll
        for (int s = 0; s < 7; s++) {
            int dp0 = s * 8 + tig, dp1 = dp0 + 4;
            qf[s][0] = dp0 < 50 ? q0p[dp0] : 0u;
            qf[s][1] = dp0 < 50 ? q1p[dp0] : 0u;
            qf[s][2] = dp1 < 50 ? q0p[dp1] : 0u;
            qf[s][3] = dp1 < 50 ? q1p[dp1] : 0u;
        }
    }

    float of[13][4];
#pragma unroll
    for (int nt = 0; nt < 13; nt++) { of[nt][0] = of[nt][1] = of[nt][2] = of[nt][3] = 0.f; }
    float m0 = -INFINITY, m1 = -INFINITY, l0 = 0.f, l1 = 0.f;

    int jend = min(c0 + JCH, q0 + QB);
    for (int jt = c0; jt < jend; jt += TJ) {
        for (int idx = t; idx < TJ * 56; idx += 128) {
            int row = idx / 56, dp = idx - row * 56;
            k_s[row][dp] = dp < 50 ? qb[(size_t)(jt + row) * 450 + 150 + h * 50 + dp] : 0u;
        }
        for (int idx = t; idx < 16 * 52; idx += 128) {
            int jp = idx / 52, dp = idx - jp * 52;
            uint32_t w0 = 0u, w1 = 0u;
            if (dp < 50) {
                const uint32_t* vb = qb + (size_t)(jt + 2 * jp) * 450 + 300 + h * 50 + dp;
                w0 = vb[0];
                w1 = vb[450];
            }
            v_s[jp][2 * dp]     = __byte_perm(w0, w1, 0x5410);
            v_s[jp][2 * dp + 1] = __byte_perm(w0, w1, 0x7632);
        }
        __syncthreads();

        float sc[4][4];
#pragma unroll
        for (int nt = 0; nt < 4; nt++) { sc[nt][0] = sc[nt][1] = sc[nt][2] = sc[nt][3] = 0.f; }
#pragma unroll
        for (int s = 0; s < 7; s++) {
#pragma unroll
            for (int nt = 0; nt < 4; nt++) {
                uint32_t b0 = k_s[nt * 8 + g][s * 8 + tig];
                uint32_t b1 = k_s[nt * 8 + g][s * 8 + tig + 4];
                MMA_BF16(sc[nt], qf[s], b0, b1);
            }
        }
#pragma unroll
        for (int nt = 0; nt < 4; nt++) {
            sc[nt][0] *= 0.1f; sc[nt][1] *= 0.1f; sc[nt][2] *= 0.1f; sc[nt][3] *= 0.1f;
        }

        if (jt + TJ > q0) {
#pragma unroll
            for (int nt = 0; nt < 4; nt++) {
                int jb = jt + nt * 8 + 2 * tig;
                if (jb > r0)     sc[nt][0] = -INFINITY;
                if (jb + 1 > r0) sc[nt][1] = -INFINITY;
                if (jb > r1)     sc[nt][2] = -INFINITY;
                if (jb + 1 > r1) sc[nt][3] = -INFINITY;
            }
        }

        float rm0 = -INFINITY, rm1 = -INFINITY;
#pragma unroll
        for (int nt = 0; nt < 4; nt++) {
            rm0 = fmaxf(rm0, fmaxf(sc[nt][0], sc[nt][1]));
            rm1 = fmaxf(rm1, fmaxf(sc[nt][2], sc[nt][3]));
        }
        rm0 = fmaxf(rm0, __shfl_xor_sync(0xffffffffu, rm0, 1));
        rm0 = fmaxf(rm0, __shfl_xor_sync(0xffffffffu, rm0, 2));
        rm1 = fmaxf(rm1, __shfl_xor_sync(0xffffffffu, rm1, 1));
        rm1 = fmaxf(rm1, __shfl_xor_sync(0xffffffffu, rm1, 2));
        float mn0 = fmaxf(m0, rm0), mn1 = fmaxf(m1, rm1);
        float s0 = __expf(m0 - mn0), s1 = __expf(m1 - mn1);

        float rs0 = 0.f, rs1 = 0.f;
#pragma unroll
        for (int nt = 0; nt < 4; nt++) {
            float p0 = __expf(sc[nt][0] - mn0);
            float p1 = __expf(sc[nt][1] - mn0);
            float p2 = __expf(sc[nt][2] - mn1);
            float p3 = __expf(sc[nt][3] - mn1);
            rs0 += p0 + p1;
            rs1 += p2 + p3;
            p_s[w][g][nt * 4 + tig]     = packbf(p0, p1);
            p_s[w][g + 8][nt * 4 + tig] = packbf(p2, p3);
        }
        rs0 += __shfl_xor_sync(0xffffffffu, rs0, 1);
        rs0 += __shfl_xor_sync(0xffffffffu, rs0, 2);
        rs1 += __shfl_xor_sync(0xffffffffu, rs1, 1);
        rs1 += __shfl_xor_sync(0xffffffffu, rs1, 2);
        l0 = l0 * s0 + rs0;
        l1 = l1 * s1 + rs1;
        m0 = mn0; m1 = mn1;

#pragma unroll
        for (int nt = 0; nt < 13; nt++) {
            of[nt][0] *= s0; of[nt][1] *= s0;
            of[nt][2] *= s1; of[nt][3] *= s1;
        }
        __syncwarp();

#pragma unroll
        for (int ks = 0; ks < 16; ks += 8) {
            uint32_t pa[4];
            pa[0] = p_s[w][g][ks + tig];
            pa[1] = p_s[w][g + 8][ks + tig];
            pa[2] = p_s[w][g][ks + tig + 4];
            pa[3] = p_s[w][g + 8][ks + tig + 4];
#pragma unroll
            for (int nt = 0; nt < 13; nt++) {
                uint32_t b0 = v_s[ks + tig][nt * 8 + g];
                uint32_t b1 = v_s[ks + tig + 4][nt * 8 + g];
                MMA_BF16(of[nt], pa, b0, b1);
            }
        }
        __syncthreads();
    }

    size_t pb0 = (size_t)(z * NCH + c) * SQ + r0;
    size_t pb1 = (size_t)(z * NCH + c) * SQ + r1;
#pragma unroll
    for (int nt = 0; nt < 13; nt++) {
        int d = nt * 8 + 2 * tig;
        if (d < HDIM) {
            *(float2*)&part_o[pb0 * HDIM + d] = make_float2(of[nt][0], of[nt][1]);
            *(float2*)&part_o[pb1 * HDIM + d] = make_float2(of[nt][2], of[nt][3]);
        }
    }
    if (tig == 0) {
        part_ml[pb0 * 2] = m0; part_ml[pb0 * 2 + 1] = l0;
        part_ml[pb1 * 2] = m1; part_ml[pb1 * 2 + 1] = l1;
    }
}

__global__ void attn_combine(const float* __restrict__ part_o,
                             const float* __restrict__ part_ml,
                             uint32_t* __restrict__ ob) {
    int qi = blockIdx.x, e = blockIdx.y;
    int t = threadIdx.x, h = threadIdx.y;
    int z = e * 3 + h;
    int nch = qi / JCH + 1;
    float M = -INFINITY;
    for (int cc = 0; cc < nch; cc++)
        M = fmaxf(M, part_ml[((size_t)(z * NCH + cc) * SQ + qi) * 2]);
    float L = 0.f, a0 = 0.f, a1 = 0.f;
    for (int cc = 0; cc < nch; cc++) {
        size_t pb = (size_t)(z * NCH + cc) * SQ + qi;
        float w = __expf(part_ml[pb * 2] - M);
        L += part_ml[pb * 2 + 1] * w;
        if (t < 50) {
            float2 v = *(const float2*)&part_o[pb * HDIM + 2 * t];
            a0 += w * v.x; a1 += w * v.y;
        }
    }
    if (t < 50) {
        float inv = 1.f / L;
        ob[((size_t)e * SQ + qi) * 150 + h * 50 + t] = packbf(a0 * inv, a1 * inv);
    }
}

// ---------------- fused residual + LayerNorm ----------------
__global__ void ln_kernel(float* __restrict__ x, const float* __restrict__ delta,
                          const float* __restrict__ g, const float* __restrict__ b,
                          uint32_t* __restrict__ xb) {
    __shared__ float rs[8];
    int z = blockIdx.z;
    x += (size_t)z * SQ * EMB; delta += (size_t)z * SQ * EMB;
    g += z * EMB; b += z * EMB; xb += (size_t)z * SQ * 150;
    int r = blockIdx.x, t = threadIdx.x;
    int lane = t & 31, wid = t >> 5;
    float v[2][2];
    float s1 = 0.f, s2 = 0.f;
    {
        float2 a = *(const float2*)&x[(size_t)r * EMB + 2 * t];
        float2 d = *(const float2*)&delta[(size_t)r * EMB + 2 * t];
        v[0][0] = a.x + d.x; v[0][1] = a.y + d.y;
        s1 += v[0][0] + v[0][1];
        s2 += v[0][0] * v[0][0] + v[0][1] * v[0][1];
    }
    if (t < 22) {
        int p = t + 128;
        float2 a = *(const float2*)&x[(size_t)r * EMB + 2 * p];
        float2 d = *(const float2*)&delta[(size_t)r * EMB + 2 * p];
        v[1][0] = a.x + d.x; v[1][1] = a.y + d.y;
        s1 += v[1][0] + v[1][1];
        s2 += v[1][0] * v[1][0] + v[1][1] * v[1][1];
    }
#pragma unroll
    for (int off = 16; off > 0; off >>= 1) {
        s1 += __shfl_xor_sync(0xffffffffu, s1, off);
        s2 += __shfl_xor_sync(0xffffffffu, s2, off);
    }
    if (lane == 0) { rs[wid * 2] = s1; rs[wid * 2 + 1] = s2; }
    __syncthreads();
    float S1 = rs[0] + rs[2] + rs[4] + rs[6];
    float S2 = rs[1] + rs[3] + rs[5] + rs[7];
    float mu = S1 / (float)EMB;
    float var = S2 / (float)EMB - mu * mu;
    float rstd = rsqrtf(var + 1e-5f);
    {
        int c = 2 * t;
        float n0 = (v[0][0] - mu) * rstd * g[c] + b[c];
        float n1 = (v[0][1] - mu) * rstd * g[c + 1] + b[c + 1];
        *(float2*)&x[(size_t)r * EMB + c] = make_float2(n0, n1);
        xb[(size_t)r * 150 + t] = packbf(n0, n1);
    }
    if (t < 22) {
        int c = 2 * (t + 128);
        float n0 = (v[1][0] - mu) * rstd * g[c] + b[c];
        float n1 = (v[1][1] - mu) * rstd * g[c + 1] + b[c + 1];
        *(float2*)&x[(size_t)r * EMB + c] = make_float2(n0, n1);
        xb[(size_t)r * 150 + t + 128] = packbf(n0, n1);
    }
}

// ---------------- row softmax over A: fp32 in, bf16 out ----------------
__global__ void softmax_rows(const float* __restrict__ A, __nv_bfloat16* __restrict__ Ab) {
    __shared__ float row[SQ];
    __shared__ float red[256];
    int r = blockIdx.x, t = threadIdx.x;
    float mx = -INFINITY;
    for (int j = t; j < SQ; j += 256) { float v = A[(size_t)r * SQ + j]; row[j] = v; mx = fmaxf(mx, v); }
    red[t] = mx; __syncthreads();
    for (int off = 128; off > 0; off >>= 1) { if (t < off) red[t] = fmaxf(red[t], red[t + off]); __syncthreads(); }
    mx = red[0];
    __syncthreads();
    float s = 0.f;
    for (int j = t; j < SQ; j += 256) { float e = __expf(row[j] - mx); row[j] = e; s += e; }
    red[t] = s; __syncthreads();
    for (int off = 128; off > 0; off >>= 1) { if (t < off) red[t] += red[t + off]; __syncthreads(); }
    float inv = 1.f / red[0];
    uint32_t* out = (uint32_t*)(Ab + (size_t)r * SQ);
    for (int j = 2 * t; j < SQ; j += 512)
        out[j >> 1] = packbf(row[j] * inv, row[j + 1] * inv);
}

// ---------------- column sum of elementwise max ----------------
__global__ void colsum_max_kernel(const float* __restrict__ X, const float* __restrict__ Y,
                                  float* __restrict__ out) {
    __shared__ float red[256];
    int c = blockIdx.x, t = threadIdx.x;
    float s = 0.f;
    for (int r = t; r < SQ; r += 256)
        s += fmaxf(X[(size_t)r * EMB + c], Y[(size_t)r * EMB + c]);
    red[t] = s; __syncthreads();
    for (int off = 128; off > 0; off >>= 1) { if (t < off) red[t] += red[t + off]; __syncthreads(); }
    if (t == 0) out[c] = red[0];
}

// ---------------- tiny FC layers ----------------
__global__ void fc1_kernel(const float* __restrict__ inp, const float* __restrict__ w,
                           const float* __restrict__ b, float* __restrict__ out) {
    __shared__ float red[128];
    int i = blockIdx.x, t = threadIdx.x;
    float s = 0.f;
    for (int j = t; j < 2 * EMB; j += 128) s += inp[j] * w[(size_t)i * 2 * EMB + j];
    red[t] = s; __syncthreads();
    for (int off = 64; off > 0; off >>= 1) { if (t < off) red[t] += red[t + off]; __syncthreads(); }
    if (t == 0) out[i] = fmaxf(red[0] + b[i], 0.f);
}

__global__ void fc2_kernel(const float* __restrict__ inp, const float* __restrict__ w,
                           const float* __restrict__ b, float* __restrict__ out) {
    __shared__ float red[256];
    int t = threadIdx.x;
    float s = 0.f;
    for (int j = t; j < EMB; j += 256) s += inp[j] * w[j];
    red[t] = s; __syncthreads();
    for (int off = 128; off > 0; off >>= 1) { if (t < off) red[t] += red[t + off]; __syncthreads(); }
    if (t == 0) out[0] = red[0] + b[0];
}

// ---------------- host orchestration ----------------
extern "C" void kernel_launch(void* const* d_in, const int* in_sizes, int n_in,
                              void* d_out, int out_size) {
    const float* solv = (const float*)d_in[0];
    const float* solu = (const float*)d_in[1];
    const float* ipw  = (const float*)d_in[2];
    const float* ipb  = (const float*)d_in[3];
    const float* ow   = (const float*)d_in[4];
    const float* ob_b = (const float*)d_in[5];
    const float* g1   = (const float*)d_in[6];
    const float* b1   = (const float*)d_in[7];
    const float* w1   = (const float*)d_in[8];
    const float* bb1  = (const float*)d_in[9];
    const float* w2   = (const float*)d_in[10];
    const float* bb2  = (const float*)d_in[11];
    const float* g2   = (const float*)d_in[12];
    const float* b2   = (const float*)d_in[13];
    const float* fc1w = (const float*)d_in[14];
    const float* fc1b = (const float*)d_in[15];
    const float* fc2w = (const float*)d_in[16];
    const float* fc2b = (const float*)d_in[17];

    float *x, *t1, *A, *P, *Q, *Pp, *Qp, *po, *pml, *suv, *fc1o;
    uint32_t *xb, *xbT, *wp, *qkvb, *ob, *ffb;
    __nv_bfloat16* Ab;
    cudaGetSymbolAddress((void**)&x,    g_x);
    cudaGetSymbolAddress((void**)&xb,   g_xb);
    cudaGetSymbolAddress((void**)&xbT,  g_xbT);
    cudaGetSymbolAddress((void**)&wp,   g_wpack);
    cudaGetSymbolAddress((void**)&qkvb, g_qkvb);
    cudaGetSymbolAddress((void**)&ob,   g_ob);
    cudaGetSymbolAddress((void**)&t1,   g_t1);
    cudaGetSymbolAddress((void**)&ffb,  g_ffb);
    cudaGetSymbolAddress((void**)&A,    g_A);
    cudaGetSymbolAddress((void**)&Ab,   g_Ab);
    cudaGetSymbolAddress((void**)&P,    g_P);
    cudaGetSymbolAddress((void**)&Q,    g_Q);
    cudaGetSymbolAddress((void**)&Pp,   g_Pp);
    cudaGetSymbolAddress((void**)&Qp,   g_Qp);
    cudaGetSymbolAddress((void**)&po,   g_part_o);
    cudaGetSymbolAddress((void**)&pml,  g_part_ml);
    cudaGetSymbolAddress((void**)&suv,  g_suv);
    cudaGetSymbolAddress((void**)&fc1o, g_fc1o);

    const size_t SE = (size_t)SQ * EMB;
    // packed weight offsets (words)
    uint32_t* ipwb = wp;            // 2*900*150 = 270000
    uint32_t* owb  = wp + 270000;   // 2*300*150 = 90000
    uint32_t* w1b  = wp + 360000;   // 2*200*150 = 60000
    uint32_t* w2b  = wp + 420000;   // 2*300*100 = 60000

    // weight packing (cheap, graph-captured)
    pack_flat<<<(270000 + 255) / 256, 256>>>(ipw, ipwb, 270000);
    pack_flat<<<(90000 + 255) / 256, 256>>>(ow, owb, 90000);
    pack_flat<<<(60000 + 255) / 256, 256>>>(w1, w1b, 60000);
    pack_flat<<<(60000 + 255) / 256, 256>>>(w2, w2b, 60000);

    add_pe_kernel<<<dim3((SQ * 150 + 255) / 256, 1, 2), 256>>>(solv, solu, x, xb);

    // qkv = x @ ipw^T + ipb  -> bf16 packed
    mma2<0, 0, 0, 1><<<dim3(15, 32, 2), 256>>>(
        (const __nv_bfloat16*)xb, (const __nv_bfloat16*)ipwb, ipb, (float*)qkvb,
        SQ, 3 * EMB, EMB, EMB, EMB,
        (size_t)SQ * EMB, (size_t)3 * EMB * EMB, 3 * EMB, (size_t)SQ * 450, 0);

    attn_mma_kernel<<<dim3(SQ / QB, NCH, 6), 128>>>(qkvb, po, pml);
    attn_combine<<<dim3(SQ, 2), dim3(64, 3)>>>(po, pml, ob);

    // proj = o @ ow^T + ob  -> fp32 (feeds LN)
    mma2<0, 0, 0, 0><<<dim3(5, 32, 2), 256>>>(
        (const __nv_bfloat16*)ob, (const __nv_bfloat16*)owb, ob_b, t1,
        SQ, EMB, EMB, EMB, EMB,
        (size_t)SQ * EMB, (size_t)EMB * EMB, EMB, SE, 0);
    ln_kernel<<<dim3(SQ, 1, 2), 128>>>(x, t1, g1, b1, xb);

    // ff1 = relu(x @ w1^T + bb1) -> bf16 packed
    mma2<0, 1, 0, 1><<<dim3(4, 32, 2), 256>>>(
        (const __nv_bfloat16*)xb, (const __nv_bfloat16*)w1b, bb1, (float*)ffb,
        SQ, NHID, EMB, EMB, EMB,
        (size_t)SQ * EMB, (size_t)NHID * EMB, NHID, (size_t)SQ * 100, 0);
    // ff2 = ff1 @ w2^T + bb2 -> fp32 (feeds LN)
    mma2<0, 0, 0, 0><<<dim3(5, 32, 2), 256>>>(
        (const __nv_bfloat16*)ffb, (const __nv_bfloat16*)w2b, bb2, t1,
        SQ, EMB, NHID, NHID, NHID,
        (size_t)SQ * NHID, (size_t)EMB * NHID, EMB, SE, 0);
    ln_kernel<<<dim3(SQ, 1, 2), 128>>>(x, t1, g2, b2, xb);

    float* H = x;
    float* G = x + SE;
    uint32_t* Hb = xb;
    uint32_t* Gb = xb + (size_t)SQ * 150;

    // transposed bf16 copies for P/Q B-operands (after final LN)
    transpose_pack<<<dim3(SQ / 64, 5, 2), 256>>>(x, xbT);
    const __nv_bfloat16* HbT = (const __nv_bfloat16*)xbT;
    const __nv_bfloat16* GbT = (const __nv_bfloat16*)xbT + (size_t)EMB * SQ;

    // A = H @ G^T  (B = Gb is already k-major rows)
    mma2<0, 0, 0, 0><<<dim3(64, 32, 1), 256>>>(
        (const __nv_bfloat16*)Hb, (const __nv_bfloat16*)Gb, (const float*)nullptr, A,
        SQ, SQ, EMB, EMB, EMB, 0, 0, 0, 0, 0);
    softmax_rows<<<SQ, 256>>>(A, Ab);

    // P = Ab @ G (A NT raw, B = GbT), Q = Ab^T @ H (A TN interleave, B = HbT); split-K x4
    mma2<0, 0, 1, 0><<<dim3(5, 32, NCH), 256>>>(
        Ab, GbT, (const float*)nullptr, Pp, SQ, EMB, SQ, SQ, SQ, 0, 0, 0, SE, KSPL);
    mma2<1, 0, 1, 0><<<dim3(5, 32, NCH), 256>>>(
        Ab, HbT, (const float*)nullptr, Qp, SQ, EMB, SQ, SQ, SQ, 0, 0, 0, SE, KSPL);
    reduce_pq<<<dim3((SQ * EMB / 4 + 255) / 256, 2), 256>>>(Pp, Qp, P, Q);

    colsum_max_kernel<<<EMB, 256>>>(H, P, suv);
    colsum_max_kernel<<<EMB, 256>>>(G, Q, suv + EMB);

    fc1_kernel<<<EMB, 128>>>(suv, fc1w, fc1b, fc1o);
    fc2_kernel<<<1, 256>>>(fc1o, fc2w, fc2b, (float*)d_out);
}

// round 10
// speedup vs baseline: 1.2515x; 1.0503x over previous
#include <cuda_runtime.h>
#include <cuda_bf16.h>
#include <math.h>
#include <stdint.h>

#define SQ   4096
#define EMB  300
#define NH   3
#define HDIM 100
#define NHID 200
#define QB   64
#define TJ   32
#define JCH  1024
#define NCH  4
#define KSPL 1024
#define ASTR 136   // As smem stride (words)
#define BSTR 72    // Bs smem stride (words)

// ---------------- scratch (static device globals; no allocation) ----------------
__device__ float g_x[2 * SQ * EMB];            // fp32 encoder state
__device__ uint32_t g_xb[2 * SQ * 150];        // bf16x2 packed x
__device__ uint32_t g_xbT[2 * EMB * (SQ / 2)]; // bf16x2 transposed x (k-major)
__device__ uint32_t g_wpack[480000];           // packed weights: ipw|ow|w1|w2
__device__ uint32_t g_qkvb[2 * SQ * 450];
__device__ uint32_t g_ob[2 * SQ * 150];
__device__ float g_t1[2 * SQ * EMB];
__device__ uint32_t g_ffb[2 * SQ * 100];
__device__ float g_A[SQ * SQ];
__device__ __nv_bfloat16 g_Ab[SQ * SQ];
__device__ float g_P[SQ * EMB];
__device__ float g_Q[SQ * EMB];
__device__ float g_Pp[NCH * SQ * EMB];
__device__ float g_Qp[NCH * SQ * EMB];
__device__ float g_part_o[6 * NCH * SQ * HDIM];
__device__ float g_part_ml[6 * NCH * SQ * 2];
__device__ float g_colpart[2 * 32 * EMB];      // colsum partials [pair][chunk][col]
__device__ float g_suv[2 * EMB];
__device__ float g_fc1o[EMB];

// ---------------- bf16 helpers ----------------
__device__ __forceinline__ uint32_t packbf(float lo, float hi) {
    uint32_t r;
    asm("cvt.rn.bf16x2.f32 %0, %1, %2;" : "=r"(r) : "f"(hi), "f"(lo));
    return r;
}

#define MMA_BF16(C, A, B0, B1)                                                  \
    asm volatile(                                                               \
        "mma.sync.aligned.m16n8k16.row.col.f32.bf16.bf16.f32 "                  \
        "{%0,%1,%2,%3},{%4,%5,%6,%7},{%8,%9},{%0,%1,%2,%3};"                    \
        : "+f"((C)[0]), "+f"((C)[1]), "+f"((C)[2]), "+f"((C)[3])                \
        : "r"((A)[0]), "r"((A)[1]), "r"((A)[2]), "r"((A)[3]), "r"(B0), "r"(B1))

// ---------------- packing kernels ----------------
// pack all 4 weight tensors in one launch (segments by flat word index)
__global__ void pack4(const float* __restrict__ ipw, const float* __restrict__ ow,
                      const float* __restrict__ w1, const float* __restrict__ w2,
                      uint32_t* __restrict__ dst) {
    int i = blockIdx.x * 256 + threadIdx.x;
    if (i >= 480000) return;
    const float* src;
    int off;
    if (i < 270000)      { src = ipw; off = i; }
    else if (i < 360000) { src = ow;  off = i - 270000; }
    else if (i < 420000) { src = w1;  off = i - 360000; }
    else                 { src = w2;  off = i - 420000; }
    float2 v = ((const float2*)src)[off];
    dst[i] = packbf(v.x, v.y);
}

// x[z][SQ][300] fp32 -> xT[z][300][SQ/2] bf16x2 words (k-major pairs)
__global__ void transpose_pack(const float* __restrict__ x, uint32_t* __restrict__ xT) {
    __shared__ float tile[64][65];
    int z = blockIdx.z;
    int s0 = blockIdx.x * 64, c0 = blockIdx.y * 64;
    int t = threadIdx.x;
#pragma unroll
    for (int i = 0; i < 16; i++) {
        int idx = t + i * 256;
        int ls = idx >> 6, lc = idx & 63;
        int c = c0 + lc;
        tile[ls][lc] = (c < EMB) ? x[(size_t)z * SQ * EMB + (size_t)(s0 + ls) * EMB + c] : 0.f;
    }
    __syncthreads();
#pragma unroll
    for (int i = 0; i < 8; i++) {
        int idx = t + i * 256;
        int lc = idx >> 5, lsp = idx & 31;
        int c = c0 + lc;
        if (c < EMB)
            xT[(size_t)z * EMB * (SQ / 2) + (size_t)c * (SQ / 2) + (s0 >> 1) + lsp] =
                packbf(tile[2 * lsp][lc], tile[2 * lsp + 1][lc]);
    }
}

// ---------------- positional encoding + add ----------------
__global__ void add_pe_kernel(const float* __restrict__ solv, const float* __restrict__ solu,
                              float* __restrict__ x, uint32_t* __restrict__ xb) {
    int p = blockIdx.x * blockDim.x + threadIdx.x;
    if (p >= SQ * 150) return;
    int z = blockIdx.z;
    const float* src = z ? solu : solv;
    int s = p / 150, pc = p - s * 150, c = 2 * pc;
    float dv = __expf(-(float)c * (logf(10000.0f) / (float)EMB));
    float arg = (float)s * dv;
    float pe0 = sinf(arg), pe1 = cosf(arg);
    float2 a = *(const float2*)&src[(size_t)s * EMB + c];
    float v0 = a.x + pe0, v1 = a.y + pe1;
    *(float2*)&x[(size_t)z * SQ * EMB + (size_t)s * EMB + c] = make_float2(v0, v1);
    xb[(size_t)z * SQ * 150 + p] = packbf(v0, v1);
}

// ---------------- all-bf16 tensor-core GEMM (128x64 tile, KCF=32, double-buffered) ----
template<int TA, int RELU, int SPLITK, int BF16OUT>
__global__ __launch_bounds__(256, 2)
void mma2(const __nv_bfloat16* __restrict__ A, const __nv_bfloat16* __restrict__ B,
          const float* __restrict__ bias, float* __restrict__ C,
          int M, int N, int K, int lda, int ldb,
          size_t sA, size_t sB, size_t sBias, size_t sC, int kc) {
    int z = blockIdx.z;
    int k_begin = 0, k_end = K;
    if (SPLITK) {
        k_begin = z * kc;
        k_end = min(K, k_begin + kc);
        C += (size_t)z * sC;
    } else {
        A += (size_t)z * sA; B += (size_t)z * sB; C += (size_t)z * sC;
        if (bias) bias += (size_t)z * sBias;
    }
    uint32_t* C32 = (uint32_t*)C;

    __shared__ uint32_t As[2][16][ASTR];
    __shared__ uint32_t Bs[2][16][BSTR];

    int t = threadIdx.x;
    int warp = t >> 5, lane = t & 31;
    int g = lane >> 2, tig = lane & 3;
    int wm = warp & 3, wn = warp >> 2;
    int row0 = blockIdx.y * 128, col0 = blockIdx.x * 64;
    int wr0 = wm * 32, wc0 = wn * 32;

    float acc[2][4][4];
#pragma unroll
    for (int i = 0; i < 2; i++)
#pragma unroll
        for (int j = 0; j < 4; j++)
#pragma unroll
            for (int h = 0; h < 4; h++) acc[i][j][h] = 0.f;

    uint32_t ra[8], rb[4];

    auto loadA = [&](int kt) {
        if (!TA) {
            int m = t >> 1, kq = (t & 1) * 16;
            const uint32_t* Ap = (const uint32_t*)(A + (size_t)(row0 + m) * lda + kt + kq);
            if (kt + kq + 15 < k_end) {
#pragma unroll
                for (int u = 0; u < 8; u++) ra[u] = Ap[u];
            } else {
                const unsigned short* A16 = (const unsigned short*)(A + (size_t)(row0 + m) * lda);
#pragma unroll
                for (int u = 0; u < 8; u++) {
                    int gk = kt + kq + 2 * u;
                    uint32_t lo = (gk < k_end) ? A16[gk] : 0;
                    uint32_t hi = (gk + 1 < k_end) ? A16[gk + 1] : 0;
                    ra[u] = lo | (hi << 16);
                }
            }
        } else {
            int kp = t >> 4, mq = (t & 15) * 8;
            int gk0 = kt + 2 * kp;
            bool ok0 = gk0 < k_end, ok1 = gk0 + 1 < k_end;
            const uint32_t* r0p = (const uint32_t*)(A + (size_t)gk0 * lda + row0 + mq);
            const uint32_t* r1p = (const uint32_t*)(A + (size_t)(gk0 + 1) * lda + row0 + mq);
            if (ok1) {
#pragma unroll
                for (int u = 0; u < 4; u++) {
                    uint32_t w0 = r0p[u], w1 = r1p[u];
                    ra[2 * u]     = __byte_perm(w0, w1, 0x5410);
                    ra[2 * u + 1] = __byte_perm(w0, w1, 0x7632);
                }
            } else {
#pragma unroll
                for (int u = 0; u < 4; u++) {
                    uint32_t w0 = ok0 ? r0p[u] : 0;
                    ra[2 * u]     = __byte_perm(w0, 0u, 0x5410);
                    ra[2 * u + 1] = __byte_perm(w0, 0u, 0x7632);
                }
            }
        }
    };
    auto loadB = [&](int kt) {
        int n = t >> 2, kq = (t & 3) * 8;
        int gn = col0 + n;
        bool okn = gn < N;
        const uint32_t* Bp = (const uint32_t*)(B + (size_t)gn * ldb + kt + kq);
        if (okn && kt + kq + 7 < k_end) {
#pragma unroll
            for (int u = 0; u < 4; u++) rb[u] = Bp[u];
        } else {
            const unsigned short* B16 = (const unsigned short*)(B + (size_t)gn * ldb);
#pragma unroll
            for (int u = 0; u < 4; u++) {
                int gk = kt + kq + 2 * u;
                uint32_t lo = (okn && gk < k_end) ? B16[gk] : 0;
                uint32_t hi = (okn && gk + 1 < k_end) ? B16[gk + 1] : 0;
                rb[u] = lo | (hi << 16);
            }
        }
    };
    auto storeA = [&](int bf) {
        if (!TA) {
            int m = t >> 1, kp0 = (t & 1) * 8;
#pragma unroll
            for (int u = 0; u < 8; u++) As[bf][kp0 + u][m] = ra[u];
        } else {
            int kp = t >> 4, mq = (t & 15) * 8;
#pragma unroll
            for (int u = 0; u < 8; u++) As[bf][kp][mq + u] = ra[u];
        }
    };
    auto storeB = [&](int bf) {
        int n = t >> 2, kp0 = (t & 3) * 4;
#pragma unroll
        for (int u = 0; u < 4; u++) Bs[bf][kp0 + u][n] = rb[u];
    };

    int nk = (k_end - k_begin + 31) >> 5;
    loadA(k_begin); loadB(k_begin);
    storeA(0); storeB(0);
    __syncthreads();

    int buf = 0;
    for (int it = 0; it < nk; it++) {
        if (it + 1 < nk) { loadA(k_begin + (it + 1) * 32); loadB(k_begin + (it + 1) * 32); }
#pragma unroll
        for (int ks = 0; ks < 16; ks += 8) {
            uint32_t a[2][4], b[4][2];
#pragma unroll
            for (int i = 0; i < 2; i++) {
                int mb = wr0 + i * 16;
                a[i][0] = As[buf][ks + tig][mb + g];
                a[i][1] = As[buf][ks + tig][mb + 8 + g];
                a[i][2] = As[buf][ks + tig + 4][mb + g];
                a[i][3] = As[buf][ks + tig + 4][mb + 8 + g];
            }
#pragma unroll
            for (int j = 0; j < 4; j++) {
                int nb = wc0 + j * 8;
                b[j][0] = Bs[buf][ks + tig][nb + g];
                b[j][1] = Bs[buf][ks + tig + 4][nb + g];
            }
#pragma unroll
            for (int i = 0; i < 2; i++)
#pragma unroll
                for (int j = 0; j < 4; j++)
                    MMA_BF16(acc[i][j], a[i], b[j][0], b[j][1]);
        }
        if (it + 1 < nk) {
            storeA(1 - buf); storeB(1 - buf);
            __syncthreads();
            buf ^= 1;
        }
    }

#pragma unroll
    for (int i = 0; i < 2; i++) {
        int r0 = row0 + wr0 + i * 16 + g;
#pragma unroll
        for (int j = 0; j < 4; j++) {
            int cc = col0 + wc0 + j * 8 + tig * 2;
#pragma unroll
            for (int h = 0; h < 2; h++) {
                int gr = r0 + h * 8;
                float v0 = acc[i][j][h * 2], v1 = acc[i][j][h * 2 + 1];
                if (!SPLITK && bias) {
                    if (cc < N) v0 += bias[cc];
                    if (cc + 1 < N) v1 += bias[cc + 1];
                }
                if (RELU) { v0 = fmaxf(v0, 0.f); v1 = fmaxf(v1, 0.f); }
                if (BF16OUT) {
                    if (cc < N)
                        C32[(size_t)gr * (N >> 1) + (cc >> 1)] = packbf(v0, v1);
                } else if (cc + 1 < N) {
                    *(float2*)&C[(size_t)gr * N + cc] = make_float2(v0, v1);
                } else if (cc < N) {
                    C[(size_t)gr * N + cc] = v0;
                }
            }
        }
    }
}

// ---------------- fused P+Q split-K GEMM (runtime transpose flag) ----------------
// z < NCH: P-chunk (A = Ab row-major NT). z >= NCH: Q-chunk (A = Ab k-major interleave).
__global__ __launch_bounds__(256, 2)
void mma2_pq(const __nv_bfloat16* __restrict__ Ain, const __nv_bfloat16* __restrict__ BP,
             const __nv_bfloat16* __restrict__ BQ, float* __restrict__ CP,
             float* __restrict__ CQ) {
    int z = blockIdx.z;
    int ta = (z >= NCH) ? 1 : 0;
    int zz = ta ? z - NCH : z;
    int k_begin = zz * KSPL, k_end = k_begin + KSPL;
    const __nv_bfloat16* B = ta ? BQ : BP;
    float* C = (ta ? CQ : CP) + (size_t)zz * SQ * EMB;
    const int lda = SQ, ldb = SQ, N = EMB;

    __shared__ uint32_t As[2][16][ASTR];
    __shared__ uint32_t Bs[2][16][BSTR];

    int t = threadIdx.x;
    int warp = t >> 5, lane = t & 31;
    int g = lane >> 2, tig = lane & 3;
    int wm = warp & 3, wn = warp >> 2;
    int row0 = blockIdx.y * 128, col0 = blockIdx.x * 64;
    int wr0 = wm * 32, wc0 = wn * 32;

    float acc[2][4][4];
#pragma unroll
    for (int i = 0; i < 2; i++)
#pragma unroll
        for (int j = 0; j < 4; j++)
#pragma unroll
            for (int h = 0; h < 4; h++) acc[i][j][h] = 0.f;

    uint32_t ra[8], rb[4];

    auto loadA = [&](int kt) {
        if (!ta) {
            int m = t >> 1, kq = (t & 1) * 16;
            const uint32_t* Ap = (const uint32_t*)(Ain + (size_t)(row0 + m) * lda + kt + kq);
#pragma unroll
            for (int u = 0; u < 8; u++) ra[u] = Ap[u];
        } else {
            int kp = t >> 4, mq = (t & 15) * 8;
            int gk0 = kt + 2 * kp;
            const uint32_t* r0p = (const uint32_t*)(Ain + (size_t)gk0 * lda + row0 + mq);
            const uint32_t* r1p = (const uint32_t*)(Ain + (size_t)(gk0 + 1) * lda + row0 + mq);
#pragma unroll
            for (int u = 0; u < 4; u++) {
                uint32_t w0 = r0p[u], w1 = r1p[u];
                ra[2 * u]     = __byte_perm(w0, w1, 0x5410);
                ra[2 * u + 1] = __byte_perm(w0, w1, 0x7632);
            }
        }
    };
    auto loadB = [&](int kt) {
        int n = t >> 2, kq = (t & 3) * 8;
        int gn = col0 + n;
        if (gn < N) {
            const uint32_t* Bp = (const uint32_t*)(B + (size_t)gn * ldb + kt + kq);
#pragma unroll
            for (int u = 0; u < 4; u++) rb[u] = Bp[u];
        } else {
#pragma unroll
            for (int u = 0; u < 4; u++) rb[u] = 0u;
        }
    };
    auto storeA = [&](int bf) {
        if (!ta) {
            int m = t >> 1, kp0 = (t & 1) * 8;
#pragma unroll
            for (int u = 0; u < 8; u++) As[bf][kp0 + u][m] = ra[u];
        } else {
            int kp = t >> 4, mq = (t & 15) * 8;
#pragma unroll
            for (int u = 0; u < 8; u++) As[bf][kp][mq + u] = ra[u];
        }
    };
    auto storeB = [&](int bf) {
        int n = t >> 2, kp0 = (t & 3) * 4;
#pragma unroll
        for (int u = 0; u < 4; u++) Bs[bf][kp0 + u][n] = rb[u];
    };

    const int nk = KSPL >> 5;
    loadA(k_begin); loadB(k_begin);
    storeA(0); storeB(0);
    __syncthreads();

    int buf = 0;
    for (int it = 0; it < nk; it++) {
        if (it + 1 < nk) { loadA(k_begin + (it + 1) * 32); loadB(k_begin + (it + 1) * 32); }
#pragma unroll
        for (int ks = 0; ks < 16; ks += 8) {
            uint32_t a[2][4], b[4][2];
#pragma unroll
            for (int i = 0; i < 2; i++) {
                int mb = wr0 + i * 16;
                a[i][0] = As[buf][ks + tig][mb + g];
                a[i][1] = As[buf][ks + tig][mb + 8 + g];
                a[i][2] = As[buf][ks + tig + 4][mb + g];
                a[i][3] = As[buf][ks + tig + 4][mb + 8 + g];
            }
#pragma unroll
            for (int j = 0; j < 4; j++) {
                int nb = wc0 + j * 8;
                b[j][0] = Bs[buf][ks + tig][nb + g];
                b[j][1] = Bs[buf][ks + tig + 4][nb + g];
            }
#pragma unroll
            for (int i = 0; i < 2; i++)
#pragma unroll
                for (int j = 0; j < 4; j++)
                    MMA_BF16(acc[i][j], a[i], b[j][0], b[j][1]);
        }
        if (it + 1 < nk) {
            storeA(1 - buf); storeB(1 - buf);
            __syncthreads();
            buf ^= 1;
        }
    }

#pragma unroll
    for (int i = 0; i < 2; i++) {
        int r0 = row0 + wr0 + i * 16 + g;
#pragma unroll
        for (int j = 0; j < 4; j++) {
            int cc = col0 + wc0 + j * 8 + tig * 2;
#pragma unroll
            for (int h = 0; h < 2; h++) {
                int gr = r0 + h * 8;
                float v0 = acc[i][j][h * 2], v1 = acc[i][j][h * 2 + 1];
                if (cc + 1 < N) {
                    *(float2*)&C[(size_t)gr * N + cc] = make_float2(v0, v1);
                } else if (cc < N) {
                    C[(size_t)gr * N + cc] = v0;
                }
            }
        }
    }
}

// ---------------- split-K reduce for P and Q ----------------
__global__ void reduce_pq(const float* __restrict__ Pp, const float* __restrict__ Qp,
                          float* __restrict__ P, float* __restrict__ Q) {
    int idx = blockIdx.x * 256 + threadIdx.x;
    if (idx >= SQ * EMB / 4) return;
    const float* src = blockIdx.y ? Qp : Pp;
    float* dst = blockIdx.y ? Q : P;
    float4 r = make_float4(0.f, 0.f, 0.f, 0.f);
#pragma unroll
    for (int c = 0; c < NCH; c++) {
        float4 a = ((const float4*)(src + (size_t)c * SQ * EMB))[idx];
        r.x += a.x; r.y += a.y; r.z += a.z; r.w += a.w;
    }
    ((float4*)dst)[idx] = r;
}

// ---------------- bf16 tensor-core flash attention (packed qkv input) ----------------
__global__ void attn_mma_kernel(const uint32_t* __restrict__ qb_all,
                                float* __restrict__ part_o, float* __restrict__ part_ml) {
    __shared__ uint32_t k_s[TJ][60];
    __shared__ uint32_t v_s[16][108];
    __shared__ uint32_t p_s[4][16][20];

    int z = blockIdx.z, e = z / 3, h = z % 3;
    int qt = (int)gridDim.x - 1 - (int)blockIdx.x;
    int q0 = qt * QB;
    int c = blockIdx.y, c0 = c * JCH;
    if (c0 > q0 + QB - 1) return;

    const uint32_t* qb = qb_all + (size_t)e * SQ * 450;
    int t = threadIdx.x, w = t >> 5, lane = t & 31;
    int g = lane >> 2, tig = lane & 3;

    int r0 = q0 + w * 16 + g;
    int r1 = r0 + 8;

    uint32_t qf[7][4];
    {
        const uint32_t* q0p = qb + (size_t)r0 * 450 + h * 50;
        const uint32_t* q1p = qb + (size_t)r1 * 450 + h * 50;
#pragma unroll
        for (int s = 0; s < 7; s++) {
            int dp0 = s * 8 + tig, dp1 = dp0 + 4;
            qf[s][0] = dp0 < 50 ? q0p[dp0] : 0u;
            qf[s][1] = dp0 < 50 ? q1p[dp0] : 0u;
            qf[s][2] = dp1 < 50 ? q0p[dp1] : 0u;
            qf[s][3] = dp1 < 50 ? q1p[dp1] : 0u;
        }
    }

    float of[13][4];
#pragma unroll
    for (int nt = 0; nt < 13; nt++) { of[nt][0] = of[nt][1] = of[nt][2] = of[nt][3] = 0.f; }
    float m0 = -INFINITY, m1 = -INFINITY, l0 = 0.f, l1 = 0.f;

    int jend = min(c0 + JCH, q0 + QB);
    for (int jt = c0; jt < jend; jt += TJ) {
        for (int idx = t; idx < TJ * 56; idx += 128) {
            int row = idx / 56, dp = idx - row * 56;
            k_s[row][dp] = dp < 50 ? qb[(size_t)(jt + row) * 450 + 150 + h * 50 + dp] : 0u;
        }
        for (int idx = t; idx < 16 * 52; idx += 128) {
            int jp = idx / 52, dp = idx - jp * 52;
            uint32_t w0 = 0u, w1 = 0u;
            if (dp < 50) {
                const uint32_t* vb = qb + (size_t)(jt + 2 * jp) * 450 + 300 + h * 50 + dp;
                w0 = vb[0];
                w1 = vb[450];
            }
            v_s[jp][2 * dp]     = __byte_perm(w0, w1, 0x5410);
            v_s[jp][2 * dp + 1] = __byte_perm(w0, w1, 0x7632);
        }
        __syncthreads();

        float sc[4][4];
#pragma unroll
        for (int nt = 0; nt < 4; nt++) { sc[nt][0] = sc[nt][1] = sc[nt][2] = sc[nt][3] = 0.f; }
#pragma unroll
        for (int s = 0; s < 7; s++) {
#pragma unroll
            for (int nt = 0; nt < 4; nt++) {
                uint32_t b0 = k_s[nt * 8 + g][s * 8 + tig];
                uint32_t b1 = k_s[nt * 8 + g][s * 8 + tig + 4];
                MMA_BF16(sc[nt], qf[s], b0, b1);
            }
        }
#pragma unroll
        for (int nt = 0; nt < 4; nt++) {
            sc[nt][0] *= 0.1f; sc[nt][1] *= 0.1f; sc[nt][2] *= 0.1f; sc[nt][3] *= 0.1f;
        }

        if (jt + TJ > q0) {
#pragma unroll
            for (int nt = 0; nt < 4; nt++) {
                int jb = jt + nt * 8 + 2 * tig;
                if (jb > r0)     sc[nt][0] = -INFINITY;
                if (jb + 1 > r0) sc[nt][1] = -INFINITY;
                if (jb > r1)     sc[nt][2] = -INFINITY;
                if (jb + 1 > r1) sc[nt][3] = -INFINITY;
            }
        }

        float rm0 = -INFINITY, rm1 = -INFINITY;
#pragma unroll
        for (int nt = 0; nt < 4; nt++) {
            rm0 = fmaxf(rm0, fmaxf(sc[nt][0], sc[nt][1]));
            rm1 = fmaxf(rm1, fmaxf(sc[nt][2], sc[nt][3]));
        }
        rm0 = fmaxf(rm0, __shfl_xor_sync(0xffffffffu, rm0, 1));
        rm0 = fmaxf(rm0, __shfl_xor_sync(0xffffffffu, rm0, 2));
        rm1 = fmaxf(rm1, __shfl_xor_sync(0xffffffffu, rm1, 1));
        rm1 = fmaxf(rm1, __shfl_xor_sync(0xffffffffu, rm1, 2));
        float mn0 = fmaxf(m0, rm0), mn1 = fmaxf(m1, rm1);
        float s0 = __expf(m0 - mn0), s1 = __expf(m1 - mn1);

        float rs0 = 0.f, rs1 = 0.f;
#pragma unroll
        for (int nt = 0; nt < 4; nt++) {
            float p0 = __expf(sc[nt][0] - mn0);
            float p1 = __expf(sc[nt][1] - mn0);
            float p2 = __expf(sc[nt][2] - mn1);
            float p3 = __expf(sc[nt][3] - mn1);
            rs0 += p0 + p1;
            rs1 += p2 + p3;
            p_s[w][g][nt * 4 + tig]     = packbf(p0, p1);
            p_s[w][g + 8][nt * 4 + tig] = packbf(p2, p3);
        }
        rs0 += __shfl_xor_sync(0xffffffffu, rs0, 1);
        rs0 += __shfl_xor_sync(0xffffffffu, rs0, 2);
        rs1 += __shfl_xor_sync(0xffffffffu, rs1, 1);
        rs1 += __shfl_xor_sync(0xffffffffu, rs1, 2);
        l0 = l0 * s0 + rs0;
        l1 = l1 * s1 + rs1;
        m0 = mn0; m1 = mn1;

#pragma unroll
        for (int nt = 0; nt < 13; nt++) {
            of[nt][0] *= s0; of[nt][1] *= s0;
            of[nt][2] *= s1; of[nt][3] *= s1;
        }
        __syncwarp();

#pragma unroll
        for (int ks = 0; ks < 16; ks += 8) {
            uint32_t pa[4];
            pa[0] = p_s[w][g][ks + tig];
            pa[1] = p_s[w][g + 8][ks + tig];
            pa[2] = p_s[w][g][ks + tig + 4];
            pa[3] = p_s[w][g + 8][ks + tig + 4];
#pragma unroll
            for (int nt = 0; nt < 13; nt++) {
                uint32_t b0 = v_s[ks + tig][nt * 8 + g];
                uint32_t b1 = v_s[ks + tig + 4][nt * 8 + g];
                MMA_BF16(of[nt], pa, b0, b1);
            }
        }
        __syncthreads();
    }

    size_t pb0 = (size_t)(z * NCH + c) * SQ + r0;
    size_t pb1 = (size_t)(z * NCH + c) * SQ + r1;
#pragma unroll
    for (int nt = 0; nt < 13; nt++) {
        int d = nt * 8 + 2 * tig;
        if (d < HDIM) {
            *(float2*)&part_o[pb0 * HDIM + d] = make_float2(of[nt][0], of[nt][1]);
            *(float2*)&part_o[pb1 * HDIM + d] = make_float2(of[nt][2], of[nt][3]);
        }
    }
    if (tig == 0) {
        part_ml[pb0 * 2] = m0; part_ml[pb0 * 2 + 1] = l0;
        part_ml[pb1 * 2] = m1; part_ml[pb1 * 2 + 1] = l1;
    }
}

__global__ void attn_combine(const float* __restrict__ part_o,
                             const float* __restrict__ part_ml,
                             uint32_t* __restrict__ ob) {
    int qi = blockIdx.x, e = blockIdx.y;
    int t = threadIdx.x, h = threadIdx.y;
    int z = e * 3 + h;
    int nch = qi / JCH + 1;
    float M = -INFINITY;
    for (int cc = 0; cc < nch; cc++)
        M = fmaxf(M, part_ml[((size_t)(z * NCH + cc) * SQ + qi) * 2]);
    float L = 0.f, a0 = 0.f, a1 = 0.f;
    for (int cc = 0; cc < nch; cc++) {
        size_t pb = (size_t)(z * NCH + cc) * SQ + qi;
        float w = __expf(part_ml[pb * 2] - M);
        L += part_ml[pb * 2 + 1] * w;
        if (t < 50) {
            float2 v = *(const float2*)&part_o[pb * HDIM + 2 * t];
            a0 += w * v.x; a1 += w * v.y;
        }
    }
    if (t < 50) {
        float inv = 1.f / L;
        ob[((size_t)e * SQ + qi) * 150 + h * 50 + t] = packbf(a0 * inv, a1 * inv);
    }
}

// ---------------- fused residual + LayerNorm ----------------
__global__ void ln_kernel(float* __restrict__ x, const float* __restrict__ delta,
                          const float* __restrict__ g, const float* __restrict__ b,
                          uint32_t* __restrict__ xb) {
    __shared__ float rs[8];
    int z = blockIdx.z;
    x += (size_t)z * SQ * EMB; delta += (size_t)z * SQ * EMB;
    g += z * EMB; b += z * EMB; xb += (size_t)z * SQ * 150;
    int r = blockIdx.x, t = threadIdx.x;
    int lane = t & 31, wid = t >> 5;
    float v[2][2];
    float s1 = 0.f, s2 = 0.f;
    {
        float2 a = *(const float2*)&x[(size_t)r * EMB + 2 * t];
        float2 d = *(const float2*)&delta[(size_t)r * EMB + 2 * t];
        v[0][0] = a.x + d.x; v[0][1] = a.y + d.y;
        s1 += v[0][0] + v[0][1];
        s2 += v[0][0] * v[0][0] + v[0][1] * v[0][1];
    }
    if (t < 22) {
        int p = t + 128;
        float2 a = *(const float2*)&x[(size_t)r * EMB + 2 * p];
        float2 d = *(const float2*)&delta[(size_t)r * EMB + 2 * p];
        v[1][0] = a.x + d.x; v[1][1] = a.y + d.y;
        s1 += v[1][0] + v[1][1];
        s2 += v[1][0] * v[1][0] + v[1][1] * v[1][1];
    }
#pragma unroll
    for (int off = 16; off > 0; off >>= 1) {
        s1 += __shfl_xor_sync(0xffffffffu, s1, off);
        s2 += __shfl_xor_sync(0xffffffffu, s2, off);
    }
    if (lane == 0) { rs[wid * 2] = s1; rs[wid * 2 + 1] = s2; }
    __syncthreads();
    float S1 = rs[0] + rs[2] + rs[4] + rs[6];
    float S2 = rs[1] + rs[3] + rs[5] + rs[7];
    float mu = S1 / (float)EMB;
    float var = S2 / (float)EMB - mu * mu;
    float rstd = rsqrtf(var + 1e-5f);
    {
        int c = 2 * t;
        float n0 = (v[0][0] - mu) * rstd * g[c] + b[c];
        float n1 = (v[0][1] - mu) * rstd * g[c + 1] + b[c + 1];
        *(float2*)&x[(size_t)r * EMB + c] = make_float2(n0, n1);
        xb[(size_t)r * 150 + t] = packbf(n0, n1);
    }
    if (t < 22) {
        int c = 2 * (t + 128);
        float n0 = (v[1][0] - mu) * rstd * g[c] + b[c];
        float n1 = (v[1][1] - mu) * rstd * g[c + 1] + b[c + 1];
        *(float2*)&x[(size_t)r * EMB + c] = make_float2(n0, n1);
        xb[(size_t)r * 150 + t + 128] = packbf(n0, n1);
    }
}

// ---------------- row softmax over A: fp32 in, bf16 out ----------------
__global__ void softmax_rows(const float* __restrict__ A, __nv_bfloat16* __restrict__ Ab) {
    __shared__ float row[SQ];
    __shared__ float red[256];
    int r = blockIdx.x, t = threadIdx.x;
    float mx = -INFINITY;
    for (int j = t; j < SQ; j += 256) { float v = A[(size_t)r * SQ + j]; row[j] = v; mx = fmaxf(mx, v); }
    red[t] = mx; __syncthreads();
    for (int off = 128; off > 0; off >>= 1) { if (t < off) red[t] = fmaxf(red[t], red[t + off]); __syncthreads(); }
    mx = red[0];
    __syncthreads();
    float s = 0.f;
    for (int j = t; j < SQ; j += 256) { float e = __expf(row[j] - mx); row[j] = e; s += e; }
    red[t] = s; __syncthreads();
    for (int off = 128; off > 0; off >>= 1) { if (t < off) red[t] += red[t + off]; __syncthreads(); }
    float inv = 1.f / red[0];
    uint32_t* out = (uint32_t*)(Ab + (size_t)r * SQ);
    for (int j = 2 * t; j < SQ; j += 512)
        out[j >> 1] = packbf(row[j] * inv, row[j + 1] * inv);
}

// ---------------- coalesced colsum of elementwise max (two phase) ----------------
// phase 1: grid (32 chunks, 2 pairs); block 300 threads (one per column)
__global__ void colsum_partial(const float* __restrict__ H, const float* __restrict__ P,
                               const float* __restrict__ G, const float* __restrict__ Q,
                               float* __restrict__ part) {
    int chunk = blockIdx.x, pair = blockIdx.y;
    int c = threadIdx.x;
    const float* X = pair ? G : H;
    const float* Y = pair ? Q : P;
    int r0 = chunk * 128;
    float s = 0.f;
    for (int r = r0; r < r0 + 128; r++)
        s += fmaxf(X[(size_t)r * EMB + c], Y[(size_t)r * EMB + c]);
    part[((size_t)pair * 32 + chunk) * EMB + c] = s;
}
// phase 2: 1 block, 600 threads
__global__ void colsum_final(const float* __restrict__ part, float* __restrict__ suv) {
    int j = threadIdx.x;            // 0..599
    int pair = j / EMB, c = j - pair * EMB;
    float s = 0.f;
#pragma unroll
    for (int ch = 0; ch < 32; ch++)
        s += part[((size_t)pair * 32 + ch) * EMB + c];
    suv[j] = s;
}

// ---------------- tiny FC layers ----------------
__global__ void fc1_kernel(const float* __restrict__ inp, const float* __restrict__ w,
                           const float* __restrict__ b, float* __restrict__ out) {
    __shared__ float red[128];
    int i = blockIdx.x, t = threadIdx.x;
    float s = 0.f;
    for (int j = t; j < 2 * EMB; j += 128) s += inp[j] * w[(size_t)i * 2 * EMB + j];
    red[t] = s; __syncthreads();
    for (int off = 64; off > 0; off >>= 1) { if (t < off) red[t] += red[t + off]; __syncthreads(); }
    if (t == 0) out[i] = fmaxf(red[0] + b[i], 0.f);
}

__global__ void fc2_kernel(const float* __restrict__ inp, const float* __restrict__ w,
                           const float* __restrict__ b, float* __restrict__ out) {
    __shared__ float red[256];
    int t = threadIdx.x;
    float s = 0.f;
    for (int j = t; j < EMB; j += 256) s += inp[j] * w[j];
    red[t] = s; __syncthreads();
    for (int off = 128; off > 0; off >>= 1) { if (t < off) red[t] += red[t + off]; __syncthreads(); }
    if (t == 0) out[0] = red[0] + b[0];
}

// ---------------- host orchestration ----------------
extern "C" void kernel_launch(void* const* d_in, const int* in_sizes, int n_in,
                              void* d_out, int out_size) {
    const float* solv = (const float*)d_in[0];
    const float* solu = (const float*)d_in[1];
    const float* ipw  = (const float*)d_in[2];
    const float* ipb  = (const float*)d_in[3];
    const float* ow   = (const float*)d_in[4];
    const float* ob_b = (const float*)d_in[5];
    const float* g1   = (const float*)d_in[6];
    const float* b1   = (const float*)d_in[7];
    const float* w1   = (const float*)d_in[8];
    const float* bb1  = (const float*)d_in[9];
    const float* w2   = (const float*)d_in[10];
    const float* bb2  = (const float*)d_in[11];
    const float* g2   = (const float*)d_in[12];
    const float* b2   = (const float*)d_in[13];
    const float* fc1w = (const float*)d_in[14];
    const float* fc1b = (const float*)d_in[15];
    const float* fc2w = (const float*)d_in[16];
    const float* fc2b = (const float*)d_in[17];

    float *x, *t1, *A, *P, *Q, *Pp, *Qp, *po, *pml, *cpart, *suv, *fc1o;
    uint32_t *xb, *xbT, *wp, *qkvb, *ob, *ffb;
    __nv_bfloat16* Ab;
    cudaGetSymbolAddress((void**)&x,    g_x);
    cudaGetSymbolAddress((void**)&xb,   g_xb);
    cudaGetSymbolAddress((void**)&xbT,  g_xbT);
    cudaGetSymbolAddress((void**)&wp,   g_wpack);
    cudaGetSymbolAddress((void**)&qkvb, g_qkvb);
    cudaGetSymbolAddress((void**)&ob,   g_ob);
    cudaGetSymbolAddress((void**)&t1,   g_t1);
    cudaGetSymbolAddress((void**)&ffb,  g_ffb);
    cudaGetSymbolAddress((void**)&A,    g_A);
    cudaGetSymbolAddress((void**)&Ab,   g_Ab);
    cudaGetSymbolAddress((void**)&P,    g_P);
    cudaGetSymbolAddress((void**)&Q,    g_Q);
    cudaGetSymbolAddress((void**)&Pp,   g_Pp);
    cudaGetSymbolAddress((void**)&Qp,   g_Qp);
    cudaGetSymbolAddress((void**)&po,   g_part_o);
    cudaGetSymbolAddress((void**)&pml,  g_part_ml);
    cudaGetSymbolAddress((void**)&cpart, g_colpart);
    cudaGetSymbolAddress((void**)&suv,  g_suv);
    cudaGetSymbolAddress((void**)&fc1o, g_fc1o);

    const size_t SE = (size_t)SQ * EMB;
    uint32_t* ipwb = wp;
    uint32_t* owb  = wp + 270000;
    uint32_t* w1b  = wp + 360000;
    uint32_t* w2b  = wp + 420000;

    pack4<<<(480000 + 255) / 256, 256>>>(ipw, ow, w1, w2, wp);

    add_pe_kernel<<<dim3((SQ * 150 + 255) / 256, 1, 2), 256>>>(solv, solu, x, xb);

    // qkv = x @ ipw^T + ipb  -> bf16 packed
    mma2<0, 0, 0, 1><<<dim3(15, 32, 2), 256>>>(
        (const __nv_bfloat16*)xb, (const __nv_bfloat16*)ipwb, ipb, (float*)qkvb,
        SQ, 3 * EMB, EMB, EMB, EMB,
        (size_t)SQ * EMB, (size_t)3 * EMB * EMB, 3 * EMB, (size_t)SQ * 450, 0);

    attn_mma_kernel<<<dim3(SQ / QB, NCH, 6), 128>>>(qkvb, po, pml);
    attn_combine<<<dim3(SQ, 2), dim3(64, 3)>>>(po, pml, ob);

    // proj = o @ ow^T + ob  -> fp32 (feeds LN)
    mma2<0, 0, 0, 0><<<dim3(5, 32, 2), 256>>>(
        (const __nv_bfloat16*)ob, (const __nv_bfloat16*)owb, ob_b, t1,
        SQ, EMB, EMB, EMB, EMB,
        (size_t)SQ * EMB, (size_t)EMB * EMB, EMB, SE, 0);
    ln_kernel<<<dim3(SQ, 1, 2), 128>>>(x, t1, g1, b1, xb);

    // ff1 = relu(x @ w1^T + bb1) -> bf16 packed
    mma2<0, 1, 0, 1><<<dim3(4, 32, 2), 256>>>(
        (const __nv_bfloat16*)xb, (const __nv_bfloat16*)w1b, bb1, (float*)ffb,
        SQ, NHID, EMB, EMB, EMB,
        (size_t)SQ * EMB, (size_t)NHID * EMB, NHID, (size_t)SQ * 100, 0);
    // ff2 = ff1 @ w2^T + bb2 -> fp32 (feeds LN)
    mma2<0, 0, 0, 0><<<dim3(5, 32, 2), 256>>>(
        (const __nv_bfloat16*)ffb, (const __nv_bfloat16*)w2b, bb2, t1,
        SQ, EMB, NHID, NHID, NHID,
        (size_t)SQ * NHID, (size_t)EMB * NHID, EMB, SE, 0);
    ln_kernel<<<dim3(SQ, 1, 2), 128>>>(x, t1, g2, b2, xb);

    float* H = x;
    float* G = x + SE;
    uint32_t* Hb = xb;
    uint32_t* Gb = xb + (size_t)SQ * 150;

    transpose_pack<<<dim3(SQ / 64, 5, 2), 256>>>(x, xbT);
    const __nv_bfloat16* HbT = (const __nv_bfloat16*)xbT;
    const __nv_bfloat16* GbT = (const __nv_bfloat16*)xbT + (size_t)EMB * SQ;

    // A = H @ G^T
    mma2<0, 0, 0, 0><<<dim3(64, 32, 1), 256>>>(
        (const __nv_bfloat16*)Hb, (const __nv_bfloat16*)Gb, (const float*)nullptr, A,
        SQ, SQ, EMB, EMB, EMB, 0, 0, 0, 0, 0);
    softmax_rows<<<SQ, 256>>>(A, Ab);

    // P and Q split-K chunks fused into one launch (z<4 -> P, z>=4 -> Q)
    mma2_pq<<<dim3(5, 32, 2 * NCH), 256>>>(Ab, GbT, HbT, Pp, Qp);
    reduce_pq<<<dim3((SQ * EMB / 4 + 255) / 256, 2), 256>>>(Pp, Qp, P, Q);

    colsum_partial<<<dim3(32, 2), 300>>>(H, P, G, Q, cpart);
    colsum_final<<<1, 600>>>(cpart, suv);

    fc1_kernel<<<EMB, 128>>>(suv, fc1w, fc1b, fc1o);
    fc2_kernel<<<1, 256>>>(fc1o, fc2w, fc2b, (float*)d_out);
}

// round 11
// speedup vs baseline: 1.2937x; 1.0337x over previous
#include <cuda_runtime.h>
#include <cuda_bf16.h>
#include <math.h>
#include <stdint.h>

#define SQ   4096
#define EMB  300
#define NH   3
#define HDIM 100
#define NHID 200
#define QB   64
#define TJ   32
#define JCH  1024
#define NCH  4
#define KSPL 1024
#define ASTR 136   // As smem stride (words)
#define BSTR 72    // Bs smem stride (words)

// ---------------- scratch (static device globals; no allocation) ----------------
__device__ float g_x[2 * SQ * EMB];            // fp32 encoder state
__device__ uint32_t g_xb[2 * SQ * 150];        // bf16x2 packed x
__device__ uint32_t g_xbT[2 * EMB * (SQ / 2)]; // bf16x2 transposed x (k-major)
__device__ uint32_t g_wpack[480000];           // packed weights: ipw|ow|w1|w2
__device__ uint32_t g_qkvb[2 * SQ * 450];
__device__ uint32_t g_ob[2 * SQ * 150];
__device__ float g_t1[2 * SQ * EMB];
__device__ uint32_t g_ffb[2 * SQ * 100];
__device__ float g_A[SQ * SQ];
__device__ __nv_bfloat16 g_Ab[SQ * SQ];
__device__ float g_P[SQ * EMB];
__device__ float g_Q[SQ * EMB];
__device__ float g_Pp[NCH * SQ * EMB];
__device__ float g_Qp[NCH * SQ * EMB];
__device__ float g_part_o[6 * NCH * SQ * HDIM];
__device__ float g_part_ml[6 * NCH * SQ * 2];
__device__ float g_colpart[2 * 32 * EMB];
__device__ float g_suv[2 * EMB];
__device__ float g_fc1o[EMB];

// ---------------- bf16 helpers ----------------
__device__ __forceinline__ uint32_t packbf(float lo, float hi) {
    uint32_t r;
    asm("cvt.rn.bf16x2.f32 %0, %1, %2;" : "=r"(r) : "f"(hi), "f"(lo));
    return r;
}

#define MMA_BF16(C, A, B0, B1)                                                  \
    asm volatile(                                                               \
        "mma.sync.aligned.m16n8k16.row.col.f32.bf16.bf16.f32 "                  \
        "{%0,%1,%2,%3},{%4,%5,%6,%7},{%8,%9},{%0,%1,%2,%3};"                    \
        : "+f"((C)[0]), "+f"((C)[1]), "+f"((C)[2]), "+f"((C)[3])                \
        : "r"((A)[0]), "r"((A)[1]), "r"((A)[2]), "r"((A)[3]), "r"(B0), "r"(B1))

// ---------------- packing kernels ----------------
__global__ void pack4(const float* __restrict__ ipw, const float* __restrict__ ow,
                      const float* __restrict__ w1, const float* __restrict__ w2,
                      uint32_t* __restrict__ dst) {
    int i = blockIdx.x * 256 + threadIdx.x;
    if (i >= 480000) return;
    const float* src;
    int off;
    if (i < 270000)      { src = ipw; off = i; }
    else if (i < 360000) { src = ow;  off = i - 270000; }
    else if (i < 420000) { src = w1;  off = i - 360000; }
    else                 { src = w2;  off = i - 420000; }
    float2 v = ((const float2*)src)[off];
    dst[i] = packbf(v.x, v.y);
}

__global__ void transpose_pack(const float* __restrict__ x, uint32_t* __restrict__ xT) {
    __shared__ float tile[64][65];
    int z = blockIdx.z;
    int s0 = blockIdx.x * 64, c0 = blockIdx.y * 64;
    int t = threadIdx.x;
#pragma unroll
    for (int i = 0; i < 16; i++) {
        int idx = t + i * 256;
        int ls = idx >> 6, lc = idx & 63;
        int c = c0 + lc;
        tile[ls][lc] = (c < EMB) ? x[(size_t)z * SQ * EMB + (size_t)(s0 + ls) * EMB + c] : 0.f;
    }
    __syncthreads();
#pragma unroll
    for (int i = 0; i < 8; i++) {
        int idx = t + i * 256;
        int lc = idx >> 5, lsp = idx & 31;
        int c = c0 + lc;
        if (c < EMB)
            xT[(size_t)z * EMB * (SQ / 2) + (size_t)c * (SQ / 2) + (s0 >> 1) + lsp] =
                packbf(tile[2 * lsp][lc], tile[2 * lsp + 1][lc]);
    }
}

// ---------------- positional encoding + add ----------------
__global__ void add_pe_kernel(const float* __restrict__ solv, const float* __restrict__ solu,
                              float* __restrict__ x, uint32_t* __restrict__ xb) {
    int p = blockIdx.x * blockDim.x + threadIdx.x;
    if (p >= SQ * 150) return;
    int z = blockIdx.z;
    const float* src = z ? solu : solv;
    int s = p / 150, pc = p - s * 150, c = 2 * pc;
    float dv = __expf(-(float)c * (logf(10000.0f) / (float)EMB));
    float arg = (float)s * dv;
    float pe0 = sinf(arg), pe1 = cosf(arg);
    float2 a = *(const float2*)&src[(size_t)s * EMB + c];
    float v0 = a.x + pe0, v1 = a.y + pe1;
    *(float2*)&x[(size_t)z * SQ * EMB + (size_t)s * EMB + c] = make_float2(v0, v1);
    xb[(size_t)z * SQ * 150 + p] = packbf(v0, v1);
}

// ---------------- all-bf16 tensor-core GEMM (128x64 tile, KCF=32, double-buffered) ----
template<int TA, int RELU, int SPLITK, int BF16OUT>
__global__ __launch_bounds__(256, 2)
void mma2(const __nv_bfloat16* __restrict__ A, const __nv_bfloat16* __restrict__ B,
          const float* __restrict__ bias, float* __restrict__ C,
          int M, int N, int K, int lda, int ldb,
          size_t sA, size_t sB, size_t sBias, size_t sC, int kc) {
    int z = blockIdx.z;
    int k_begin = 0, k_end = K;
    if (SPLITK) {
        k_begin = z * kc;
        k_end = min(K, k_begin + kc);
        C += (size_t)z * sC;
    } else {
        A += (size_t)z * sA; B += (size_t)z * sB; C += (size_t)z * sC;
        if (bias) bias += (size_t)z * sBias;
    }
    uint32_t* C32 = (uint32_t*)C;

    __shared__ uint32_t As[2][16][ASTR];
    __shared__ uint32_t Bs[2][16][BSTR];

    int t = threadIdx.x;
    int warp = t >> 5, lane = t & 31;
    int g = lane >> 2, tig = lane & 3;
    int wm = warp & 3, wn = warp >> 2;
    int row0 = blockIdx.y * 128, col0 = blockIdx.x * 64;
    int wr0 = wm * 32, wc0 = wn * 32;

    float acc[2][4][4];
#pragma unroll
    for (int i = 0; i < 2; i++)
#pragma unroll
        for (int j = 0; j < 4; j++)
#pragma unroll
            for (int h = 0; h < 4; h++) acc[i][j][h] = 0.f;

    uint32_t ra[8], rb[4];

    auto loadA = [&](int kt) {
        if (!TA) {
            int m = t >> 1, kq = (t & 1) * 16;
            const uint32_t* Ap = (const uint32_t*)(A + (size_t)(row0 + m) * lda + kt + kq);
            if (kt + kq + 15 < k_end) {
#pragma unroll
                for (int u = 0; u < 8; u++) ra[u] = Ap[u];
            } else {
                const unsigned short* A16 = (const unsigned short*)(A + (size_t)(row0 + m) * lda);
#pragma unroll
                for (int u = 0; u < 8; u++) {
                    int gk = kt + kq + 2 * u;
                    uint32_t lo = (gk < k_end) ? A16[gk] : 0;
                    uint32_t hi = (gk + 1 < k_end) ? A16[gk + 1] : 0;
                    ra[u] = lo | (hi << 16);
                }
            }
        } else {
            int kp = t >> 4, mq = (t & 15) * 8;
            int gk0 = kt + 2 * kp;
            bool ok0 = gk0 < k_end, ok1 = gk0 + 1 < k_end;
            const uint32_t* r0p = (const uint32_t*)(A + (size_t)gk0 * lda + row0 + mq);
            const uint32_t* r1p = (const uint32_t*)(A + (size_t)(gk0 + 1) * lda + row0 + mq);
            if (ok1) {
#pragma unroll
                for (int u = 0; u < 4; u++) {
                    uint32_t w0 = r0p[u], w1 = r1p[u];
                    ra[2 * u]     = __byte_perm(w0, w1, 0x5410);
                    ra[2 * u + 1] = __byte_perm(w0, w1, 0x7632);
                }
            } else {
#pragma unroll
                for (int u = 0; u < 4; u++) {
                    uint32_t w0 = ok0 ? r0p[u] : 0;
                    ra[2 * u]     = __byte_perm(w0, 0u, 0x5410);
                    ra[2 * u + 1] = __byte_perm(w0, 0u, 0x7632);
                }
            }
        }
    };
    auto loadB = [&](int kt) {
        int n = t >> 2, kq = (t & 3) * 8;
        int gn = col0 + n;
        bool okn = gn < N;
        const uint32_t* Bp = (const uint32_t*)(B + (size_t)gn * ldb + kt + kq);
        if (okn && kt + kq + 7 < k_end) {
#pragma unroll
            for (int u = 0; u < 4; u++) rb[u] = Bp[u];
        } else {
            const unsigned short* B16 = (const unsigned short*)(B + (size_t)gn * ldb);
#pragma unroll
            for (int u = 0; u < 4; u++) {
                int gk = kt + kq + 2 * u;
                uint32_t lo = (okn && gk < k_end) ? B16[gk] : 0;
                uint32_t hi = (okn && gk + 1 < k_end) ? B16[gk + 1] : 0;
                rb[u] = lo | (hi << 16);
            }
        }
    };
    auto storeA = [&](int bf) {
        if (!TA) {
            int m = t >> 1, kp0 = (t & 1) * 8;
#pragma unroll
            for (int u = 0; u < 8; u++) As[bf][kp0 + u][m] = ra[u];
        } else {
            int kp = t >> 4, mq = (t & 15) * 8;
#pragma unroll
            for (int u = 0; u < 8; u++) As[bf][kp][mq + u] = ra[u];
        }
    };
    auto storeB = [&](int bf) {
        int n = t >> 2, kp0 = (t & 3) * 4;
#pragma unroll
        for (int u = 0; u < 4; u++) Bs[bf][kp0 + u][n] = rb[u];
    };

    int nk = (k_end - k_begin + 31) >> 5;
    loadA(k_begin); loadB(k_begin);
    storeA(0); storeB(0);
    __syncthreads();

    int buf = 0;
    for (int it = 0; it < nk; it++) {
        if (it + 1 < nk) { loadA(k_begin + (it + 1) * 32); loadB(k_begin + (it + 1) * 32); }
#pragma unroll
        for (int ks = 0; ks < 16; ks += 8) {
            uint32_t a[2][4], b[4][2];
#pragma unroll
            for (int i = 0; i < 2; i++) {
                int mb = wr0 + i * 16;
                a[i][0] = As[buf][ks + tig][mb + g];
                a[i][1] = As[buf][ks + tig][mb + 8 + g];
                a[i][2] = As[buf][ks + tig + 4][mb + g];
                a[i][3] = As[buf][ks + tig + 4][mb + 8 + g];
            }
#pragma unroll
            for (int j = 0; j < 4; j++) {
                int nb = wc0 + j * 8;
                b[j][0] = Bs[buf][ks + tig][nb + g];
                b[j][1] = Bs[buf][ks + tig + 4][nb + g];
            }
#pragma unroll
            for (int i = 0; i < 2; i++)
#pragma unroll
                for (int j = 0; j < 4; j++)
                    MMA_BF16(acc[i][j], a[i], b[j][0], b[j][1]);
        }
        if (it + 1 < nk) {
            storeA(1 - buf); storeB(1 - buf);
            __syncthreads();
            buf ^= 1;
        }
    }

#pragma unroll
    for (int i = 0; i < 2; i++) {
        int r0 = row0 + wr0 + i * 16 + g;
#pragma unroll
        for (int j = 0; j < 4; j++) {
            int cc = col0 + wc0 + j * 8 + tig * 2;
#pragma unroll
            for (int h = 0; h < 2; h++) {
                int gr = r0 + h * 8;
                float v0 = acc[i][j][h * 2], v1 = acc[i][j][h * 2 + 1];
                if (!SPLITK && bias) {
                    if (cc < N) v0 += bias[cc];
                    if (cc + 1 < N) v1 += bias[cc + 1];
                }
                if (RELU) { v0 = fmaxf(v0, 0.f); v1 = fmaxf(v1, 0.f); }
                if (BF16OUT) {
                    if (cc < N)
                        C32[(size_t)gr * (N >> 1) + (cc >> 1)] = packbf(v0, v1);
                } else if (cc + 1 < N) {
                    *(float2*)&C[(size_t)gr * N + cc] = make_float2(v0, v1);
                } else if (cc < N) {
                    C[(size_t)gr * N + cc] = v0;
                }
            }
        }
    }
}

// ---------------- fused P+Q split-K GEMM (runtime transpose flag) ----------------
__global__ __launch_bounds__(256, 2)
void mma2_pq(const __nv_bfloat16* __restrict__ Ain, const __nv_bfloat16* __restrict__ BP,
             const __nv_bfloat16* __restrict__ BQ, float* __restrict__ CP,
             float* __restrict__ CQ) {
    int z = blockIdx.z;
    int ta = (z >= NCH) ? 1 : 0;
    int zz = ta ? z - NCH : z;
    int k_begin = zz * KSPL;
    const __nv_bfloat16* B = ta ? BQ : BP;
    float* C = (ta ? CQ : CP) + (size_t)zz * SQ * EMB;
    const int lda = SQ, ldb = SQ, N = EMB;

    __shared__ uint32_t As[2][16][ASTR];
    __shared__ uint32_t Bs[2][16][BSTR];

    int t = threadIdx.x;
    int warp = t >> 5, lane = t & 31;
    int g = lane >> 2, tig = lane & 3;
    int wm = warp & 3, wn = warp >> 2;
    int row0 = blockIdx.y * 128, col0 = blockIdx.x * 64;
    int wr0 = wm * 32, wc0 = wn * 32;

    float acc[2][4][4];
#pragma unroll
    for (int i = 0; i < 2; i++)
#pragma unroll
        for (int j = 0; j < 4; j++)
#pragma unroll
            for (int h = 0; h < 4; h++) acc[i][j][h] = 0.f;

    uint32_t ra[8], rb[4];

    auto loadA = [&](int kt) {
        if (!ta) {
            int m = t >> 1, kq = (t & 1) * 16;
            const uint32_t* Ap = (const uint32_t*)(Ain + (size_t)(row0 + m) * lda + kt + kq);
#pragma unroll
            for (int u = 0; u < 8; u++) ra[u] = Ap[u];
        } else {
            int kp = t >> 4, mq = (t & 15) * 8;
            int gk0 = kt + 2 * kp;
            const uint32_t* r0p = (const uint32_t*)(Ain + (size_t)gk0 * lda + row0 + mq);
            const uint32_t* r1p = (const uint32_t*)(Ain + (size_t)(gk0 + 1) * lda + row0 + mq);
#pragma unroll
            for (int u = 0; u < 4; u++) {
                uint32_t w0 = r0p[u], w1 = r1p[u];
                ra[2 * u]     = __byte_perm(w0, w1, 0x5410);
                ra[2 * u + 1] = __byte_perm(w0, w1, 0x7632);
            }
        }
    };
    auto loadB = [&](int kt) {
        int n = t >> 2, kq = (t & 3) * 8;
        int gn = col0 + n;
        if (gn < N) {
            const uint32_t* Bp = (const uint32_t*)(B + (size_t)gn * ldb + kt + kq);
#pragma unroll
            for (int u = 0; u < 4; u++) rb[u] = Bp[u];
        } else {
#pragma unroll
            for (int u = 0; u < 4; u++) rb[u] = 0u;
        }
    };
    auto storeA = [&](int bf) {
        if (!ta) {
            int m = t >> 1, kp0 = (t & 1) * 8;
#pragma unroll
            for (int u = 0; u < 8; u++) As[bf][kp0 + u][m] = ra[u];
        } else {
            int kp = t >> 4, mq = (t & 15) * 8;
#pragma unroll
            for (int u = 0; u < 8; u++) As[bf][kp][mq + u] = ra[u];
        }
    };
    auto storeB = [&](int bf) {
        int n = t >> 2, kp0 = (t & 3) * 4;
#pragma unroll
        for (int u = 0; u < 4; u++) Bs[bf][kp0 + u][n] = rb[u];
    };

    const int nk = KSPL >> 5;
    loadA(k_begin); loadB(k_begin);
    storeA(0); storeB(0);
    __syncthreads();

    int buf = 0;
    for (int it = 0; it < nk; it++) {
        if (it + 1 < nk) { loadA(k_begin + (it + 1) * 32); loadB(k_begin + (it + 1) * 32); }
#pragma unroll
        for (int ks = 0; ks < 16; ks += 8) {
            uint32_t a[2][4], b[4][2];
#pragma unroll
            for (int i = 0; i < 2; i++) {
                int mb = wr0 + i * 16;
                a[i][0] = As[buf][ks + tig][mb + g];
                a[i][1] = As[buf][ks + tig][mb + 8 + g];
                a[i][2] = As[buf][ks + tig + 4][mb + g];
                a[i][3] = As[buf][ks + tig + 4][mb + 8 + g];
            }
#pragma unroll
            for (int j = 0; j < 4; j++) {
                int nb = wc0 + j * 8;
                b[j][0] = Bs[buf][ks + tig][nb + g];
                b[j][1] = Bs[buf][ks + tig + 4][nb + g];
            }
#pragma unroll
            for (int i = 0; i < 2; i++)
#pragma unroll
                for (int j = 0; j < 4; j++)
                    MMA_BF16(acc[i][j], a[i], b[j][0], b[j][1]);
        }
        if (it + 1 < nk) {
            storeA(1 - buf); storeB(1 - buf);
            __syncthreads();
            buf ^= 1;
        }
    }

#pragma unroll
    for (int i = 0; i < 2; i++) {
        int r0 = row0 + wr0 + i * 16 + g;
#pragma unroll
        for (int j = 0; j < 4; j++) {
            int cc = col0 + wc0 + j * 8 + tig * 2;
#pragma unroll
            for (int h = 0; h < 2; h++) {
                int gr = r0 + h * 8;
                float v0 = acc[i][j][h * 2], v1 = acc[i][j][h * 2 + 1];
                if (cc + 1 < N) {
                    *(float2*)&C[(size_t)gr * N + cc] = make_float2(v0, v1);
                } else if (cc < N) {
                    C[(size_t)gr * N + cc] = v0;
                }
            }
        }
    }
}

// ---------------- split-K reduce for P and Q ----------------
__global__ void reduce_pq(const float* __restrict__ Pp, const float* __restrict__ Qp,
                          float* __restrict__ P, float* __restrict__ Q) {
    int idx = blockIdx.x * 256 + threadIdx.x;
    if (idx >= SQ * EMB / 4) return;
    const float* src = blockIdx.y ? Qp : Pp;
    float* dst = blockIdx.y ? Q : P;
    float4 r = make_float4(0.f, 0.f, 0.f, 0.f);
#pragma unroll
    for (int c = 0; c < NCH; c++) {
        float4 a = ((const float4*)(src + (size_t)c * SQ * EMB))[idx];
        r.x += a.x; r.y += a.y; r.z += a.z; r.w += a.w;
    }
    ((float4*)dst)[idx] = r;
}

// ---------------- bf16 tensor-core flash attention (Q in smem, 5 blocks/SM) --------
__global__ __launch_bounds__(128, 5)
void attn_mma_kernel(const uint32_t* __restrict__ qb_all,
                     float* __restrict__ part_o, float* __restrict__ part_ml) {
    __shared__ uint32_t k_s[TJ][60];
    __shared__ uint32_t v_s[16][108];
    __shared__ uint32_t p_s[4][16][20];
    __shared__ uint32_t q_s[4][16][58];   // Q fragments: [warp][row-in-warp][d-pair], stride 58 conflict-free

    int z = blockIdx.z, e = z / 3, h = z % 3;
    int qt = (int)gridDim.x - 1 - (int)blockIdx.x;
    int q0 = qt * QB;
    int c = blockIdx.y, c0 = c * JCH;
    if (c0 > q0 + QB - 1) return;

    const uint32_t* qb = qb_all + (size_t)e * SQ * 450;
    int t = threadIdx.x, w = t >> 5, lane = t & 31;
    int g = lane >> 2, tig = lane & 3;

    int r0 = q0 + w * 16 + g;
    int r1 = r0 + 8;

    // stage Q fragments into smem once (row g and g+8 of this warp)
    {
        const uint32_t* q0p = qb + (size_t)r0 * 450 + h * 50;
        const uint32_t* q1p = qb + (size_t)r1 * 450 + h * 50;
#pragma unroll
        for (int s = 0; s < 7; s++) {
            int dp0 = s * 8 + tig, dp1 = dp0 + 4;
            q_s[w][g][dp0]     = dp0 < 50 ? q0p[dp0] : 0u;
            q_s[w][g + 8][dp0] = dp0 < 50 ? q1p[dp0] : 0u;
            q_s[w][g][dp1]     = dp1 < 50 ? q0p[dp1] : 0u;
            q_s[w][g + 8][dp1] = dp1 < 50 ? q1p[dp1] : 0u;
        }
    }
    __syncwarp();

    float of[13][4];
#pragma unroll
    for (int nt = 0; nt < 13; nt++) { of[nt][0] = of[nt][1] = of[nt][2] = of[nt][3] = 0.f; }
    float m0 = -INFINITY, m1 = -INFINITY, l0 = 0.f, l1 = 0.f;

    int jend = min(c0 + JCH, q0 + QB);
    for (int jt = c0; jt < jend; jt += TJ) {
        for (int idx = t; idx < TJ * 56; idx += 128) {
            int row = idx / 56, dp = idx - row * 56;
            k_s[row][dp] = dp < 50 ? qb[(size_t)(jt + row) * 450 + 150 + h * 50 + dp] : 0u;
        }
        for (int idx = t; idx < 16 * 52; idx += 128) {
            int jp = idx / 52, dp = idx - jp * 52;
            uint32_t w0 = 0u, w1 = 0u;
            if (dp < 50) {
                const uint32_t* vb = qb + (size_t)(jt + 2 * jp) * 450 + 300 + h * 50 + dp;
                w0 = vb[0];
                w1 = vb[450];
            }
            v_s[jp][2 * dp]     = __byte_perm(w0, w1, 0x5410);
            v_s[jp][2 * dp + 1] = __byte_perm(w0, w1, 0x7632);
        }
        __syncthreads();

        float sc[4][4];
#pragma unroll
        for (int nt = 0; nt < 4; nt++) { sc[nt][0] = sc[nt][1] = sc[nt][2] = sc[nt][3] = 0.f; }
#pragma unroll
        for (int s = 0; s < 7; s++) {
            uint32_t qa[4];
            qa[0] = q_s[w][g][s * 8 + tig];
            qa[1] = q_s[w][g + 8][s * 8 + tig];
            qa[2] = q_s[w][g][s * 8 + tig + 4];
            qa[3] = q_s[w][g + 8][s * 8 + tig + 4];
#pragma unroll
            for (int nt = 0; nt < 4; nt++) {
                uint32_t b0 = k_s[nt * 8 + g][s * 8 + tig];
                uint32_t b1 = k_s[nt * 8 + g][s * 8 + tig + 4];
                MMA_BF16(sc[nt], qa, b0, b1);
            }
        }
#pragma unroll
        for (int nt = 0; nt < 4; nt++) {
            sc[nt][0] *= 0.1f; sc[nt][1] *= 0.1f; sc[nt][2] *= 0.1f; sc[nt][3] *= 0.1f;
        }

        if (jt + TJ > q0) {
#pragma unroll
            for (int nt = 0; nt < 4; nt++) {
                int jb = jt + nt * 8 + 2 * tig;
                if (jb > r0)     sc[nt][0] = -INFINITY;
                if (jb + 1 > r0) sc[nt][1] = -INFINITY;
                if (jb > r1)     sc[nt][2] = -INFINITY;
                if (jb + 1 > r1) sc[nt][3] = -INFINITY;
            }
        }

        float rm0 = -INFINITY, rm1 = -INFINITY;
#pragma unroll
        for (int nt = 0; nt < 4; nt++) {
            rm0 = fmaxf(rm0, fmaxf(sc[nt][0], sc[nt][1]));
            rm1 = fmaxf(rm1, fmaxf(sc[nt][2], sc[nt][3]));
        }
        rm0 = fmaxf(rm0, __shfl_xor_sync(0xffffffffu, rm0, 1));
        rm0 = fmaxf(rm0, __shfl_xor_sync(0xffffffffu, rm0, 2));
        rm1 = fmaxf(rm1, __shfl_xor_sync(0xffffffffu, rm1, 1));
        rm1 = fmaxf(rm1, __shfl_xor_sync(0xffffffffu, rm1, 2));
        float mn0 = fmaxf(m0, rm0), mn1 = fmaxf(m1, rm1);
        float s0 = __expf(m0 - mn0), s1 = __expf(m1 - mn1);

        float rs0 = 0.f, rs1 = 0.f;
#pragma unroll
        for (int nt = 0; nt < 4; nt++) {
            float p0 = __expf(sc[nt][0] - mn0);
            float p1 = __expf(sc[nt][1] - mn0);
            float p2 = __expf(sc[nt][2] - mn1);
            float p3 = __expf(sc[nt][3] - mn1);
            rs0 += p0 + p1;
            rs1 += p2 + p3;
            p_s[w][g][nt * 4 + tig]     = packbf(p0, p1);
            p_s[w][g + 8][nt * 4 + tig] = packbf(p2, p3);
        }
        rs0 += __shfl_xor_sync(0xffffffffu, rs0, 1);
        rs0 += __shfl_xor_sync(0xffffffffu, rs0, 2);
        rs1 += __shfl_xor_sync(0xffffffffu, rs1, 1);
        rs1 += __shfl_xor_sync(0xffffffffu, rs1, 2);
        l0 = l0 * s0 + rs0;
        l1 = l1 * s1 + rs1;
        m0 = mn0; m1 = mn1;

#pragma unroll
        for (int nt = 0; nt < 13; nt++) {
            of[nt][0] *= s0; of[nt][1] *= s0;
            of[nt][2] *= s1; of[nt][3] *= s1;
        }
        __syncwarp();

#pragma unroll
        for (int ks = 0; ks < 16; ks += 8) {
            uint32_t pa[4];
            pa[0] = p_s[w][g][ks + tig];
            pa[1] = p_s[w][g + 8][ks + tig];
            pa[2] = p_s[w][g][ks + tig + 4];
            pa[3] = p_s[w][g + 8][ks + tig + 4];
#pragma unroll
            for (int nt = 0; nt < 13; nt++) {
                uint32_t b0 = v_s[ks + tig][nt * 8 + g];
                uint32_t b1 = v_s[ks + tig + 4][nt * 8 + g];
                MMA_BF16(of[nt], pa, b0, b1);
            }
        }
        __syncthreads();
    }

    size_t pb0 = (size_t)(z * NCH + c) * SQ + r0;
    size_t pb1 = (size_t)(z * NCH + c) * SQ + r1;
#pragma unroll
    for (int nt = 0; nt < 13; nt++) {
        int d = nt * 8 + 2 * tig;
        if (d < HDIM) {
            *(float2*)&part_o[pb0 * HDIM + d] = make_float2(of[nt][0], of[nt][1]);
            *(float2*)&part_o[pb1 * HDIM + d] = make_float2(of[nt][2], of[nt][3]);
        }
    }
    if (tig == 0) {
        part_ml[pb0 * 2] = m0; part_ml[pb0 * 2 + 1] = l0;
        part_ml[pb1 * 2] = m1; part_ml[pb1 * 2 + 1] = l1;
    }
}

__global__ void attn_combine(const float* __restrict__ part_o,
                             const float* __restrict__ part_ml,
                             uint32_t* __restrict__ ob) {
    int qi = blockIdx.x, e = blockIdx.y;
    int t = threadIdx.x, h = threadIdx.y;
    int z = e * 3 + h;
    int nch = qi / JCH + 1;
    float M = -INFINITY;
    for (int cc = 0; cc < nch; cc++)
        M = fmaxf(M, part_ml[((size_t)(z * NCH + cc) * SQ + qi) * 2]);
    float L = 0.f, a0 = 0.f, a1 = 0.f;
    for (int cc = 0; cc < nch; cc++) {
        size_t pb = (size_t)(z * NCH + cc) * SQ + qi;
        float w = __expf(part_ml[pb * 2] - M);
        L += part_ml[pb * 2 + 1] * w;
        if (t < 50) {
            float2 v = *(const float2*)&part_o[pb * HDIM + 2 * t];
            a0 += w * v.x; a1 += w * v.y;
        }
    }
    if (t < 50) {
        float inv = 1.f / L;
        ob[((size_t)e * SQ + qi) * 150 + h * 50 + t] = packbf(a0 * inv, a1 * inv);
    }
}

// ---------------- fused residual + LayerNorm ----------------
__global__ void ln_kernel(float* __restrict__ x, const float* __restrict__ delta,
                          const float* __restrict__ g, const float* __restrict__ b,
                          uint32_t* __restrict__ xb) {
    __shared__ float rs[8];
    int z = blockIdx.z;
    x += (size_t)z * SQ * EMB; delta += (size_t)z * SQ * EMB;
    g += z * EMB; b += z * EMB; xb += (size_t)z * SQ * 150;
    int r = blockIdx.x, t = threadIdx.x;
    int lane = t & 31, wid = t >> 5;
    float v[2][2];
    float s1 = 0.f, s2 = 0.f;
    {
        float2 a = *(const float2*)&x[(size_t)r * EMB + 2 * t];
        float2 d = *(const float2*)&delta[(size_t)r * EMB + 2 * t];
        v[0][0] = a.x + d.x; v[0][1] = a.y + d.y;
        s1 += v[0][0] + v[0][1];
        s2 += v[0][0] * v[0][0] + v[0][1] * v[0][1];
    }
    if (t < 22) {
        int p = t + 128;
        float2 a = *(const float2*)&x[(size_t)r * EMB + 2 * p];
        float2 d = *(const float2*)&delta[(size_t)r * EMB + 2 * p];
        v[1][0] = a.x + d.x; v[1][1] = a.y + d.y;
        s1 += v[1][0] + v[1][1];
        s2 += v[1][0] * v[1][0] + v[1][1] * v[1][1];
    }
#pragma unroll
    for (int off = 16; off > 0; off >>= 1) {
        s1 += __shfl_xor_sync(0xffffffffu, s1, off);
        s2 += __shfl_xor_sync(0xffffffffu, s2, off);
    }
    if (lane == 0) { rs[wid * 2] = s1; rs[wid * 2 + 1] = s2; }
    __syncthreads();
    float S1 = rs[0] + rs[2] + rs[4] + rs[6];
    float S2 = rs[1] + rs[3] + rs[5] + rs[7];
    float mu = S1 / (float)EMB;
    float var = S2 / (float)EMB - mu * mu;
    float rstd = rsqrtf(var + 1e-5f);
    {
        int c = 2 * t;
        float n0 = (v[0][0] - mu) * rstd * g[c] + b[c];
        float n1 = (v[0][1] - mu) * rstd * g[c + 1] + b[c + 1];
        *(float2*)&x[(size_t)r * EMB + c] = make_float2(n0, n1);
        xb[(size_t)r * 150 + t] = packbf(n0, n1);
    }
    if (t < 22) {
        int c = 2 * (t + 128);
        float n0 = (v[1][0] - mu) * rstd * g[c] + b[c];
        float n1 = (v[1][1] - mu) * rstd * g[c + 1] + b[c + 1];
        *(float2*)&x[(size_t)r * EMB + c] = make_float2(n0, n1);
        xb[(size_t)r * 150 + t + 128] = packbf(n0, n1);
    }
}

// ---------------- row softmax over A: fp32 in, bf16 out ----------------
__global__ void softmax_rows(const float* __restrict__ A, __nv_bfloat16* __restrict__ Ab) {
    __shared__ float row[SQ];
    __shared__ float red[256];
    int r = blockIdx.x, t = threadIdx.x;
    float mx = -INFINITY;
    for (int j = t; j < SQ; j += 256) { float v = A[(size_t)r * SQ + j]; row[j] = v; mx = fmaxf(mx, v); }
    red[t] = mx; __syncthreads();
    for (int off = 128; off > 0; off >>= 1) { if (t < off) red[t] = fmaxf(red[t], red[t + off]); __syncthreads(); }
    mx = red[0];
    __syncthreads();
    float s = 0.f;
    for (int j = t; j < SQ; j += 256) { float e = __expf(row[j] - mx); row[j] = e; s += e; }
    red[t] = s; __syncthreads();
    for (int off = 128; off > 0; off >>= 1) { if (t < off) red[t] += red[t + off]; __syncthreads(); }
    float inv = 1.f / red[0];
    uint32_t* out = (uint32_t*)(Ab + (size_t)r * SQ);
    for (int j = 2 * t; j < SQ; j += 512)
        out[j >> 1] = packbf(row[j] * inv, row[j + 1] * inv);
}

// ---------------- coalesced colsum of elementwise max (two phase) ----------------
__global__ void colsum_partial(const float* __restrict__ H, const float* __restrict__ P,
                               const float* __restrict__ G, const float* __restrict__ Q,
                               float* __restrict__ part) {
    int chunk = blockIdx.x, pair = blockIdx.y;
    int c = threadIdx.x;
    const float* X = pair ? G : H;
    const float* Y = pair ? Q : P;
    int r0 = chunk * 128;
    float s = 0.f;
    for (int r = r0; r < r0 + 128; r++)
        s += fmaxf(X[(size_t)r * EMB + c], Y[(size_t)r * EMB + c]);
    part[((size_t)pair * 32 + chunk) * EMB + c] = s;
}
__global__ void colsum_final(const float* __restrict__ part, float* __restrict__ suv) {
    int j = threadIdx.x;
    int pair = j / EMB, c = j - pair * EMB;
    float s = 0.f;
#pragma unroll
    for (int ch = 0; ch < 32; ch++)
        s += part[((size_t)pair * 32 + ch) * EMB + c];
    suv[j] = s;
}

// ---------------- tiny FC layers ----------------
__global__ void fc1_kernel(const float* __restrict__ inp, const float* __restrict__ w,
                           const float* __restrict__ b, float* __restrict__ out) {
    __shared__ float red[128];
    int i = blockIdx.x, t = threadIdx.x;
    float s = 0.f;
    for (int j = t; j < 2 * EMB; j += 128) s += inp[j] * w[(size_t)i * 2 * EMB + j];
    red[t] = s; __syncthreads();
    for (int off = 64; off > 0; off >>= 1) { if (t < off) red[t] += red[t + off]; __syncthreads(); }
    if (t == 0) out[i] = fmaxf(red[0] + b[i], 0.f);
}

__global__ void fc2_kernel(const float* __restrict__ inp, const float* __restrict__ w,
                           const float* __restrict__ b, float* __restrict__ out) {
    __shared__ float red[256];
    int t = threadIdx.x;
    float s = 0.f;
    for (int j = t; j < EMB; j += 256) s += inp[j] * w[j];
    red[t] = s; __syncthreads();
    for (int off = 128; off > 0; off >>= 1) { if (t < off) red[t] += red[t + off]; __syncthreads(); }
    if (t == 0) out[0] = red[0] + b[0];
}

// ---------------- host orchestration ----------------
extern "C" void kernel_launch(void* const* d_in, const int* in_sizes, int n_in,
                              void* d_out, int out_size) {
    const float* solv = (const float*)d_in[0];
    const float* solu = (const float*)d_in[1];
    const float* ipw  = (const float*)d_in[2];
    const float* ipb  = (const float*)d_in[3];
    const float* ow   = (const float*)d_in[4];
    const float* ob_b = (const float*)d_in[5];
    const float* g1   = (const float*)d_in[6];
    const float* b1   = (const float*)d_in[7];
    const float* w1   = (const float*)d_in[8];
    const float* bb1  = (const float*)d_in[9];
    const float* w2   = (const float*)d_in[10];
    const float* bb2  = (const float*)d_in[11];
    const float* g2   = (const float*)d_in[12];
    const float* b2   = (const float*)d_in[13];
    const float* fc1w = (const float*)d_in[14];
    const float* fc1b = (const float*)d_in[15];
    const float* fc2w = (const float*)d_in[16];
    const float* fc2b = (const float*)d_in[17];

    float *x, *t1, *A, *P, *Q, *Pp, *Qp, *po, *pml, *cpart, *suv, *fc1o;
    uint32_t *xb, *xbT, *wp, *qkvb, *ob, *ffb;
    __nv_bfloat16* Ab;
    cudaGetSymbolAddress((void**)&x,    g_x);
    cudaGetSymbolAddress((void**)&xb,   g_xb);
    cudaGetSymbolAddress((void**)&xbT,  g_xbT);
    cudaGetSymbolAddress((void**)&wp,   g_wpack);
    cudaGetSymbolAddress((void**)&qkvb, g_qkvb);
    cudaGetSymbolAddress((void**)&ob,   g_ob);
    cudaGetSymbolAddress((void**)&t1,   g_t1);
    cudaGetSymbolAddress((void**)&ffb,  g_ffb);
    cudaGetSymbolAddress((void**)&A,    g_A);
    cudaGetSymbolAddress((void**)&Ab,   g_Ab);
    cudaGetSymbolAddress((void**)&P,    g_P);
    cudaGetSymbolAddress((void**)&Q,    g_Q);
    cudaGetSymbolAddress((void**)&Pp,   g_Pp);
    cudaGetSymbolAddress((void**)&Qp,   g_Qp);
    cudaGetSymbolAddress((void**)&po,   g_part_o);
    cudaGetSymbolAddress((void**)&pml,  g_part_ml);
    cudaGetSymbolAddress((void**)&cpart, g_colpart);
    cudaGetSymbolAddress((void**)&suv,  g_suv);
    cudaGetSymbolAddress((void**)&fc1o, g_fc1o);

    const size_t SE = (size_t)SQ * EMB;
    uint32_t* ipwb = wp;
    uint32_t* owb  = wp + 270000;
    uint32_t* w1b  = wp + 360000;
    uint32_t* w2b  = wp + 420000;

    pack4<<<(480000 + 255) / 256, 256>>>(ipw, ow, w1, w2, wp);

    add_pe_kernel<<<dim3((SQ * 150 + 255) / 256, 1, 2), 256>>>(solv, solu, x, xb);

    // qkv = x @ ipw^T + ipb  -> bf16 packed
    mma2<0, 0, 0, 1><<<dim3(15, 32, 2), 256>>>(
        (const __nv_bfloat16*)xb, (const __nv_bfloat16*)ipwb, ipb, (float*)qkvb,
        SQ, 3 * EMB, EMB, EMB, EMB,
        (size_t)SQ * EMB, (size_t)3 * EMB * EMB, 3 * EMB, (size_t)SQ * 450, 0);

    attn_mma_kernel<<<dim3(SQ / QB, NCH, 6), 128>>>(qkvb, po, pml);
    attn_combine<<<dim3(SQ, 2), dim3(64, 3)>>>(po, pml, ob);

    // proj = o @ ow^T + ob  -> fp32 (feeds LN)
    mma2<0, 0, 0, 0><<<dim3(5, 32, 2), 256>>>(
        (const __nv_bfloat16*)ob, (const __nv_bfloat16*)owb, ob_b, t1,
        SQ, EMB, EMB, EMB, EMB,
        (size_t)SQ * EMB, (size_t)EMB * EMB, EMB, SE, 0);
    ln_kernel<<<dim3(SQ, 1, 2), 128>>>(x, t1, g1, b1, xb);

    // ff1 = relu(x @ w1^T + bb1) -> bf16 packed
    mma2<0, 1, 0, 1><<<dim3(4, 32, 2), 256>>>(
        (const __nv_bfloat16*)xb, (const __nv_bfloat16*)w1b, bb1, (float*)ffb,
        SQ, NHID, EMB, EMB, EMB,
        (size_t)SQ * EMB, (size_t)NHID * EMB, NHID, (size_t)SQ * 100, 0);
    // ff2 = ff1 @ w2^T + bb2 -> fp32 (feeds LN)
    mma2<0, 0, 0, 0><<<dim3(5, 32, 2), 256>>>(
        (const __nv_bfloat16*)ffb, (const __nv_bfloat16*)w2b, bb2, t1,
        SQ, EMB, NHID, NHID, NHID,
        (size_t)SQ * NHID, (size_t)EMB * NHID, EMB, SE, 0);
    ln_kernel<<<dim3(SQ, 1, 2), 128>>>(x, t1, g2, b2, xb);

    float* H = x;
    float* G = x + SE;
    uint32_t* Hb = xb;
    uint32_t* Gb = xb + (size_t)SQ * 150;

    transpose_pack<<<dim3(SQ / 64, 5, 2), 256>>>(x, xbT);
    const __nv_bfloat16* HbT = (const __nv_bfloat16*)xbT;
    const __nv_bfloat16* GbT = (const __nv_bfloat16*)xbT + (size_t)EMB * SQ;

    // A = H @ G^T
    mma2<0, 0, 0, 0><<<dim3(64, 32, 1), 256>>>(
        (const __nv_bfloat16*)Hb, (const __nv_bfloat16*)Gb, (const float*)nullptr, A,
        SQ, SQ, EMB, EMB, EMB, 0, 0, 0, 0, 0);
    softmax_rows<<<SQ, 256>>>(A, Ab);

    // P and Q split-K chunks fused into one launch
    mma2_pq<<<dim3(5, 32, 2 * NCH), 256>>>(Ab, GbT, HbT, Pp, Qp);
    reduce_pq<<<dim3((SQ * EMB / 4 + 255) / 256, 2), 256>>>(Pp, Qp, P, Q);

    colsum_partial<<<dim3(32, 2), 300>>>(H, P, G, Q, cpart);
    colsum_final<<<1, 600>>>(cpart, suv);

    fc1_kernel<<<EMB, 128>>>(suv, fc1w, fc1b, fc1o);
    fc2_kernel<<<1, 256>>>(fc1o, fc2w, fc2b, (float*)d_out);
}

// round 12
// speedup vs baseline: 1.3740x; 1.0621x over previous
#include <cuda_runtime.h>
#include <cuda_bf16.h>
#include <math.h>
#include <stdint.h>

#define SQ   4096
#define EMB  300
#define NH   3
#define HDIM 100
#define NHID 200
#define QB   64
#define TJ   32
#define JCH  1024
#define NCH  4
#define KSPL 1024
#define ASTR 136   // As smem stride (words)
#define BSTR 72    // Bs smem stride (words)
#define QKVS 468   // padded qkv row stride (words): 3 segs x 156, head stride 52

// ---------------- scratch (static device globals; no allocation) ----------------
__device__ float g_x[2 * SQ * EMB];            // fp32 encoder state
__device__ uint32_t g_xb[2 * SQ * 150];        // bf16x2 packed x
__device__ uint32_t g_xbT[2 * EMB * (SQ / 2)]; // bf16x2 transposed x (k-major)
__device__ uint32_t g_wpack[480000];           // packed weights: ipw|ow|w1|w2
__device__ __align__(16) uint32_t g_qkvb[2 * SQ * QKVS];
__device__ uint32_t g_ob[2 * SQ * 150];
__device__ float g_t1[2 * SQ * EMB];
__device__ uint32_t g_ffb[2 * SQ * 100];
__device__ float g_A[SQ * SQ];
__device__ __nv_bfloat16 g_Ab[SQ * SQ];
__device__ float g_P[SQ * EMB];
__device__ float g_Q[SQ * EMB];
__device__ float g_Pp[NCH * SQ * EMB];
__device__ float g_Qp[NCH * SQ * EMB];
__device__ float g_part_o[6 * NCH * SQ * HDIM];
__device__ float g_part_ml[6 * NCH * SQ * 2];
__device__ float g_colpart[2 * 32 * EMB];
__device__ float g_suv[2 * EMB];
__device__ float g_fc1o[EMB];

// ---------------- bf16 helpers ----------------
__device__ __forceinline__ uint32_t packbf(float lo, float hi) {
    uint32_t r;
    asm("cvt.rn.bf16x2.f32 %0, %1, %2;" : "=r"(r) : "f"(hi), "f"(lo));
    return r;
}

#define MMA_BF16(C, A, B0, B1)                                                  \
    asm volatile(                                                               \
        "mma.sync.aligned.m16n8k16.row.col.f32.bf16.bf16.f32 "                  \
        "{%0,%1,%2,%3},{%4,%5,%6,%7},{%8,%9},{%0,%1,%2,%3};"                    \
        : "+f"((C)[0]), "+f"((C)[1]), "+f"((C)[2]), "+f"((C)[3])                \
        : "r"((A)[0]), "r"((A)[1]), "r"((A)[2]), "r"((A)[3]), "r"(B0), "r"(B1))

// ---------------- packing kernels ----------------
__global__ void pack4(const float* __restrict__ ipw, const float* __restrict__ ow,
                      const float* __restrict__ w1, const float* __restrict__ w2,
                      uint32_t* __restrict__ dst) {
    int i = blockIdx.x * 256 + threadIdx.x;
    if (i >= 480000) return;
    const float* src;
    int off;
    if (i < 270000)      { src = ipw; off = i; }
    else if (i < 360000) { src = ow;  off = i - 270000; }
    else if (i < 420000) { src = w1;  off = i - 360000; }
    else                 { src = w2;  off = i - 420000; }
    float2 v = ((const float2*)src)[off];
    dst[i] = packbf(v.x, v.y);
}

__global__ void transpose_pack(const float* __restrict__ x, uint32_t* __restrict__ xT) {
    __shared__ float tile[64][65];
    int z = blockIdx.z;
    int s0 = blockIdx.x * 64, c0 = blockIdx.y * 64;
    int t = threadIdx.x;
#pragma unroll
    for (int i = 0; i < 16; i++) {
        int idx = t + i * 256;
        int ls = idx >> 6, lc = idx & 63;
        int c = c0 + lc;
        tile[ls][lc] = (c < EMB) ? x[(size_t)z * SQ * EMB + (size_t)(s0 + ls) * EMB + c] : 0.f;
    }
    __syncthreads();
#pragma unroll
    for (int i = 0; i < 8; i++) {
        int idx = t + i * 256;
        int lc = idx >> 5, lsp = idx & 31;
        int c = c0 + lc;
        if (c < EMB)
            xT[(size_t)z * EMB * (SQ / 2) + (size_t)c * (SQ / 2) + (s0 >> 1) + lsp] =
                packbf(tile[2 * lsp][lc], tile[2 * lsp + 1][lc]);
    }
}

// ---------------- positional encoding + add ----------------
__global__ void add_pe_kernel(const float* __restrict__ solv, const float* __restrict__ solu,
                              float* __restrict__ x, uint32_t* __restrict__ xb) {
    int p = blockIdx.x * blockDim.x + threadIdx.x;
    if (p >= SQ * 150) return;
    int z = blockIdx.z;
    const float* src = z ? solu : solv;
    int s = p / 150, pc = p - s * 150, c = 2 * pc;
    float dv = __expf(-(float)c * (logf(10000.0f) / (float)EMB));
    float arg = (float)s * dv;
    float pe0 = sinf(arg), pe1 = cosf(arg);
    float2 a = *(const float2*)&src[(size_t)s * EMB + c];
    float v0 = a.x + pe0, v1 = a.y + pe1;
    *(float2*)&x[(size_t)z * SQ * EMB + (size_t)s * EMB + c] = make_float2(v0, v1);
    xb[(size_t)z * SQ * 150 + p] = packbf(v0, v1);
}

// ---------------- all-bf16 tensor-core GEMM (128x64 tile, KCF=32, double-buffered) ----
// BF16OUT: 0 = fp32 out, 1 = bf16x2 packed out (row stride N/2), 2 = padded qkv layout.
template<int TA, int RELU, int SPLITK, int BF16OUT>
__global__ __launch_bounds__(256, 2)
void mma2(const __nv_bfloat16* __restrict__ A, const __nv_bfloat16* __restrict__ B,
          const float* __restrict__ bias, float* __restrict__ C,
          int M, int N, int K, int lda, int ldb,
          size_t sA, size_t sB, size_t sBias, size_t sC, int kc) {
    int z = blockIdx.z;
    int k_begin = 0, k_end = K;
    if (SPLITK) {
        k_begin = z * kc;
        k_end = min(K, k_begin + kc);
        C += (size_t)z * sC;
    } else {
        A += (size_t)z * sA; B += (size_t)z * sB; C += (size_t)z * sC;
        if (bias) bias += (size_t)z * sBias;
    }
    uint32_t* C32 = (uint32_t*)C;

    __shared__ uint32_t As[2][16][ASTR];
    __shared__ uint32_t Bs[2][16][BSTR];

    int t = threadIdx.x;
    int warp = t >> 5, lane = t & 31;
    int g = lane >> 2, tig = lane & 3;
    int wm = warp & 3, wn = warp >> 2;
    int row0 = blockIdx.y * 128, col0 = blockIdx.x * 64;
    int wr0 = wm * 32, wc0 = wn * 32;

    float acc[2][4][4];
#pragma unroll
    for (int i = 0; i < 2; i++)
#pragma unroll
        for (int j = 0; j < 4; j++)
#pragma unroll
            for (int h = 0; h < 4; h++) acc[i][j][h] = 0.f;

    uint32_t ra[8], rb[4];

    auto loadA = [&](int kt) {
        if (!TA) {
            int m = t >> 1, kq = (t & 1) * 16;
            const uint32_t* Ap = (const uint32_t*)(A + (size_t)(row0 + m) * lda + kt + kq);
            if (kt + kq + 15 < k_end) {
#pragma unroll
                for (int u = 0; u < 8; u++) ra[u] = Ap[u];
            } else {
                const unsigned short* A16 = (const unsigned short*)(A + (size_t)(row0 + m) * lda);
#pragma unroll
                for (int u = 0; u < 8; u++) {
                    int gk = kt + kq + 2 * u;
                    uint32_t lo = (gk < k_end) ? A16[gk] : 0;
                    uint32_t hi = (gk + 1 < k_end) ? A16[gk + 1] : 0;
                    ra[u] = lo | (hi << 16);
                }
            }
        } else {
            int kp = t >> 4, mq = (t & 15) * 8;
            int gk0 = kt + 2 * kp;
            bool ok0 = gk0 < k_end, ok1 = gk0 + 1 < k_end;
            const uint32_t* r0p = (const uint32_t*)(A + (size_t)gk0 * lda + row0 + mq);
            const uint32_t* r1p = (const uint32_t*)(A + (size_t)(gk0 + 1) * lda + row0 + mq);
            if (ok1) {
#pragma unroll
                for (int u = 0; u < 4; u++) {
                    uint32_t w0 = r0p[u], w1 = r1p[u];
                    ra[2 * u]     = __byte_perm(w0, w1, 0x5410);
                    ra[2 * u + 1] = __byte_perm(w0, w1, 0x7632);
                }
            } else {
#pragma unroll
                for (int u = 0; u < 4; u++) {
                    uint32_t w0 = ok0 ? r0p[u] : 0;
                    ra[2 * u]     = __byte_perm(w0, 0u, 0x5410);
                    ra[2 * u + 1] = __byte_perm(w0, 0u, 0x7632);
                }
            }
        }
    };
    auto loadB = [&](int kt) {
        int n = t >> 2, kq = (t & 3) * 8;
        int gn = col0 + n;
        bool okn = gn < N;
        const uint32_t* Bp = (const uint32_t*)(B + (size_t)gn * ldb + kt + kq);
        if (okn && kt + kq + 7 < k_end) {
#pragma unroll
            for (int u = 0; u < 4; u++) rb[u] = Bp[u];
        } else {
            const unsigned short* B16 = (const unsigned short*)(B + (size_t)gn * ldb);
#pragma unroll
            for (int u = 0; u < 4; u++) {
                int gk = kt + kq + 2 * u;
                uint32_t lo = (okn && gk < k_end) ? B16[gk] : 0;
                uint32_t hi = (okn && gk + 1 < k_end) ? B16[gk + 1] : 0;
                rb[u] = lo | (hi << 16);
            }
        }
    };
    auto storeA = [&](int bf) {
        if (!TA) {
            int m = t >> 1, kp0 = (t & 1) * 8;
#pragma unroll
            for (int u = 0; u < 8; u++) As[bf][kp0 + u][m] = ra[u];
        } else {
            int kp = t >> 4, mq = (t & 15) * 8;
#pragma unroll
            for (int u = 0; u < 8; u++) As[bf][kp][mq + u] = ra[u];
        }
    };
    auto storeB = [&](int bf) {
        int n = t >> 2, kp0 = (t & 3) * 4;
#pragma unroll
        for (int u = 0; u < 4; u++) Bs[bf][kp0 + u][n] = rb[u];
    };

    int nk = (k_end - k_begin + 31) >> 5;
    loadA(k_begin); loadB(k_begin);
    storeA(0); storeB(0);
    __syncthreads();

    int buf = 0;
    for (int it = 0; it < nk; it++) {
        if (it + 1 < nk) { loadA(k_begin + (it + 1) * 32); loadB(k_begin + (it + 1) * 32); }
#pragma unroll
        for (int ks = 0; ks < 16; ks += 8) {
            uint32_t a[2][4], b[4][2];
#pragma unroll
            for (int i = 0; i < 2; i++) {
                int mb = wr0 + i * 16;
                a[i][0] = As[buf][ks + tig][mb + g];
                a[i][1] = As[buf][ks + tig][mb + 8 + g];
                a[i][2] = As[buf][ks + tig + 4][mb + g];
                a[i][3] = As[buf][ks + tig + 4][mb + 8 + g];
            }
#pragma unroll
            for (int j = 0; j < 4; j++) {
                int nb = wc0 + j * 8;
                b[j][0] = Bs[buf][ks + tig][nb + g];
                b[j][1] = Bs[buf][ks + tig + 4][nb + g];
            }
#pragma unroll
            for (int i = 0; i < 2; i++)
#pragma unroll
                for (int j = 0; j < 4; j++)
                    MMA_BF16(acc[i][j], a[i], b[j][0], b[j][1]);
        }
        if (it + 1 < nk) {
            storeA(1 - buf); storeB(1 - buf);
            __syncthreads();
            buf ^= 1;
        }
    }

#pragma unroll
    for (int i = 0; i < 2; i++) {
        int r0 = row0 + wr0 + i * 16 + g;
#pragma unroll
        for (int j = 0; j < 4; j++) {
            int cc = col0 + wc0 + j * 8 + tig * 2;
#pragma unroll
            for (int h = 0; h < 2; h++) {
                int gr = r0 + h * 8;
                float v0 = acc[i][j][h * 2], v1 = acc[i][j][h * 2 + 1];
                if (!SPLITK && bias) {
                    if (cc < N) v0 += bias[cc];
                    if (cc + 1 < N) v1 += bias[cc + 1];
                }
                if (RELU) { v0 = fmaxf(v0, 0.f); v1 = fmaxf(v1, 0.f); }
                if (BF16OUT == 2) {
                    if (cc < N) {   // padded qkv layout: seg*156 + head*52 + pair
                        int seg = cc / 300, rem = cc - seg * 300;
                        int hh = rem / 100, wi = rem - hh * 100;
                        C32[(size_t)gr * QKVS + seg * 156 + hh * 52 + (wi >> 1)] = packbf(v0, v1);
                    }
                } else if (BF16OUT == 1) {
                    if (cc < N)
                        C32[(size_t)gr * (N >> 1) + (cc >> 1)] = packbf(v0, v1);
                } else if (cc + 1 < N) {
                    *(float2*)&C[(size_t)gr * N + cc] = make_float2(v0, v1);
                } else if (cc < N) {
                    C[(size_t)gr * N + cc] = v0;
                }
            }
        }
    }
}

// ---------------- fused P+Q split-K GEMM (runtime transpose flag) ----------------
__global__ __launch_bounds__(256, 2)
void mma2_pq(const __nv_bfloat16* __restrict__ Ain, const __nv_bfloat16* __restrict__ BP,
             const __nv_bfloat16* __restrict__ BQ, float* __restrict__ CP,
             float* __restrict__ CQ) {
    int z = blockIdx.z;
    int ta = (z >= NCH) ? 1 : 0;
    int zz = ta ? z - NCH : z;
    int k_begin = zz * KSPL;
    const __nv_bfloat16* B = ta ? BQ : BP;
    float* C = (ta ? CQ : CP) + (size_t)zz * SQ * EMB;
    const int lda = SQ, ldb = SQ, N = EMB;

    __shared__ uint32_t As[2][16][ASTR];
    __shared__ uint32_t Bs[2][16][BSTR];

    int t = threadIdx.x;
    int warp = t >> 5, lane = t & 31;
    int g = lane >> 2, tig = lane & 3;
    int wm = warp & 3, wn = warp >> 2;
    int row0 = blockIdx.y * 128, col0 = blockIdx.x * 64;
    int wr0 = wm * 32, wc0 = wn * 32;

    float acc[2][4][4];
#pragma unroll
    for (int i = 0; i < 2; i++)
#pragma unroll
        for (int j = 0; j < 4; j++)
#pragma unroll
            for (int h = 0; h < 4; h++) acc[i][j][h] = 0.f;

    uint32_t ra[8], rb[4];

    auto loadA = [&](int kt) {
        if (!ta) {
            int m = t >> 1, kq = (t & 1) * 16;
            const uint32_t* Ap = (const uint32_t*)(Ain + (size_t)(row0 + m) * lda + kt + kq);
#pragma unroll
            for (int u = 0; u < 8; u++) ra[u] = Ap[u];
        } else {
            int kp = t >> 4, mq = (t & 15) * 8;
            int gk0 = kt + 2 * kp;
            const uint32_t* r0p = (const uint32_t*)(Ain + (size_t)gk0 * lda + row0 + mq);
            const uint32_t* r1p = (const uint32_t*)(Ain + (size_t)(gk0 + 1) * lda + row0 + mq);
#pragma unroll
            for (int u = 0; u < 4; u++) {
                uint32_t w0 = r0p[u], w1 = r1p[u];
                ra[2 * u]     = __byte_perm(w0, w1, 0x5410);
                ra[2 * u + 1] = __byte_perm(w0, w1, 0x7632);
            }
        }
    };
    auto loadB = [&](int kt) {
        int n = t >> 2, kq = (t & 3) * 8;
        int gn = col0 + n;
        if (gn < N) {
            const uint32_t* Bp = (const uint32_t*)(B + (size_t)gn * ldb + kt + kq);
#pragma unroll
            for (int u = 0; u < 4; u++) rb[u] = Bp[u];
        } else {
#pragma unroll
            for (int u = 0; u < 4; u++) rb[u] = 0u;
        }
    };
    auto storeA = [&](int bf) {
        if (!ta) {
            int m = t >> 1, kp0 = (t & 1) * 8;
#pragma unroll
            for (int u = 0; u < 8; u++) As[bf][kp0 + u][m] = ra[u];
        } else {
            int kp = t >> 4, mq = (t & 15) * 8;
#pragma unroll
            for (int u = 0; u < 8; u++) As[bf][kp][mq + u] = ra[u];
        }
    };
    auto storeB = [&](int bf) {
        int n = t >> 2, kp0 = (t & 3) * 4;
#pragma unroll
        for (int u = 0; u < 4; u++) Bs[bf][kp0 + u][n] = rb[u];
    };

    const int nk = KSPL >> 5;
    loadA(k_begin); loadB(k_begin);
    storeA(0); storeB(0);
    __syncthreads();

    int buf = 0;
    for (int it = 0; it < nk; it++) {
        if (it + 1 < nk) { loadA(k_begin + (it + 1) * 32); loadB(k_begin + (it + 1) * 32); }
#pragma unroll
        for (int ks = 0; ks < 16; ks += 8) {
            uint32_t a[2][4], b[4][2];
#pragma unroll
            for (int i = 0; i < 2; i++) {
                int mb = wr0 + i * 16;
                a[i][0] = As[buf][ks + tig][mb + g];
                a[i][1] = As[buf][ks + tig][mb + 8 + g];
                a[i][2] = As[buf][ks + tig + 4][mb + g];
                a[i][3] = As[buf][ks + tig + 4][mb + 8 + g];
            }
#pragma unroll
            for (int j = 0; j < 4; j++) {
                int nb = wc0 + j * 8;
                b[j][0] = Bs[buf][ks + tig][nb + g];
                b[j][1] = Bs[buf][ks + tig + 4][nb + g];
            }
#pragma unroll
            for (int i = 0; i < 2; i++)
#pragma unroll
                for (int j = 0; j < 4; j++)
                    MMA_BF16(acc[i][j], a[i], b[j][0], b[j][1]);
        }
        if (it + 1 < nk) {
            storeA(1 - buf); storeB(1 - buf);
            __syncthreads();
            buf ^= 1;
        }
    }

#pragma unroll
    for (int i = 0; i < 2; i++) {
        int r0 = row0 + wr0 + i * 16 + g;
#pragma unroll
        for (int j = 0; j < 4; j++) {
            int cc = col0 + wc0 + j * 8 + tig * 2;
#pragma unroll
            for (int h = 0; h < 2; h++) {
                int gr = r0 + h * 8;
                float v0 = acc[i][j][h * 2], v1 = acc[i][j][h * 2 + 1];
                if (cc + 1 < N) {
                    *(float2*)&C[(size_t)gr * N + cc] = make_float2(v0, v1);
                } else if (cc < N) {
                    C[(size_t)gr * N + cc] = v0;
                }
            }
        }
    }
}

// ---------------- split-K reduce for P and Q ----------------
__global__ void reduce_pq(const float* __restrict__ Pp, const float* __restrict__ Qp,
                          float* __restrict__ P, float* __restrict__ Q) {
    int idx = blockIdx.x * 256 + threadIdx.x;
    if (idx >= SQ * EMB / 4) return;
    const float* src = blockIdx.y ? Qp : Pp;
    float* dst = blockIdx.y ? Q : P;
    float4 r = make_float4(0.f, 0.f, 0.f, 0.f);
#pragma unroll
    for (int c = 0; c < NCH; c++) {
        float4 a = ((const float4*)(src + (size_t)c * SQ * EMB))[idx];
        r.x += a.x; r.y += a.y; r.z += a.z; r.w += a.w;
    }
    ((float4*)dst)[idx] = r;
}

// ---------------- bf16 flash attention: padded qkv, vectorized staging, reg P -----
__global__ __launch_bounds__(128, 5)
void attn_mma_kernel(const uint32_t* __restrict__ qb_all,
                     float* __restrict__ part_o, float* __restrict__ part_ml) {
    __shared__ __align__(16) uint32_t k_s[TJ][60];
    __shared__ __align__(16) uint32_t v_s[16][108];
    __shared__ uint32_t q_s[4][16][58];

    int z = blockIdx.z, e = z / 3, h = z % 3;
    int qt = (int)gridDim.x - 1 - (int)blockIdx.x;
    int q0 = qt * QB;
    int c = blockIdx.y, c0 = c * JCH;
    if (c0 > q0 + QB - 1) return;

    const uint32_t* qb = qb_all + (size_t)e * SQ * QKVS;
    int t = threadIdx.x, w = t >> 5, lane = t & 31;
    int g = lane >> 2, tig = lane & 3;

    int r0 = q0 + w * 16 + g;
    int r1 = r0 + 8;

    // stage Q fragments into smem once
    {
        const uint32_t* q0p = qb + (size_t)r0 * QKVS + h * 52;
        const uint32_t* q1p = qb + (size_t)r1 * QKVS + h * 52;
#pragma unroll
        for (int s = 0; s < 7; s++) {
            int dp0 = s * 8 + tig, dp1 = dp0 + 4;
            q_s[w][g][dp0]     = dp0 < 50 ? q0p[dp0] : 0u;
            q_s[w][g + 8][dp0] = dp0 < 50 ? q1p[dp0] : 0u;
            q_s[w][g][dp1]     = dp1 < 50 ? q0p[dp1] : 0u;
            q_s[w][g + 8][dp1] = dp1 < 50 ? q1p[dp1] : 0u;
        }
    }
    // zero pad columns once (never rewritten in the loop; disjoint from staged cols)
    for (int idx = t; idx < 32 * 6; idx += 128) k_s[idx / 6][50 + idx % 6] = 0u;
    for (int idx = t; idx < 16 * 8; idx += 128) v_s[idx / 8][100 + idx % 8] = 0u;

    float of[13][4];
#pragma unroll
    for (int nt = 0; nt < 13; nt++) { of[nt][0] = of[nt][1] = of[nt][2] = of[nt][3] = 0.f; }
    float m0 = -INFINITY, m1 = -INFINITY, l0 = 0.f, l1 = 0.f;

    int jend = min(c0 + JCH, q0 + QB);
    for (int jt = c0; jt < jend; jt += TJ) {
        // K stage: 12 x uint4 + 1 x uint2 per row (16B-aligned in padded layout)
        for (int idx = t; idx < 32 * 13; idx += 128) {
            int row = idx / 13, sl = idx - row * 13;
            const uint32_t* src = qb + (size_t)(jt + row) * QKVS + 156 + h * 52;
            if (sl < 12) {
                *(uint4*)&k_s[row][4 * sl] = *(const uint4*)(src + 4 * sl);
            } else {
                *(uint2*)&k_s[row][48] = *(const uint2*)(src + 48);
            }
        }
        // V stage: interleave two j rows, vectorized
        for (int idx = t; idx < 16 * 13; idx += 128) {
            int jp = idx / 13, sl = idx - jp * 13;
            const uint32_t* s0p = qb + (size_t)(jt + 2 * jp) * QKVS + 312 + h * 52;
            const uint32_t* s1p = s0p + QKVS;
            if (sl < 12) {
                uint4 a = *(const uint4*)(s0p + 4 * sl);
                uint4 b = *(const uint4*)(s1p + 4 * sl);
                uint4 o0, o1;
                o0.x = __byte_perm(a.x, b.x, 0x5410); o0.y = __byte_perm(a.x, b.x, 0x7632);
                o0.z = __byte_perm(a.y, b.y, 0x5410); o0.w = __byte_perm(a.y, b.y, 0x7632);
                o1.x = __byte_perm(a.z, b.z, 0x5410); o1.y = __byte_perm(a.z, b.z, 0x7632);
                o1.z = __byte_perm(a.w, b.w, 0x5410); o1.w = __byte_perm(a.w, b.w, 0x7632);
                *(uint4*)&v_s[jp][8 * sl] = o0;
                *(uint4*)&v_s[jp][8 * sl + 4] = o1;
            } else {
                uint2 a = *(const uint2*)(s0p + 48);
                uint2 b = *(const uint2*)(s1p + 48);
                uint4 o;
                o.x = __byte_perm(a.x, b.x, 0x5410); o.y = __byte_perm(a.x, b.x, 0x7632);
                o.z = __byte_perm(a.y, b.y, 0x5410); o.w = __byte_perm(a.y, b.y, 0x7632);
                *(uint4*)&v_s[jp][96] = o;
            }
        }
        __syncthreads();

        float sc[4][4];
#pragma unroll
        for (int nt = 0; nt < 4; nt++) { sc[nt][0] = sc[nt][1] = sc[nt][2] = sc[nt][3] = 0.f; }
#pragma unroll
        for (int s = 0; s < 7; s++) {
            uint32_t qa[4];
            qa[0] = q_s[w][g][s * 8 + tig];
            qa[1] = q_s[w][g + 8][s * 8 + tig];
            qa[2] = q_s[w][g][s * 8 + tig + 4];
            qa[3] = q_s[w][g + 8][s * 8 + tig + 4];
#pragma unroll
            for (int nt = 0; nt < 4; nt++) {
                uint32_t b0 = k_s[nt * 8 + g][s * 8 + tig];
                uint32_t b1 = k_s[nt * 8 + g][s * 8 + tig + 4];
                MMA_BF16(sc[nt], qa, b0, b1);
            }
        }
#pragma unroll
        for (int nt = 0; nt < 4; nt++) {
            sc[nt][0] *= 0.1f; sc[nt][1] *= 0.1f; sc[nt][2] *= 0.1f; sc[nt][3] *= 0.1f;
        }

        if (jt + TJ > q0) {
#pragma unroll
            for (int nt = 0; nt < 4; nt++) {
                int jb = jt + nt * 8 + 2 * tig;
                if (jb > r0)     sc[nt][0] = -INFINITY;
                if (jb + 1 > r0) sc[nt][1] = -INFINITY;
                if (jb > r1)     sc[nt][2] = -INFINITY;
                if (jb + 1 > r1) sc[nt][3] = -INFINITY;
            }
        }

        float rm0 = -INFINITY, rm1 = -INFINITY;
#pragma unroll
        for (int nt = 0; nt < 4; nt++) {
            rm0 = fmaxf(rm0, fmaxf(sc[nt][0], sc[nt][1]));
            rm1 = fmaxf(rm1, fmaxf(sc[nt][2], sc[nt][3]));
        }
        rm0 = fmaxf(rm0, __shfl_xor_sync(0xffffffffu, rm0, 1));
        rm0 = fmaxf(rm0, __shfl_xor_sync(0xffffffffu, rm0, 2));
        rm1 = fmaxf(rm1, __shfl_xor_sync(0xffffffffu, rm1, 1));
        rm1 = fmaxf(rm1, __shfl_xor_sync(0xffffffffu, rm1, 2));
        float mn0 = fmaxf(m0, rm0), mn1 = fmaxf(m1, rm1);
        float s0 = __expf(m0 - mn0), s1 = __expf(m1 - mn1);

        // P stays in registers: the S C-fragment IS the PV A-fragment (same thread)
        uint32_t pp[4][2];
        float rs0 = 0.f, rs1 = 0.f;
#pragma unroll
        for (int nt = 0; nt < 4; nt++) {
            float p0 = __expf(sc[nt][0] - mn0);
            float p1 = __expf(sc[nt][1] - mn0);
            float p2 = __expf(sc[nt][2] - mn1);
            float p3 = __expf(sc[nt][3] - mn1);
            rs0 += p0 + p1;
            rs1 += p2 + p3;
            pp[nt][0] = packbf(p0, p1);
            pp[nt][1] = packbf(p2, p3);
        }
        rs0 += __shfl_xor_sync(0xffffffffu, rs0, 1);
        rs0 += __shfl_xor_sync(0xffffffffu, rs0, 2);
        rs1 += __shfl_xor_sync(0xffffffffu, rs1, 1);
        rs1 += __shfl_xor_sync(0xffffffffu, rs1, 2);
        l0 = l0 * s0 + rs0;
        l1 = l1 * s1 + rs1;
        m0 = mn0; m1 = mn1;

#pragma unroll
        for (int nt = 0; nt < 13; nt++) {
            of[nt][0] *= s0; of[nt][1] *= s0;
            of[nt][2] *= s1; of[nt][3] *= s1;
        }

        // O += P V : pa for ks=0 is pp[0],pp[1]; for ks=8 is pp[2],pp[3]
#pragma unroll
        for (int kh = 0; kh < 2; kh++) {
            int ks = kh * 8;
            uint32_t pa[4];
            pa[0] = pp[2 * kh][0];
            pa[1] = pp[2 * kh][1];
            pa[2] = pp[2 * kh + 1][0];
            pa[3] = pp[2 * kh + 1][1];
#pragma unroll
            for (int nt = 0; nt < 13; nt++) {
                uint32_t b0 = v_s[ks + tig][nt * 8 + g];
                uint32_t b1 = v_s[ks + tig + 4][nt * 8 + g];
                MMA_BF16(of[nt], pa, b0, b1);
            }
        }
        __syncthreads();
    }

    size_t pb0 = (size_t)(z * NCH + c) * SQ + r0;
    size_t pb1 = (size_t)(z * NCH + c) * SQ + r1;
#pragma unroll
    for (int nt = 0; nt < 13; nt++) {
        int d = nt * 8 + 2 * tig;
        if (d < HDIM) {
            *(float2*)&part_o[pb0 * HDIM + d] = make_float2(of[nt][0], of[nt][1]);
            *(float2*)&part_o[pb1 * HDIM + d] = make_float2(of[nt][2], of[nt][3]);
        }
    }
    if (tig == 0) {
        part_ml[pb0 * 2] = m0; part_ml[pb0 * 2 + 1] = l0;
        part_ml[pb1 * 2] = m1; part_ml[pb1 * 2 + 1] = l1;
    }
}

__global__ void attn_combine(const float* __restrict__ part_o,
                             const float* __restrict__ part_ml,
                             uint32_t* __restrict__ ob) {
    int qi = blockIdx.x, e = blockIdx.y;
    int t = threadIdx.x, h = threadIdx.y;
    int z = e * 3 + h;
    int nch = qi / JCH + 1;
    float M = -INFINITY;
    for (int cc = 0; cc < nch; cc++)
        M = fmaxf(M, part_ml[((size_t)(z * NCH + cc) * SQ + qi) * 2]);
    float L = 0.f, a0 = 0.f, a1 = 0.f;
    for (int cc = 0; cc < nch; cc++) {
        size_t pb = (size_t)(z * NCH + cc) * SQ + qi;
        float w = __expf(part_ml[pb * 2] - M);
        L += part_ml[pb * 2 + 1] * w;
        if (t < 50) {
            float2 v = *(const float2*)&part_o[pb * HDIM + 2 * t];
            a0 += w * v.x; a1 += w * v.y;
        }
    }
    if (t < 50) {
        float inv = 1.f / L;
        ob[((size_t)e * SQ + qi) * 150 + h * 50 + t] = packbf(a0 * inv, a1 * inv);
    }
}

// ---------------- fused residual + LayerNorm ----------------
__global__ void ln_kernel(float* __restrict__ x, const float* __restrict__ delta,
                          const float* __restrict__ g, const float* __restrict__ b,
                          uint32_t* __restrict__ xb) {
    __shared__ float rs[8];
    int z = blockIdx.z;
    x += (size_t)z * SQ * EMB; delta += (size_t)z * SQ * EMB;
    g += z * EMB; b += z * EMB; xb += (size_t)z * SQ * 150;
    int r = blockIdx.x, t = threadIdx.x;
    int lane = t & 31, wid = t >> 5;
    float v[2][2];
    float s1 = 0.f, s2 = 0.f;
    {
        float2 a = *(const float2*)&x[(size_t)r * EMB + 2 * t];
        float2 d = *(const float2*)&delta[(size_t)r * EMB + 2 * t];
        v[0][0] = a.x + d.x; v[0][1] = a.y + d.y;
        s1 += v[0][0] + v[0][1];
        s2 += v[0][0] * v[0][0] + v[0][1] * v[0][1];
    }
    if (t < 22) {
        int p = t + 128;
        float2 a = *(const float2*)&x[(size_t)r * EMB + 2 * p];
        float2 d = *(const float2*)&delta[(size_t)r * EMB + 2 * p];
        v[1][0] = a.x + d.x; v[1][1] = a.y + d.y;
        s1 += v[1][0] + v[1][1];
        s2 += v[1][0] * v[1][0] + v[1][1] * v[1][1];
    }
#pragma unroll
    for (int off = 16; off > 0; off >>= 1) {
        s1 += __shfl_xor_sync(0xffffffffu, s1, off);
        s2 += __shfl_xor_sync(0xffffffffu, s2, off);
    }
    if (lane == 0) { rs[wid * 2] = s1; rs[wid * 2 + 1] = s2; }
    __syncthreads();
    float S1 = rs[0] + rs[2] + rs[4] + rs[6];
    float S2 = rs[1] + rs[3] + rs[5] + rs[7];
    float mu = S1 / (float)EMB;
    float var = S2 / (float)EMB - mu * mu;
    float rstd = rsqrtf(var + 1e-5f);
    {
        int c = 2 * t;
        float n0 = (v[0][0] - mu) * rstd * g[c] + b[c];
        float n1 = (v[0][1] - mu) * rstd * g[c + 1] + b[c + 1];
        *(float2*)&x[(size_t)r * EMB + c] = make_float2(n0, n1);
        xb[(size_t)r * 150 + t] = packbf(n0, n1);
    }
    if (t < 22) {
        int c = 2 * (t + 128);
        float n0 = (v[1][0] - mu) * rstd * g[c] + b[c];
        float n1 = (v[1][1] - mu) * rstd * g[c + 1] + b[c + 1];
        *(float2*)&x[(size_t)r * EMB + c] = make_float2(n0, n1);
        xb[(size_t)r * 150 + t + 128] = packbf(n0, n1);
    }
}

// ---------------- row softmax over A: fp32 in, bf16 out ----------------
__global__ void softmax_rows(const float* __restrict__ A, __nv_bfloat16* __restrict__ Ab) {
    __shared__ float row[SQ];
    __shared__ float red[256];
    int r = blockIdx.x, t = threadIdx.x;
    float mx = -INFINITY;
    for (int j = t; j < SQ; j += 256) { float v = A[(size_t)r * SQ + j]; row[j] = v; mx = fmaxf(mx, v); }
    red[t] = mx; __syncthreads();
    for (int off = 128; off > 0; off >>= 1) { if (t < off) red[t] = fmaxf(red[t], red[t + off]); __syncthreads(); }
    mx = red[0];
    __syncthreads();
    float s = 0.f;
    for (int j = t; j < SQ; j += 256) { float e = __expf(row[j] - mx); row[j] = e; s += e; }
    red[t] = s; __syncthreads();
    for (int off = 128; off > 0; off >>= 1) { if (t < off) red[t] += red[t + off]; __syncthreads(); }
    float inv = 1.f / red[0];
    uint32_t* out = (uint32_t*)(Ab + (size_t)r * SQ);
    for (int j = 2 * t; j < SQ; j += 512)
        out[j >> 1] = packbf(row[j] * inv, row[j + 1] * inv);
}

// ---------------- coalesced colsum of elementwise max (two phase) ----------------
__global__ void colsum_partial(const float* __restrict__ H, const float* __restrict__ P,
                               const float* __restrict__ G, const float* __restrict__ Q,
                               float* __restrict__ part) {
    int chunk = blockIdx.x, pair = blockIdx.y;
    int c = threadIdx.x;
    const float* X = pair ? G : H;
    const float* Y = pair ? Q : P;
    int r0 = chunk * 128;
    float s = 0.f;
    for (int r = r0; r < r0 + 128; r++)
        s += fmaxf(X[(size_t)r * EMB + c], Y[(size_t)r * EMB + c]);
    part[((size_t)pair * 32 + chunk) * EMB + c] = s;
}
__global__ void colsum_final(const float* __restrict__ part, float* __restrict__ suv) {
    int j = threadIdx.x;
    int pair = j / EMB, c = j - pair * EMB;
    float s = 0.f;
#pragma unroll
    for (int ch = 0; ch < 32; ch++)
        s += part[((size_t)pair * 32 + ch) * EMB + c];
    suv[j] = s;
}

// ---------------- tiny FC layers ----------------
__global__ void fc1_kernel(const float* __restrict__ inp, const float* __restrict__ w,
                           const float* __restrict__ b, float* __restrict__ out) {
    __shared__ float red[128];
    int i = blockIdx.x, t = threadIdx.x;
    float s = 0.f;
    for (int j = t; j < 2 * EMB; j += 128) s += inp[j] * w[(size_t)i * 2 * EMB + j];
    red[t] = s; __syncthreads();
    for (int off = 64; off > 0; off >>= 1) { if (t < off) red[t] += red[t + off]; __syncthreads(); }
    if (t == 0) out[i] = fmaxf(red[0] + b[i], 0.f);
}

__global__ void fc2_kernel(const float* __restrict__ inp, const float* __restrict__ w,
                           const float* __restrict__ b, float* __restrict__ out) {
    __shared__ float red[256];
    int t = threadIdx.x;
    float s = 0.f;
    for (int j = t; j < EMB; j += 256) s += inp[j] * w[j];
    red[t] = s; __syncthreads();
    for (int off = 128; off > 0; off >>= 1) { if (t < off) red[t] += red[t + off]; __syncthreads(); }
    if (t == 0) out[0] = red[0] + b[0];
}

// ---------------- host orchestration ----------------
extern "C" void kernel_launch(void* const* d_in, const int* in_sizes, int n_in,
                              void* d_out, int out_size) {
    const float* solv = (const float*)d_in[0];
    const float* solu = (const float*)d_in[1];
    const float* ipw  = (const float*)d_in[2];
    const float* ipb  = (const float*)d_in[3];
    const float* ow   = (const float*)d_in[4];
    const float* ob_b = (const float*)d_in[5];
    const float* g1   = (const float*)d_in[6];
    const float* b1   = (const float*)d_in[7];
    const float* w1   = (const float*)d_in[8];
    const float* bb1  = (const float*)d_in[9];
    const float* w2   = (const float*)d_in[10];
    const float* bb2  = (const float*)d_in[11];
    const float* g2   = (const float*)d_in[12];
    const float* b2   = (const float*)d_in[13];
    const float* fc1w = (const float*)d_in[14];
    const float* fc1b = (const float*)d_in[15];
    const float* fc2w = (const float*)d_in[16];
    const float* fc2b = (const float*)d_in[17];

    float *x, *t1, *A, *P, *Q, *Pp, *Qp, *po, *pml, *cpart, *suv, *fc1o;
    uint32_t *xb, *xbT, *wp, *qkvb, *ob, *ffb;
    __nv_bfloat16* Ab;
    cudaGetSymbolAddress((void**)&x,    g_x);
    cudaGetSymbolAddress((void**)&xb,   g_xb);
    cudaGetSymbolAddress((void**)&xbT,  g_xbT);
    cudaGetSymbolAddress((void**)&wp,   g_wpack);
    cudaGetSymbolAddress((void**)&qkvb, g_qkvb);
    cudaGetSymbolAddress((void**)&ob,   g_ob);
    cudaGetSymbolAddress((void**)&t1,   g_t1);
    cudaGetSymbolAddress((void**)&ffb,  g_ffb);
    cudaGetSymbolAddress((void**)&A,    g_A);
    cudaGetSymbolAddress((void**)&Ab,   g_Ab);
    cudaGetSymbolAddress((void**)&P,    g_P);
    cudaGetSymbolAddress((void**)&Q,    g_Q);
    cudaGetSymbolAddress((void**)&Pp,   g_Pp);
    cudaGetSymbolAddress((void**)&Qp,   g_Qp);
    cudaGetSymbolAddress((void**)&po,   g_part_o);
    cudaGetSymbolAddress((void**)&pml,  g_part_ml);
    cudaGetSymbolAddress((void**)&cpart, g_colpart);
    cudaGetSymbolAddress((void**)&suv,  g_suv);
    cudaGetSymbolAddress((void**)&fc1o, g_fc1o);

    const size_t SE = (size_t)SQ * EMB;
    uint32_t* ipwb = wp;
    uint32_t* owb  = wp + 270000;
    uint32_t* w1b  = wp + 360000;
    uint32_t* w2b  = wp + 420000;

    pack4<<<(480000 + 255) / 256, 256>>>(ipw, ow, w1, w2, wp);

    add_pe_kernel<<<dim3((SQ * 150 + 255) / 256, 1, 2), 256>>>(solv, solu, x, xb);

    // qkv = x @ ipw^T + ipb  -> padded bf16 qkv layout (BF16OUT=2)
    mma2<0, 0, 0, 2><<<dim3(15, 32, 2), 256>>>(
        (const __nv_bfloat16*)xb, (const __nv_bfloat16*)ipwb, ipb, (float*)qkvb,
        SQ, 3 * EMB, EMB, EMB, EMB,
        (size_t)SQ * EMB, (size_t)3 * EMB * EMB, 3 * EMB, (size_t)SQ * QKVS, 0);

    attn_mma_kernel<<<dim3(SQ / QB, NCH, 6), 128>>>(qkvb, po, pml);
    attn_combine<<<dim3(SQ, 2), dim3(64, 3)>>>(po, pml, ob);

    // proj = o @ ow^T + ob  -> fp32 (feeds LN)
    mma2<0, 0, 0, 0><<<dim3(5, 32, 2), 256>>>(
        (const __nv_bfloat16*)ob, (const __nv_bfloat16*)owb, ob_b, t1,
        SQ, EMB, EMB, EMB, EMB,
        (size_t)SQ * EMB, (size_t)EMB * EMB, EMB, SE, 0);
    ln_kernel<<<dim3(SQ, 1, 2), 128>>>(x, t1, g1, b1, xb);

    // ff1 = relu(x @ w1^T + bb1) -> bf16 packed
    mma2<0, 1, 0, 1><<<dim3(4, 32, 2), 256>>>(
        (const __nv_bfloat16*)xb, (const __nv_bfloat16*)w1b, bb1, (float*)ffb,
        SQ, NHID, EMB, EMB, EMB,
        (size_t)SQ * EMB, (size_t)NHID * EMB, NHID, (size_t)SQ * 100, 0);
    // ff2 = ff1 @ w2^T + bb2 -> fp32 (feeds LN)
    mma2<0, 0, 0, 0><<<dim3(5, 32, 2), 256>>>(
        (const __nv_bfloat16*)ffb, (const __nv_bfloat16*)w2b, bb2, t1,
        SQ, EMB, NHID, NHID, NHID,
        (size_t)SQ * NHID, (size_t)EMB * NHID, EMB, SE, 0);
    ln_kernel<<<dim3(SQ, 1, 2), 128>>>(x, t1, g2, b2, xb);

    float* H = x;
    float* G = x + SE;
    uint32_t* Hb = xb;
    uint32_t* Gb = xb + (size_t)SQ * 150;

    transpose_pack<<<dim3(SQ / 64, 5, 2), 256>>>(x, xbT);
    const __nv_bfloat16* HbT = (const __nv_bfloat16*)xbT;
    const __nv_bfloat16* GbT = (const __nv_bfloat16*)xbT + (size_t)EMB * SQ;

    // A = H @ G^T
    mma2<0, 0, 0, 0><<<dim3(64, 32, 1), 256>>>(
        (const __nv_bfloat16*)Hb, (const __nv_bfloat16*)Gb, (const float*)nullptr, A,
        SQ, SQ, EMB, EMB, EMB, 0, 0, 0, 0, 0);
    softmax_rows<<<SQ, 256>>>(A, Ab);

    // P and Q split-K chunks fused into one launch
    mma2_pq<<<dim3(5, 32, 2 * NCH), 256>>>(Ab, GbT, HbT, Pp, Qp);
    reduce_pq<<<dim3((SQ * EMB / 4 + 255) / 256, 2), 256>>>(Pp, Qp, P, Q);

    colsum_partial<<<dim3(32, 2), 300>>>(H, P, G, Q, cpart);
    colsum_final<<<1, 600>>>(cpart, suv);

    fc1_kernel<<<EMB, 128>>>(suv, fc1w, fc1b, fc1o);
    fc2_kernel<<<1, 256>>>(fc1o, fc2w, fc2b, (float*)d_out);
}

// round 13
// speedup vs baseline: 1.3839x; 1.0072x over previous
#include <cuda_runtime.h>
#include <cuda_bf16.h>
#include <math.h>
#include <stdint.h>

#define SQ   4096
#define EMB  300
#define NH   3
#define HDIM 100
#define NHID 200
#define QB   64
#define TJ   32
#define JCH  1024
#define NCH  4
#define KSPL 1024
#define ASTR 136   // As smem stride (words)
#define BSTR 72    // Bs smem stride (words)
#define QKVS 468   // padded qkv row stride (words): 3 segs x 156, head stride 52

// ---------------- scratch (static device globals; no allocation) ----------------
__device__ float g_x[2 * SQ * EMB];            // fp32 encoder state
__device__ uint32_t g_xb[2 * SQ * 150];        // bf16x2 packed x
__device__ uint32_t g_xbT[2 * EMB * (SQ / 2)]; // bf16x2 transposed x (k-major)
__device__ uint32_t g_wpack[480000];           // packed weights: ipw|ow|w1|w2
__device__ __align__(16) uint32_t g_qkvb[2 * SQ * QKVS];
__device__ uint32_t g_ob[2 * SQ * 150];
__device__ float g_t1[2 * SQ * EMB];
__device__ uint32_t g_ffb[2 * SQ * 100];
__device__ float g_A[SQ * SQ];
__device__ __nv_bfloat16 g_Ab[SQ * SQ];
__device__ float g_P[SQ * EMB];
__device__ float g_Q[SQ * EMB];
__device__ float g_Pp[NCH * SQ * EMB];
__device__ float g_Qp[NCH * SQ * EMB];
__device__ float g_part_o[6 * NCH * SQ * HDIM];
__device__ float g_part_ml[6 * NCH * SQ * 2];
__device__ float g_colpart[2 * 32 * EMB];
__device__ float g_suv[2 * EMB];
__device__ float g_fc1o[EMB];

// ---------------- bf16 helpers ----------------
__device__ __forceinline__ uint32_t packbf(float lo, float hi) {
    uint32_t r;
    asm("cvt.rn.bf16x2.f32 %0, %1, %2;" : "=r"(r) : "f"(hi), "f"(lo));
    return r;
}

#define MMA_BF16(C, A, B0, B1)                                                  \
    asm volatile(                                                               \
        "mma.sync.aligned.m16n8k16.row.col.f32.bf16.bf16.f32 "                  \
        "{%0,%1,%2,%3},{%4,%5,%6,%7},{%8,%9},{%0,%1,%2,%3};"                    \
        : "+f"((C)[0]), "+f"((C)[1]), "+f"((C)[2]), "+f"((C)[3])                \
        : "r"((A)[0]), "r"((A)[1]), "r"((A)[2]), "r"((A)[3]), "r"(B0), "r"(B1))

#define LDMX4(R, ADDR)                                                          \
    asm volatile("ldmatrix.sync.aligned.m8n8.x4.shared.b16 {%0,%1,%2,%3}, [%4];" \
        : "=r"((R)[0]), "=r"((R)[1]), "=r"((R)[2]), "=r"((R)[3]) : "r"(ADDR))

// ---------------- packing kernels ----------------
__global__ void pack4(const float* __restrict__ ipw, const float* __restrict__ ow,
                      const float* __restrict__ w1, const float* __restrict__ w2,
                      uint32_t* __restrict__ dst) {
    int i = blockIdx.x * 256 + threadIdx.x;
    if (i >= 480000) return;
    const float* src;
    int off;
    if (i < 270000)      { src = ipw; off = i; }
    else if (i < 360000) { src = ow;  off = i - 270000; }
    else if (i < 420000) { src = w1;  off = i - 360000; }
    else                 { src = w2;  off = i - 420000; }
    float2 v = ((const float2*)src)[off];
    dst[i] = packbf(v.x, v.y);
}

__global__ void transpose_pack(const float* __restrict__ x, uint32_t* __restrict__ xT) {
    __shared__ float tile[64][65];
    int z = blockIdx.z;
    int s0 = blockIdx.x * 64, c0 = blockIdx.y * 64;
    int t = threadIdx.x;
#pragma unroll
    for (int i = 0; i < 16; i++) {
        int idx = t + i * 256;
        int ls = idx >> 6, lc = idx & 63;
        int c = c0 + lc;
        tile[ls][lc] = (c < EMB) ? x[(size_t)z * SQ * EMB + (size_t)(s0 + ls) * EMB + c] : 0.f;
    }
    __syncthreads();
#pragma unroll
    for (int i = 0; i < 8; i++) {
        int idx = t + i * 256;
        int lc = idx >> 5, lsp = idx & 31;
        int c = c0 + lc;
        if (c < EMB)
            xT[(size_t)z * EMB * (SQ / 2) + (size_t)c * (SQ / 2) + (s0 >> 1) + lsp] =
                packbf(tile[2 * lsp][lc], tile[2 * lsp + 1][lc]);
    }
}

// ---------------- positional encoding + add ----------------
__global__ void add_pe_kernel(const float* __restrict__ solv, const float* __restrict__ solu,
                              float* __restrict__ x, uint32_t* __restrict__ xb) {
    int p = blockIdx.x * blockDim.x + threadIdx.x;
    if (p >= SQ * 150) return;
    int z = blockIdx.z;
    const float* src = z ? solu : solv;
    int s = p / 150, pc = p - s * 150, c = 2 * pc;
    float dv = __expf(-(float)c * (logf(10000.0f) / (float)EMB));
    float arg = (float)s * dv;
    float pe0 = sinf(arg), pe1 = cosf(arg);
    float2 a = *(const float2*)&src[(size_t)s * EMB + c];
    float v0 = a.x + pe0, v1 = a.y + pe1;
    *(float2*)&x[(size_t)z * SQ * EMB + (size_t)s * EMB + c] = make_float2(v0, v1);
    xb[(size_t)z * SQ * 150 + p] = packbf(v0, v1);
}

// ---------------- all-bf16 tensor-core GEMM (128x64 tile, KCF=32, double-buffered) ----
// BF16OUT: 0 = fp32 out, 1 = bf16x2 packed out (row stride N/2), 2 = padded qkv layout.
template<int TA, int RELU, int SPLITK, int BF16OUT>
__global__ __launch_bounds__(256, 2)
void mma2(const __nv_bfloat16* __restrict__ A, const __nv_bfloat16* __restrict__ B,
          const float* __restrict__ bias, float* __restrict__ C,
          int M, int N, int K, int lda, int ldb,
          size_t sA, size_t sB, size_t sBias, size_t sC, int kc) {
    int z = blockIdx.z;
    int k_begin = 0, k_end = K;
    if (SPLITK) {
        k_begin = z * kc;
        k_end = min(K, k_begin + kc);
        C += (size_t)z * sC;
    } else {
        A += (size_t)z * sA; B += (size_t)z * sB; C += (size_t)z * sC;
        if (bias) bias += (size_t)z * sBias;
    }
    uint32_t* C32 = (uint32_t*)C;

    __shared__ uint32_t As[2][16][ASTR];
    __shared__ uint32_t Bs[2][16][BSTR];

    int t = threadIdx.x;
    int warp = t >> 5, lane = t & 31;
    int g = lane >> 2, tig = lane & 3;
    int wm = warp & 3, wn = warp >> 2;
    int row0 = blockIdx.y * 128, col0 = blockIdx.x * 64;
    int wr0 = wm * 32, wc0 = wn * 32;

    float acc[2][4][4];
#pragma unroll
    for (int i = 0; i < 2; i++)
#pragma unroll
        for (int j = 0; j < 4; j++)
#pragma unroll
            for (int h = 0; h < 4; h++) acc[i][j][h] = 0.f;

    uint32_t ra[8], rb[4];

    auto loadA = [&](int kt) {
        if (!TA) {
            int m = t >> 1, kq = (t & 1) * 16;
            const uint32_t* Ap = (const uint32_t*)(A + (size_t)(row0 + m) * lda + kt + kq);
            if (kt + kq + 15 < k_end) {
#pragma unroll
                for (int u = 0; u < 8; u++) ra[u] = Ap[u];
            } else {
                const unsigned short* A16 = (const unsigned short*)(A + (size_t)(row0 + m) * lda);
#pragma unroll
                for (int u = 0; u < 8; u++) {
                    int gk = kt + kq + 2 * u;
                    uint32_t lo = (gk < k_end) ? A16[gk] : 0;
                    uint32_t hi = (gk + 1 < k_end) ? A16[gk + 1] : 0;
                    ra[u] = lo | (hi << 16);
                }
            }
        } else {
            int kp = t >> 4, mq = (t & 15) * 8;
            int gk0 = kt + 2 * kp;
            bool ok0 = gk0 < k_end, ok1 = gk0 + 1 < k_end;
            const uint32_t* r0p = (const uint32_t*)(A + (size_t)gk0 * lda + row0 + mq);
            const uint32_t* r1p = (const uint32_t*)(A + (size_t)(gk0 + 1) * lda + row0 + mq);
            if (ok1) {
#pragma unroll
                for (int u = 0; u < 4; u++) {
                    uint32_t w0 = r0p[u], w1 = r1p[u];
                    ra[2 * u]     = __byte_perm(w0, w1, 0x5410);
                    ra[2 * u + 1] = __byte_perm(w0, w1, 0x7632);
                }
            } else {
#pragma unroll
                for (int u = 0; u < 4; u++) {
                    uint32_t w0 = ok0 ? r0p[u] : 0;
                    ra[2 * u]     = __byte_perm(w0, 0u, 0x5410);
                    ra[2 * u + 1] = __byte_perm(w0, 0u, 0x7632);
                }
            }
        }
    };
    auto loadB = [&](int kt) {
        int n = t >> 2, kq = (t & 3) * 8;
        int gn = col0 + n;
        bool okn = gn < N;
        const uint32_t* Bp = (const uint32_t*)(B + (size_t)gn * ldb + kt + kq);
        if (okn && kt + kq + 7 < k_end) {
#pragma unroll
            for (int u = 0; u < 4; u++) rb[u] = Bp[u];
        } else {
            const unsigned short* B16 = (const unsigned short*)(B + (size_t)gn * ldb);
#pragma unroll
            for (int u = 0; u < 4; u++) {
                int gk = kt + kq + 2 * u;
                uint32_t lo = (okn && gk < k_end) ? B16[gk] : 0;
                uint32_t hi = (okn && gk + 1 < k_end) ? B16[gk + 1] : 0;
                rb[u] = lo | (hi << 16);
            }
        }
    };
    auto storeA = [&](int bf) {
        if (!TA) {
            int m = t >> 1, kp0 = (t & 1) * 8;
#pragma unroll
            for (int u = 0; u < 8; u++) As[bf][kp0 + u][m] = ra[u];
        } else {
            int kp = t >> 4, mq = (t & 15) * 8;
#pragma unroll
            for (int u = 0; u < 8; u++) As[bf][kp][mq + u] = ra[u];
        }
    };
    auto storeB = [&](int bf) {
        int n = t >> 2, kp0 = (t & 3) * 4;
#pragma unroll
        for (int u = 0; u < 4; u++) Bs[bf][kp0 + u][n] = rb[u];
    };

    int nk = (k_end - k_begin + 31) >> 5;
    loadA(k_begin); loadB(k_begin);
    storeA(0); storeB(0);
    __syncthreads();

    int buf = 0;
    for (int it = 0; it < nk; it++) {
        if (it + 1 < nk) { loadA(k_begin + (it + 1) * 32); loadB(k_begin + (it + 1) * 32); }
#pragma unroll
        for (int ks = 0; ks < 16; ks += 8) {
            uint32_t a[2][4], b[4][2];
#pragma unroll
            for (int i = 0; i < 2; i++) {
                int mb = wr0 + i * 16;
                a[i][0] = As[buf][ks + tig][mb + g];
                a[i][1] = As[buf][ks + tig][mb + 8 + g];
                a[i][2] = As[buf][ks + tig + 4][mb + g];
                a[i][3] = As[buf][ks + tig + 4][mb + 8 + g];
            }
#pragma unroll
            for (int j = 0; j < 4; j++) {
                int nb = wc0 + j * 8;
                b[j][0] = Bs[buf][ks + tig][nb + g];
                b[j][1] = Bs[buf][ks + tig + 4][nb + g];
            }
#pragma unroll
            for (int i = 0; i < 2; i++)
#pragma unroll
                for (int j = 0; j < 4; j++)
                    MMA_BF16(acc[i][j], a[i], b[j][0], b[j][1]);
        }
        if (it + 1 < nk) {
            storeA(1 - buf); storeB(1 - buf);
            __syncthreads();
            buf ^= 1;
        }
    }

#pragma unroll
    for (int i = 0; i < 2; i++) {
        int r0 = row0 + wr0 + i * 16 + g;
#pragma unroll
        for (int j = 0; j < 4; j++) {
            int cc = col0 + wc0 + j * 8 + tig * 2;
#pragma unroll
            for (int h = 0; h < 2; h++) {
                int gr = r0 + h * 8;
                float v0 = acc[i][j][h * 2], v1 = acc[i][j][h * 2 + 1];
                if (!SPLITK && bias) {
                    if (cc < N) v0 += bias[cc];
                    if (cc + 1 < N) v1 += bias[cc + 1];
                }
                if (RELU) { v0 = fmaxf(v0, 0.f); v1 = fmaxf(v1, 0.f); }
                if (BF16OUT == 2) {
                    if (cc < N) {
                        int seg = cc / 300, rem = cc - seg * 300;
                        int hh = rem / 100, wi = rem - hh * 100;
                        C32[(size_t)gr * QKVS + seg * 156 + hh * 52 + (wi >> 1)] = packbf(v0, v1);
                    }
                } else if (BF16OUT == 1) {
                    if (cc < N)
                        C32[(size_t)gr * (N >> 1) + (cc >> 1)] = packbf(v0, v1);
                } else if (cc + 1 < N) {
                    *(float2*)&C[(size_t)gr * N + cc] = make_float2(v0, v1);
                } else if (cc < N) {
                    C[(size_t)gr * N + cc] = v0;
                }
            }
        }
    }
}

// ---------------- fused P+Q split-K GEMM (runtime transpose flag) ----------------
__global__ __launch_bounds__(256, 2)
void mma2_pq(const __nv_bfloat16* __restrict__ Ain, const __nv_bfloat16* __restrict__ BP,
             const __nv_bfloat16* __restrict__ BQ, float* __restrict__ CP,
             float* __restrict__ CQ) {
    int z = blockIdx.z;
    int ta = (z >= NCH) ? 1 : 0;
    int zz = ta ? z - NCH : z;
    int k_begin = zz * KSPL;
    const __nv_bfloat16* B = ta ? BQ : BP;
    float* C = (ta ? CQ : CP) + (size_t)zz * SQ * EMB;
    const int lda = SQ, ldb = SQ, N = EMB;

    __shared__ uint32_t As[2][16][ASTR];
    __shared__ uint32_t Bs[2][16][BSTR];

    int t = threadIdx.x;
    int warp = t >> 5, lane = t & 31;
    int g = lane >> 2, tig = lane & 3;
    int wm = warp & 3, wn = warp >> 2;
    int row0 = blockIdx.y * 128, col0 = blockIdx.x * 64;
    int wr0 = wm * 32, wc0 = wn * 32;

    float acc[2][4][4];
#pragma unroll
    for (int i = 0; i < 2; i++)
#pragma unroll
        for (int j = 0; j < 4; j++)
#pragma unroll
            for (int h = 0; h < 4; h++) acc[i][j][h] = 0.f;

    uint32_t ra[8], rb[4];

    auto loadA = [&](int kt) {
        if (!ta) {
            int m = t >> 1, kq = (t & 1) * 16;
            const uint32_t* Ap = (const uint32_t*)(Ain + (size_t)(row0 + m) * lda + kt + kq);
#pragma unroll
            for (int u = 0; u < 8; u++) ra[u] = Ap[u];
        } else {
            int kp = t >> 4, mq = (t & 15) * 8;
            int gk0 = kt + 2 * kp;
            const uint32_t* r0p = (const uint32_t*)(Ain + (size_t)gk0 * lda + row0 + mq);
            const uint32_t* r1p = (const uint32_t*)(Ain + (size_t)(gk0 + 1) * lda + row0 + mq);
#pragma unroll
            for (int u = 0; u < 4; u++) {
                uint32_t w0 = r0p[u], w1 = r1p[u];
                ra[2 * u]     = __byte_perm(w0, w1, 0x5410);
                ra[2 * u + 1] = __byte_perm(w0, w1, 0x7632);
            }
        }
    };
    auto loadB = [&](int kt) {
        int n = t >> 2, kq = (t & 3) * 8;
        int gn = col0 + n;
        if (gn < N) {
            const uint32_t* Bp = (const uint32_t*)(B + (size_t)gn * ldb + kt + kq);
#pragma unroll
            for (int u = 0; u < 4; u++) rb[u] = Bp[u];
        } else {
#pragma unroll
            for (int u = 0; u < 4; u++) rb[u] = 0u;
        }
    };
    auto storeA = [&](int bf) {
        if (!ta) {
            int m = t >> 1, kp0 = (t & 1) * 8;
#pragma unroll
            for (int u = 0; u < 8; u++) As[bf][kp0 + u][m] = ra[u];
        } else {
            int kp = t >> 4, mq = (t & 15) * 8;
#pragma unroll
            for (int u = 0; u < 8; u++) As[bf][kp][mq + u] = ra[u];
        }
    };
    auto storeB = [&](int bf) {
        int n = t >> 2, kp0 = (t & 3) * 4;
#pragma unroll
        for (int u = 0; u < 4; u++) Bs[bf][kp0 + u][n] = rb[u];
    };

    const int nk = KSPL >> 5;
    loadA(k_begin); loadB(k_begin);
    storeA(0); storeB(0);
    __syncthreads();

    int buf = 0;
    for (int it = 0; it < nk; it++) {
        if (it + 1 < nk) { loadA(k_begin + (it + 1) * 32); loadB(k_begin + (it + 1) * 32); }
#pragma unroll
        for (int ks = 0; ks < 16; ks += 8) {
            uint32_t a[2][4], b[4][2];
#pragma unroll
            for (int i = 0; i < 2; i++) {
                int mb = wr0 + i * 16;
                a[i][0] = As[buf][ks + tig][mb + g];
                a[i][1] = As[buf][ks + tig][mb + 8 + g];
                a[i][2] = As[buf][ks + tig + 4][mb + g];
                a[i][3] = As[buf][ks + tig + 4][mb + 8 + g];
            }
#pragma unroll
            for (int j = 0; j < 4; j++) {
                int nb = wc0 + j * 8;
                b[j][0] = Bs[buf][ks + tig][nb + g];
                b[j][1] = Bs[buf][ks + tig + 4][nb + g];
            }
#pragma unroll
            for (int i = 0; i < 2; i++)
#pragma unroll
                for (int j = 0; j < 4; j++)
                    MMA_BF16(acc[i][j], a[i], b[j][0], b[j][1]);
        }
        if (it + 1 < nk) {
            storeA(1 - buf); storeB(1 - buf);
            __syncthreads();
            buf ^= 1;
        }
    }

#pragma unroll
    for (int i = 0; i < 2; i++) {
        int r0 = row0 + wr0 + i * 16 + g;
#pragma unroll
        for (int j = 0; j < 4; j++) {
            int cc = col0 + wc0 + j * 8 + tig * 2;
#pragma unroll
            for (int h = 0; h < 2; h++) {
                int gr = r0 + h * 8;
                float v0 = acc[i][j][h * 2], v1 = acc[i][j][h * 2 + 1];
                if (cc + 1 < N) {
                    *(float2*)&C[(size_t)gr * N + cc] = make_float2(v0, v1);
                } else if (cc < N) {
                    C[(size_t)gr * N + cc] = v0;
                }
            }
        }
    }
}

// ---------------- split-K reduce for P and Q ----------------
__global__ void reduce_pq(const float* __restrict__ Pp, const float* __restrict__ Qp,
                          float* __restrict__ P, float* __restrict__ Q) {
    int idx = blockIdx.x * 256 + threadIdx.x;
    if (idx >= SQ * EMB / 4) return;
    const float* src = blockIdx.y ? Qp : Pp;
    float* dst = blockIdx.y ? Q : P;
    float4 r = make_float4(0.f, 0.f, 0.f, 0.f);
#pragma unroll
    for (int c = 0; c < NCH; c++) {
        float4 a = ((const float4*)(src + (size_t)c * SQ * EMB))[idx];
        r.x += a.x; r.y += a.y; r.z += a.z; r.w += a.w;
    }
    ((float4*)dst)[idx] = r;
}

// ---------------- bf16 flash attention: ldmatrix fragments, reg P ----------------
__global__ __launch_bounds__(128, 5)
void attn_mma_kernel(const uint32_t* __restrict__ qb_all,
                     float* __restrict__ part_o, float* __restrict__ part_ml) {
    __shared__ __align__(16) uint32_t k_s[TJ][60];
    __shared__ __align__(16) uint32_t v_s[16][108];
    __shared__ __align__(16) uint32_t q_s[4][16][60];

    int z = blockIdx.z, e = z / 3, h = z % 3;
    int qt = (int)gridDim.x - 1 - (int)blockIdx.x;
    int q0 = qt * QB;
    int c = blockIdx.y, c0 = c * JCH;
    if (c0 > q0 + QB - 1) return;

    const uint32_t* qb = qb_all + (size_t)e * SQ * QKVS;
    int t = threadIdx.x, w = t >> 5, lane = t & 31;
    int g = lane >> 2, tig = lane & 3;

    int r0 = q0 + w * 16 + g;
    int r1 = r0 + 8;

    // stage Q fragments into smem once
    {
        const uint32_t* q0p = qb + (size_t)r0 * QKVS + h * 52;
        const uint32_t* q1p = qb + (size_t)r1 * QKVS + h * 52;
#pragma unroll
        for (int s = 0; s < 7; s++) {
            int dp0 = s * 8 + tig, dp1 = dp0 + 4;
            q_s[w][g][dp0]     = dp0 < 50 ? q0p[dp0] : 0u;
            q_s[w][g + 8][dp0] = dp0 < 50 ? q1p[dp0] : 0u;
            q_s[w][g][dp1]     = dp1 < 50 ? q0p[dp1] : 0u;
            q_s[w][g + 8][dp1] = dp1 < 50 ? q1p[dp1] : 0u;
        }
    }
    // zero pad columns once
    for (int idx = t; idx < 32 * 6; idx += 128) k_s[idx / 6][50 + idx % 6] = 0u;
    for (int idx = t; idx < 16 * 8; idx += 128) v_s[idx / 8][100 + idx % 8] = 0u;

    // ldmatrix base addresses (tile = lane>>3, row-in-tile = lane&7)
    uint32_t kbase0, kbase1, qbase;
    {
        int tile = lane >> 3, row = lane & 7;
        int krow = (tile >> 1) * 8 + row;
        int kword = (tile & 1) * 4;
        kbase0 = (uint32_t)__cvta_generic_to_shared(&k_s[krow][kword]);
        kbase1 = (uint32_t)__cvta_generic_to_shared(&k_s[16 + krow][kword]);
        int qrow = ((tile & 1) ? 8 : 0) + row;
        int qword = (tile >> 1) * 4;
        qbase = (uint32_t)__cvta_generic_to_shared(&q_s[w][qrow][qword]);
    }

    float of[13][4];
#pragma unroll
    for (int nt = 0; nt < 13; nt++) { of[nt][0] = of[nt][1] = of[nt][2] = of[nt][3] = 0.f; }
    float m0 = -INFINITY, m1 = -INFINITY, l0 = 0.f, l1 = 0.f;

    int jend = min(c0 + JCH, q0 + QB);
    for (int jt = c0; jt < jend; jt += TJ) {
        // K stage: vectorized
        for (int idx = t; idx < 32 * 13; idx += 128) {
            int row = idx / 13, sl = idx - row * 13;
            const uint32_t* src = qb + (size_t)(jt + row) * QKVS + 156 + h * 52;
            if (sl < 12) {
                *(uint4*)&k_s[row][4 * sl] = *(const uint4*)(src + 4 * sl);
            } else {
                *(uint2*)&k_s[row][48] = *(const uint2*)(src + 48);
            }
        }
        // V stage: interleave two j rows, vectorized
        for (int idx = t; idx < 16 * 13; idx += 128) {
            int jp = idx / 13, sl = idx - jp * 13;
            const uint32_t* s0p = qb + (size_t)(jt + 2 * jp) * QKVS + 312 + h * 52;
            const uint32_t* s1p = s0p + QKVS;
            if (sl < 12) {
                uint4 a = *(const uint4*)(s0p + 4 * sl);
                uint4 b = *(const uint4*)(s1p + 4 * sl);
                uint4 o0, o1;
                o0.x = __byte_perm(a.x, b.x, 0x5410); o0.y = __byte_perm(a.x, b.x, 0x7632);
                o0.z = __byte_perm(a.y, b.y, 0x5410); o0.w = __byte_perm(a.y, b.y, 0x7632);
                o1.x = __byte_perm(a.z, b.z, 0x5410); o1.y = __byte_perm(a.z, b.z, 0x7632);
                o1.z = __byte_perm(a.w, b.w, 0x5410); o1.w = __byte_perm(a.w, b.w, 0x7632);
                *(uint4*)&v_s[jp][8 * sl] = o0;
                *(uint4*)&v_s[jp][8 * sl + 4] = o1;
            } else {
                uint2 a = *(const uint2*)(s0p + 48);
                uint2 b = *(const uint2*)(s1p + 48);
                uint4 o;
                o.x = __byte_perm(a.x, b.x, 0x5410); o.y = __byte_perm(a.x, b.x, 0x7632);
                o.z = __byte_perm(a.y, b.y, 0x5410); o.w = __byte_perm(a.y, b.y, 0x7632);
                *(uint4*)&v_s[jp][96] = o;
            }
        }
        __syncthreads();

        // S = Q K^T via ldmatrix fragments
        float sc[4][4];
#pragma unroll
        for (int nt = 0; nt < 4; nt++) { sc[nt][0] = sc[nt][1] = sc[nt][2] = sc[nt][3] = 0.f; }
#pragma unroll
        for (int s = 0; s < 7; s++) {
            uint32_t qa[4], kb0[4], kb1[4];
            LDMX4(qa, qbase + s * 32);
            LDMX4(kb0, kbase0 + s * 32);
            LDMX4(kb1, kbase1 + s * 32);
            MMA_BF16(sc[0], qa, kb0[0], kb0[1]);
            MMA_BF16(sc[1], qa, kb0[2], kb0[3]);
            MMA_BF16(sc[2], qa, kb1[0], kb1[1]);
            MMA_BF16(sc[3], qa, kb1[2], kb1[3]);
        }
#pragma unroll
        for (int nt = 0; nt < 4; nt++) {
            sc[nt][0] *= 0.1f; sc[nt][1] *= 0.1f; sc[nt][2] *= 0.1f; sc[nt][3] *= 0.1f;
        }

        if (jt + TJ > q0) {
#pragma unroll
            for (int nt = 0; nt < 4; nt++) {
                int jb = jt + nt * 8 + 2 * tig;
                if (jb > r0)     sc[nt][0] = -INFINITY;
                if (jb + 1 > r0) sc[nt][1] = -INFINITY;
                if (jb > r1)     sc[nt][2] = -INFINITY;
                if (jb + 1 > r1) sc[nt][3] = -INFINITY;
            }
        }

        float rm0 = -INFINITY, rm1 = -INFINITY;
#pragma unroll
        for (int nt = 0; nt < 4; nt++) {
            rm0 = fmaxf(rm0, fmaxf(sc[nt][0], sc[nt][1]));
            rm1 = fmaxf(rm1, fmaxf(sc[nt][2], sc[nt][3]));
        }
        rm0 = fmaxf(rm0, __shfl_xor_sync(0xffffffffu, rm0, 1));
        rm0 = fmaxf(rm0, __shfl_xor_sync(0xffffffffu, rm0, 2));
        rm1 = fmaxf(rm1, __shfl_xor_sync(0xffffffffu, rm1, 1));
        rm1 = fmaxf(rm1, __shfl_xor_sync(0xffffffffu, rm1, 2));
        float mn0 = fmaxf(m0, rm0), mn1 = fmaxf(m1, rm1);
        float s0 = __expf(m0 - mn0), s1 = __expf(m1 - mn1);

        uint32_t pp[4][2];
        float rs0 = 0.f, rs1 = 0.f;
#pragma unroll
        for (int nt = 0; nt < 4; nt++) {
            float p0 = __expf(sc[nt][0] - mn0);
            float p1 = __expf(sc[nt][1] - mn0);
            float p2 = __expf(sc[nt][2] - mn1);
            float p3 = __expf(sc[nt][3] - mn1);
            rs0 += p0 + p1;
            rs1 += p2 + p3;
            pp[nt][0] = packbf(p0, p1);
            pp[nt][1] = packbf(p2, p3);
        }
        rs0 += __shfl_xor_sync(0xffffffffu, rs0, 1);
        rs0 += __shfl_xor_sync(0xffffffffu, rs0, 2);
        rs1 += __shfl_xor_sync(0xffffffffu, rs1, 1);
        rs1 += __shfl_xor_sync(0xffffffffu, rs1, 2);
        l0 = l0 * s0 + rs0;
        l1 = l1 * s1 + rs1;
        m0 = mn0; m1 = mn1;

#pragma unroll
        for (int nt = 0; nt < 13; nt++) {
            of[nt][0] *= s0; of[nt][1] *= s0;
            of[nt][2] *= s1; of[nt][3] *= s1;
        }

        // O += P V
#pragma unroll
        for (int kh = 0; kh < 2; kh++) {
            int ks = kh * 8;
            uint32_t pa[4];
            pa[0] = pp[2 * kh][0];
            pa[1] = pp[2 * kh][1];
            pa[2] = pp[2 * kh + 1][0];
            pa[3] = pp[2 * kh + 1][1];
#pragma unroll
            for (int nt = 0; nt < 13; nt++) {
                uint32_t b0 = v_s[ks + tig][nt * 8 + g];
                uint32_t b1 = v_s[ks + tig + 4][nt * 8 + g];
                MMA_BF16(of[nt], pa, b0, b1);
            }
        }
        __syncthreads();
    }

    size_t pb0 = (size_t)(z * NCH + c) * SQ + r0;
    size_t pb1 = (size_t)(z * NCH + c) * SQ + r1;
#pragma unroll
    for (int nt = 0; nt < 13; nt++) {
        int d = nt * 8 + 2 * tig;
        if (d < HDIM) {
            *(float2*)&part_o[pb0 * HDIM + d] = make_float2(of[nt][0], of[nt][1]);
            *(float2*)&part_o[pb1 * HDIM + d] = make_float2(of[nt][2], of[nt][3]);
        }
    }
    if (tig == 0) {
        part_ml[pb0 * 2] = m0; part_ml[pb0 * 2 + 1] = l0;
        part_ml[pb1 * 2] = m1; part_ml[pb1 * 2 + 1] = l1;
    }
}

__global__ void attn_combine(const float* __restrict__ part_o,
                             const float* __restrict__ part_ml,
                             uint32_t* __restrict__ ob) {
    int qi = blockIdx.x, e = blockIdx.y;
    int t = threadIdx.x, h = threadIdx.y;
    int z = e * 3 + h;
    int nch = qi / JCH + 1;
    float M = -INFINITY;
    for (int cc = 0; cc < nch; cc++)
        M = fmaxf(M, part_ml[((size_t)(z * NCH + cc) * SQ + qi) * 2]);
    float L = 0.f, a0 = 0.f, a1 = 0.f;
    for (int cc = 0; cc < nch; cc++) {
        size_t pb = (size_t)(z * NCH + cc) * SQ + qi;
        float w = __expf(part_ml[pb * 2] - M);
        L += part_ml[pb * 2 + 1] * w;
        if (t < 50) {
            float2 v = *(const float2*)&part_o[pb * HDIM + 2 * t];
            a0 += w * v.x; a1 += w * v.y;
        }
    }
    if (t < 50) {
        float inv = 1.f / L;
        ob[((size_t)e * SQ + qi) * 150 + h * 50 + t] = packbf(a0 * inv, a1 * inv);
    }
}

// ---------------- fused residual + LayerNorm ----------------
__global__ void ln_kernel(float* __restrict__ x, const float* __restrict__ delta,
                          const float* __restrict__ g, const float* __restrict__ b,
                          uint32_t* __restrict__ xb) {
    __shared__ float rs[8];
    int z = blockIdx.z;
    x += (size_t)z * SQ * EMB; delta += (size_t)z * SQ * EMB;
    g += z * EMB; b += z * EMB; xb += (size_t)z * SQ * 150;
    int r = blockIdx.x, t = threadIdx.x;
    int lane = t & 31, wid = t >> 5;
    float v[2][2];
    float s1 = 0.f, s2 = 0.f;
    {
        float2 a = *(const float2*)&x[(size_t)r * EMB + 2 * t];
        float2 d = *(const float2*)&delta[(size_t)r * EMB + 2 * t];
        v[0][0] = a.x + d.x; v[0][1] = a.y + d.y;
        s1 += v[0][0] + v[0][1];
        s2 += v[0][0] * v[0][0] + v[0][1] * v[0][1];
    }
    if (t < 22) {
        int p = t + 128;
        float2 a = *(const float2*)&x[(size_t)r * EMB + 2 * p];
        float2 d = *(const float2*)&delta[(size_t)r * EMB + 2 * p];
        v[1][0] = a.x + d.x; v[1][1] = a.y + d.y;
        s1 += v[1][0] + v[1][1];
        s2 += v[1][0] * v[1][0] + v[1][1] * v[1][1];
    }
#pragma unroll
    for (int off = 16; off > 0; off >>= 1) {
        s1 += __shfl_xor_sync(0xffffffffu, s1, off);
        s2 += __shfl_xor_sync(0xffffffffu, s2, off);
    }
    if (lane == 0) { rs[wid * 2] = s1; rs[wid * 2 + 1] = s2; }
    __syncthreads();
    float S1 = rs[0] + rs[2] + rs[4] + rs[6];
    float S2 = rs[1] + rs[3] + rs[5] + rs[7];
    float mu = S1 / (float)EMB;
    float var = S2 / (float)EMB - mu * mu;
    float rstd = rsqrtf(var + 1e-5f);
    {
        int c = 2 * t;
        float n0 = (v[0][0] - mu) * rstd * g[c] + b[c];
        float n1 = (v[0][1] - mu) * rstd * g[c + 1] + b[c + 1];
        *(float2*)&x[(size_t)r * EMB + c] = make_float2(n0, n1);
        xb[(size_t)r * 150 + t] = packbf(n0, n1);
    }
    if (t < 22) {
        int c = 2 * (t + 128);
        float n0 = (v[1][0] - mu) * rstd * g[c] + b[c];
        float n1 = (v[1][1] - mu) * rstd * g[c + 1] + b[c + 1];
        *(float2*)&x[(size_t)r * EMB + c] = make_float2(n0, n1);
        xb[(size_t)r * 150 + t + 128] = packbf(n0, n1);
    }
}

// ---------------- row softmax over A: fp32 in, bf16 out ----------------
__global__ void softmax_rows(const float* __restrict__ A, __nv_bfloat16* __restrict__ Ab) {
    __shared__ float row[SQ];
    __shared__ float red[256];
    int r = blockIdx.x, t = threadIdx.x;
    float mx = -INFINITY;
    for (int j = t; j < SQ; j += 256) { float v = A[(size_t)r * SQ + j]; row[j] = v; mx = fmaxf(mx, v); }
    red[t] = mx; __syncthreads();
    for (int off = 128; off > 0; off >>= 1) { if (t < off) red[t] = fmaxf(red[t], red[t + off]); __syncthreads(); }
    mx = red[0];
    __syncthreads();
    float s = 0.f;
    for (int j = t; j < SQ; j += 256) { float e = __expf(row[j] - mx); row[j] = e; s += e; }
    red[t] = s; __syncthreads();
    for (int off = 128; off > 0; off >>= 1) { if (t < off) red[t] += red[t + off]; __syncthreads(); }
    float inv = 1.f / red[0];
    uint32_t* out = (uint32_t*)(Ab + (size_t)r * SQ);
    for (int j = 2 * t; j < SQ; j += 512)
        out[j >> 1] = packbf(row[j] * inv, row[j + 1] * inv);
}

// ---------------- coalesced colsum of elementwise max (two phase) ----------------
__global__ void colsum_partial(const float* __restrict__ H, const float* __restrict__ P,
                               const float* __restrict__ G, const float* __restrict__ Q,
                               float* __restrict__ part) {
    int chunk = blockIdx.x, pair = blockIdx.y;
    int c = threadIdx.x;
    const float* X = pair ? G : H;
    const float* Y = pair ? Q : P;
    int r0 = chunk * 128;
    float s = 0.f;
    for (int r = r0; r < r0 + 128; r++)
        s += fmaxf(X[(size_t)r * EMB + c], Y[(size_t)r * EMB + c]);
    part[((size_t)pair * 32 + chunk) * EMB + c] = s;
}
__global__ void colsum_final(const float* __restrict__ part, float* __restrict__ suv) {
    int j = threadIdx.x;
    int pair = j / EMB, c = j - pair * EMB;
    float s = 0.f;
#pragma unroll
    for (int ch = 0; ch < 32; ch++)
        s += part[((size_t)pair * 32 + ch) * EMB + c];
    suv[j] = s;
}

// ---------------- tiny FC layers ----------------
__global__ void fc1_kernel(const float* __restrict__ inp, const float* __restrict__ w,
                           const float* __restrict__ b, float* __restrict__ out) {
    __shared__ float red[128];
    int i = blockIdx.x, t = threadIdx.x;
    float s = 0.f;
    for (int j = t; j < 2 * EMB; j += 128) s += inp[j] * w[(size_t)i * 2 * EMB + j];
    red[t] = s; __syncthreads();
    for (int off = 64; off > 0; off >>= 1) { if (t < off) red[t] += red[t + off]; __syncthreads(); }
    if (t == 0) out[i] = fmaxf(red[0] + b[i], 0.f);
}

__global__ void fc2_kernel(const float* __restrict__ inp, const float* __restrict__ w,
                           const float* __restrict__ b, float* __restrict__ out) {
    __shared__ float red[256];
    int t = threadIdx.x;
    float s = 0.f;
    for (int j = t; j < EMB; j += 256) s += inp[j] * w[j];
    red[t] = s; __syncthreads();
    for (int off = 128; off > 0; off >>= 1) { if (t < off) red[t] += red[t + off]; __syncthreads(); }
    if (t == 0) out[0] = red[0] + b[0];
}

// ---------------- host orchestration ----------------
extern "C" void kernel_launch(void* const* d_in, const int* in_sizes, int n_in,
                              void* d_out, int out_size) {
    const float* solv = (const float*)d_in[0];
    const float* solu = (const float*)d_in[1];
    const float* ipw  = (const float*)d_in[2];
    const float* ipb  = (const float*)d_in[3];
    const float* ow   = (const float*)d_in[4];
    const float* ob_b = (const float*)d_in[5];
    const float* g1   = (const float*)d_in[6];
    const float* b1   = (const float*)d_in[7];
    const float* w1   = (const float*)d_in[8];
    const float* bb1  = (const float*)d_in[9];
    const float* w2   = (const float*)d_in[10];
    const float* bb2  = (const float*)d_in[11];
    const float* g2   = (const float*)d_in[12];
    const float* b2   = (const float*)d_in[13];
    const float* fc1w = (const float*)d_in[14];
    const float* fc1b = (const float*)d_in[15];
    const float* fc2w = (const float*)d_in[16];
    const float* fc2b = (const float*)d_in[17];

    float *x, *t1, *A, *P, *Q, *Pp, *Qp, *po, *pml, *cpart, *suv, *fc1o;
    uint32_t *xb, *xbT, *wp, *qkvb, *ob, *ffb;
    __nv_bfloat16* Ab;
    cudaGetSymbolAddress((void**)&x,    g_x);
    cudaGetSymbolAddress((void**)&xb,   g_xb);
    cudaGetSymbolAddress((void**)&xbT,  g_xbT);
    cudaGetSymbolAddress((void**)&wp,   g_wpack);
    cudaGetSymbolAddress((void**)&qkvb, g_qkvb);
    cudaGetSymbolAddress((void**)&ob,   g_ob);
    cudaGetSymbolAddress((void**)&t1,   g_t1);
    cudaGetSymbolAddress((void**)&ffb,  g_ffb);
    cudaGetSymbolAddress((void**)&A,    g_A);
    cudaGetSymbolAddress((void**)&Ab,   g_Ab);
    cudaGetSymbolAddress((void**)&P,    g_P);
    cudaGetSymbolAddress((void**)&Q,    g_Q);
    cudaGetSymbolAddress((void**)&Pp,   g_Pp);
    cudaGetSymbolAddress((void**)&Qp,   g_Qp);
    cudaGetSymbolAddress((void**)&po,   g_part_o);
    cudaGetSymbolAddress((void**)&pml,  g_part_ml);
    cudaGetSymbolAddress((void**)&cpart, g_colpart);
    cudaGetSymbolAddress((void**)&suv,  g_suv);
    cudaGetSymbolAddress((void**)&fc1o, g_fc1o);

    const size_t SE = (size_t)SQ * EMB;
    uint32_t* ipwb = wp;
    uint32_t* owb  = wp + 270000;
    uint32_t* w1b  = wp + 360000;
    uint32_t* w2b  = wp + 420000;

    pack4<<<(480000 + 255) / 256, 256>>>(ipw, ow, w1, w2, wp);

    add_pe_kernel<<<dim3((SQ * 150 + 255) / 256, 1, 2), 256>>>(solv, solu, x, xb);

    // qkv = x @ ipw^T + ipb  -> padded bf16 qkv layout (BF16OUT=2)
    mma2<0, 0, 0, 2><<<dim3(15, 32, 2), 256>>>(
        (const __nv_bfloat16*)xb, (const __nv_bfloat16*)ipwb, ipb, (float*)qkvb,
        SQ, 3 * EMB, EMB, EMB, EMB,
        (size_t)SQ * EMB, (size_t)3 * EMB * EMB, 3 * EMB, (size_t)SQ * QKVS, 0);

    attn_mma_kernel<<<dim3(SQ / QB, NCH, 6), 128>>>(qkvb, po, pml);
    attn_combine<<<dim3(SQ, 2), dim3(64, 3)>>>(po, pml, ob);

    // proj = o @ ow^T + ob  -> fp32 (feeds LN)
    mma2<0, 0, 0, 0><<<dim3(5, 32, 2), 256>>>(
        (const __nv_bfloat16*)ob, (const __nv_bfloat16*)owb, ob_b, t1,
        SQ, EMB, EMB, EMB, EMB,
        (size_t)SQ * EMB, (size_t)EMB * EMB, EMB, SE, 0);
    ln_kernel<<<dim3(SQ, 1, 2), 128>>>(x, t1, g1, b1, xb);

    // ff1 = relu(x @ w1^T + bb1) -> bf16 packed
    mma2<0, 1, 0, 1><<<dim3(4, 32, 2), 256>>>(
        (const __nv_bfloat16*)xb, (const __nv_bfloat16*)w1b, bb1, (float*)ffb,
        SQ, NHID, EMB, EMB, EMB,
        (size_t)SQ * EMB, (size_t)NHID * EMB, NHID, (size_t)SQ * 100, 0);
    // ff2 = ff1 @ w2^T + bb2 -> fp32 (feeds LN)
    mma2<0, 0, 0, 0><<<dim3(5, 32, 2), 256>>>(
        (const __nv_bfloat16*)ffb, (const __nv_bfloat16*)w2b, bb2, t1,
        SQ, EMB, NHID, NHID, NHID,
        (size_t)SQ * NHID, (size_t)EMB * NHID, EMB, SE, 0);
    ln_kernel<<<dim3(SQ, 1, 2), 128>>>(x, t1, g2, b2, xb);

    float* H = x;
    float* G = x + SE;
    uint32_t* Hb = xb;
    uint32_t* Gb = xb + (size_t)SQ * 150;

    transpose_pack<<<dim3(SQ / 64, 5, 2), 256>>>(x, xbT);
    const __nv_bfloat16* HbT = (const __nv_bfloat16*)xbT;
    const __nv_bfloat16* GbT = (const __nv_bfloat16*)xbT + (size_t)EMB * SQ;

    // A = H @ G^T
    mma2<0, 0, 0, 0><<<dim3(64, 32, 1), 256>>>(
        (const __nv_bfloat16*)Hb, (const __nv_bfloat16*)Gb, (const float*)nullptr, A,
        SQ, SQ, EMB, EMB, EMB, 0, 0, 0, 0, 0);
    softmax_rows<<<SQ, 256>>>(A, Ab);

    // P and Q split-K chunks fused into one launch
    mma2_pq<<<dim3(5, 32, 2 * NCH), 256>>>(Ab, GbT, HbT, Pp, Qp);
    reduce_pq<<<dim3((SQ * EMB / 4 + 255) / 256, 2), 256>>>(Pp, Qp, P, Q);

    colsum_partial<<<dim3(32, 2), 300>>>(H, P, G, Q, cpart);
    colsum_final<<<1, 600>>>(cpart, suv);

    fc1_kernel<<<EMB, 128>>>(suv, fc1w, fc1b, fc1o);
    fc2_kernel<<<1, 256>>>(fc1o, fc2w, fc2b, (float*)d_out);
}